// round 9
// baseline (speedup 1.0000x reference)
#include <cuda_runtime.h>

#define NN   50000
#define EE   150000
#define ELL  300000

// ---------------- scratch (device globals; no runtime allocation) ----------------
__device__ __align__(16) float    g_ni   [(size_t)NN * 256];   // ni, then node-acc, then gi
__device__ __align__(16) float    g_nj   [(size_t)NN * 256];   // nj, then gj
__device__ __align__(16) float    g_big  [(size_t)ELL * 256];  // fe, then lx, then gfe
__device__ __align__(16) float    g_mbuf [(size_t)EE * 256];   // lni, then m1, then m2
__device__ __align__(16) float    g_accb [(size_t)EE * 256];   // lnj, then lg-acc, then g-acc
__device__ __align__(16) float    g_hb   [(size_t)NN * 256];   // node transform h
__device__ __align__(16) float    g_fedge[(size_t)EE * 64];
__device__ __align__(16) float    g_hnode[(size_t)NN * 64];
__device__ __align__(16) float    g_aggn [(size_t)NN * 128];
__device__             float      g_cntn [NN];
__device__ __align__(16) float    g_aggx [(size_t)EE * 64];
__device__             float      g_cnte [EE];
__device__             float      g_logE [(size_t)EE * 4];
__device__             float      g_alg  [(size_t)ELL * 4];
__device__             float      g_ag   [(size_t)EE * 4];
__device__             unsigned   g_smax [(size_t)EE * 4];
__device__             float      g_ssum [(size_t)EE * 4];
__device__ __align__(16) float    g_nedge[(size_t)EE * 64];

// ---------------- device helpers ----------------
__device__ __forceinline__ float lrelu(float v) { return v >= 0.f ? v : 0.01f * v; }

// monotone encoding of float for unsigned atomicMax
__device__ __forceinline__ unsigned fenc(float f) {
    unsigned u = __float_as_uint(f);
    return (u & 0x80000000u) ? ~u : (u | 0x80000000u);
}
__device__ __forceinline__ float fdec(unsigned e) {
    unsigned u = (e & 0x80000000u) ? (e ^ 0x80000000u) : ~e;
    return __uint_as_float(u);
}

__device__ __forceinline__ void atomicAdd4(float* p, float4 v) {
#if defined(__CUDA_ARCH__) && (__CUDA_ARCH__ >= 900)
    atomicAdd(reinterpret_cast<float4*>(p), v);
#else
    atomicAdd(p + 0, v.x); atomicAdd(p + 1, v.y);
    atomicAdd(p + 2, v.z); atomicAdd(p + 3, v.w);
#endif
}

__device__ __forceinline__ void warpReduce4(float& a, float& b, float& c, float& d) {
#pragma unroll
    for (int off = 16; off; off >>= 1) {
        a += __shfl_xor_sync(0xffffffffu, a, off);
        b += __shfl_xor_sync(0xffffffffu, b, off);
        c += __shfl_xor_sync(0xffffffffu, c, off);
        d += __shfl_xor_sync(0xffffffffu, d, off);
    }
}

// ---------------- GEMM: C[M,256] = A[M,K] @ W[256,K]^T (+bias, +=C) ----------------
__global__ void __launch_bounds__(256) gemm_nt(
    const float* __restrict__ A, int ldA,
    const float* __restrict__ W, int ldW,
    const float* __restrict__ bias,
    float* __restrict__ C, int M, int K, int accum)
{
    __shared__ __align__(16) float sA[16][64];
    __shared__ __align__(16) float sB[16][64];
    const int tid  = threadIdx.x;
    const int tx   = tid & 15, ty = tid >> 4;
    const int row0 = blockIdx.x * 64, col0 = blockIdx.y * 64;
    const int lr   = tid >> 2, lc = (tid & 3) << 2;
    float acc[4][4] = {};

    for (int k0 = 0; k0 < K; k0 += 16) {
        float4 va = make_float4(0.f, 0.f, 0.f, 0.f);
        int gr = row0 + lr;
        if (gr < M) va = *reinterpret_cast<const float4*>(A + (size_t)gr * ldA + k0 + lc);
        sA[lc + 0][lr] = va.x; sA[lc + 1][lr] = va.y;
        sA[lc + 2][lr] = va.z; sA[lc + 3][lr] = va.w;
        float4 vb = *reinterpret_cast<const float4*>(W + (size_t)(col0 + lr) * ldW + k0 + lc);
        sB[lc + 0][lr] = vb.x; sB[lc + 1][lr] = vb.y;
        sB[lc + 2][lr] = vb.z; sB[lc + 3][lr] = vb.w;
        __syncthreads();
#pragma unroll
        for (int kk = 0; kk < 16; kk++) {
            float4 a4 = *reinterpret_cast<const float4*>(&sA[kk][ty << 2]);
            float4 b4 = *reinterpret_cast<const float4*>(&sB[kk][tx << 2]);
            float a[4] = {a4.x, a4.y, a4.z, a4.w};
            float b[4] = {b4.x, b4.y, b4.z, b4.w};
#pragma unroll
            for (int i = 0; i < 4; i++)
#pragma unroll
                for (int j = 0; j < 4; j++)
                    acc[i][j] = fmaf(a[i], b[j], acc[i][j]);
        }
        __syncthreads();
    }

    float4 bv = make_float4(0.f, 0.f, 0.f, 0.f);
    if (bias) bv = *reinterpret_cast<const float4*>(bias + col0 + (tx << 2));
#pragma unroll
    for (int i = 0; i < 4; i++) {
        int gr = row0 + (ty << 2) + i;
        if (gr >= M) continue;
        float* cp = C + (size_t)gr * 256 + col0 + (tx << 2);
        float4 r = make_float4(acc[i][0] + bv.x, acc[i][1] + bv.y,
                               acc[i][2] + bv.z, acc[i][3] + bv.w);
        if (accum) {
            float4 o = *reinterpret_cast<const float4*>(cp);
            r.x += o.x; r.y += o.y; r.z += o.z; r.w += o.w;
        }
        *reinterpret_cast<float4*>(cp) = r;
    }
}

// ---------------- EGAT edge kernel (atom graph): warp per bond ----------------
__global__ void edgeA_kernel(
    const float* __restrict__ ni, const float* __restrict__ nj,
    const float* __restrict__ fe, const float* __restrict__ efeats,
    const float* __restrict__ bias, const float* __restrict__ attn,
    const int* __restrict__ src, const int* __restrict__ dst,
    float* __restrict__ fedge, float* __restrict__ logit,
    unsigned* __restrict__ segmax,
    float* __restrict__ aggn, float* __restrict__ cntn, int E)
{
    int e    = (blockIdx.x * blockDim.x + threadIdx.x) >> 5;
    int lane = threadIdx.x & 31;
    if (e >= E) return;
    int s = src[e], d = dst[e];
    const float* ap = ni + (size_t)s * 256;
    const float* bp = nj + (size_t)d * 256;
    const float* cp = fe + (size_t)e * 256;
    float l0 = 0, l1 = 0, l2 = 0, l3 = 0, f0 = 0, f1 = 0;
#pragma unroll
    for (int i = 0; i < 8; i++) {
        int dim = i * 32 + lane;
        float v = lrelu(ap[dim] + bp[dim] + cp[dim] + bias[dim]);
        float av = v * attn[dim];
        if (i < 2) l0 += av; else if (i < 4) l1 += av;
        else if (i < 6) l2 += av; else l3 += av;
        if (i & 1) f1 += v; else f0 += v;
    }
    warpReduce4(l0, l1, l2, l3);
    fedge[(size_t)e * 64 + lane]      = f0;
    fedge[(size_t)e * 64 + 32 + lane] = f1;
    if (lane < 4) {
        float l = (lane == 0) ? l0 : (lane == 1) ? l1 : (lane == 2) ? l2 : l3;
        logit[(size_t)e * 4 + lane] = l;
        atomicMax(segmax + (size_t)d * 4 + lane, fenc(l));
    }
    // segment-mean numerator of efeats (128 floats = 32 float4, one per lane)
    float4 ev = reinterpret_cast<const float4*>(efeats + (size_t)e * 128)[lane];
    atomicAdd4(aggn + (size_t)d * 128 + lane * 4, ev);
    if (lane == 0) atomicAdd(cntn + d, 1.0f);
}

// ---------------- line-graph edge kernel (bond->angle): warp per angle ----------------
__global__ void edgeB_kernel(
    const float* __restrict__ lni, const float* __restrict__ lnj,
    const float* __restrict__ lx, const float* __restrict__ xfeats,
    const float* __restrict__ bias, const float* __restrict__ attn,
    const int* __restrict__ lsrc, const int* __restrict__ ldst,
    float* __restrict__ logit, unsigned* __restrict__ segmax,
    float* __restrict__ aggx, float* __restrict__ cnte, int EL)
{
    int el   = (blockIdx.x * blockDim.x + threadIdx.x) >> 5;
    int lane = threadIdx.x & 31;
    if (el >= EL) return;
    int s = lsrc[el], d = ldst[el];
    const float* ap = lni + (size_t)s * 256;
    const float* bp = lnj + (size_t)d * 256;
    const float* cp = lx + (size_t)el * 256;
    float l0 = 0, l1 = 0, l2 = 0, l3 = 0;
#pragma unroll
    for (int i = 0; i < 8; i++) {
        int dim = i * 32 + lane;
        float v = lrelu(ap[dim] + bp[dim] + cp[dim] + bias[dim]);
        float av = v * attn[dim];
        if (i < 2) l0 += av; else if (i < 4) l1 += av;
        else if (i < 6) l2 += av; else l3 += av;
    }
    warpReduce4(l0, l1, l2, l3);
    if (lane < 4) {
        float l = (lane == 0) ? l0 : (lane == 1) ? l1 : (lane == 2) ? l2 : l3;
        logit[(size_t)el * 4 + lane] = l;
        atomicMax(segmax + (size_t)d * 4 + lane, fenc(l));
    }
    if (lane < 16) {  // 64 floats = 16 float4
        float4 xv = reinterpret_cast<const float4*>(xfeats + (size_t)el * 64)[lane];
        atomicAdd4(aggx + (size_t)d * 64 + lane * 4, xv);
    }
    if (lane == 0) atomicAdd(cnte + d, 1.0f);
}

// ---------------- graph branch edge kernel (atom->bond): warp per bond ----------------
__global__ void edgeC_kernel(
    const float* __restrict__ gi, const float* __restrict__ gj,
    const float* __restrict__ gfe, const float* __restrict__ hnode,
    const float* __restrict__ bias, const float* __restrict__ attn,
    const int* __restrict__ src, const int* __restrict__ dst,
    float* __restrict__ logit, unsigned* __restrict__ segmax,
    float* __restrict__ nedge, int E)
{
    int e    = (blockIdx.x * blockDim.x + threadIdx.x) >> 5;
    int lane = threadIdx.x & 31;
    if (e >= E) return;
    int s = src[e], d = dst[e];
    const float* ap = gi + (size_t)s * 256;
    const float* bp = gj + (size_t)d * 256;
    const float* cp = gfe + (size_t)e * 256;
    float l0 = 0, l1 = 0, l2 = 0, l3 = 0;
#pragma unroll
    for (int i = 0; i < 8; i++) {
        int dim = i * 32 + lane;
        float v = lrelu(ap[dim] + bp[dim] + cp[dim] + bias[dim]);
        float av = v * attn[dim];
        if (i < 2) l0 += av; else if (i < 4) l1 += av;
        else if (i < 6) l2 += av; else l3 += av;
    }
    warpReduce4(l0, l1, l2, l3);
    if (lane < 4) {
        float l = (lane == 0) ? l0 : (lane == 1) ? l1 : (lane == 2) ? l2 : l3;
        logit[(size_t)e * 4 + lane] = l;
        atomicMax(segmax + (size_t)d * 4 + lane, fenc(l));
    }
    if (lane < 16) {  // node_edge = h_node[src] + h_node[dst]
        float4 a = reinterpret_cast<const float4*>(hnode + (size_t)s * 64)[lane];
        float4 b = reinterpret_cast<const float4*>(hnode + (size_t)d * 64)[lane];
        a.x += b.x; a.y += b.y; a.z += b.z; a.w += b.w;
        reinterpret_cast<float4*>(nedge + (size_t)e * 64)[lane] = a;
    }
}

// ---------------- softmax exp pass: logits -> exp(logit - segmax), atomic segsum ----------------
__global__ void exp_kernel(float* __restrict__ lg, const int* __restrict__ seg,
                           const unsigned* __restrict__ segmax,
                           float* __restrict__ segsum, int M)
{
    int i = blockIdx.x * blockDim.x + threadIdx.x;
    if (i >= M * 4) return;
    int e = i >> 2, hh = i & 3;
    int d = seg[e];
    float ex = expf(lg[i] - fdec(segmax[(size_t)d * 4 + hh]));
    atomicAdd(segsum + (size_t)d * 4 + hh, ex);
    lg[i] = ex;
}

// normalize in place: w[i] /= segsum[seg]
__global__ void norm_kernel(float* __restrict__ w, const int* __restrict__ seg,
                            const float* __restrict__ segsum, int M)
{
    int i = blockIdx.x * blockDim.x + threadIdx.x;
    if (i >= M * 4) return;
    w[i] = w[i] / segsum[(size_t)seg[i >> 2] * 4 + (i & 3)];
}

// segment mean finalize: buf[i] /= max(cnt,1)
__global__ void div_mean(float* __restrict__ buf, const float* __restrict__ cnt,
                         int total, int cols)
{
    int i = blockIdx.x * blockDim.x + threadIdx.x;
    if (i >= total) return;
    buf[i] = buf[i] / fmaxf(cnt[i / cols], 1.0f);
}

// ---------------- EGAT node aggregation: acc[dst] += h[src] * att ----------------
__global__ void agg_node(const float* __restrict__ h, const float* __restrict__ ex,
                         const float* __restrict__ segsum,
                         const int* __restrict__ src, const int* __restrict__ dst,
                         float* __restrict__ acc, int E)
{
    int e    = (blockIdx.x * blockDim.x + threadIdx.x) >> 5;
    int lane = threadIdx.x & 31;
    if (e >= E) return;
    int s = src[e], d = dst[e];
    const float* wp = ex + (size_t)e * 4;
    const float* sp = segsum + (size_t)d * 4;
    float w0 = wp[0] / sp[0], w1 = wp[1] / sp[1], w2 = wp[2] / sp[2], w3 = wp[3] / sp[3];
    const float4* mp = reinterpret_cast<const float4*>(h + (size_t)s * 256);
    float* apd = acc + (size_t)d * 256;
#pragma unroll
    for (int j = 0; j < 2; j++) {
        int i4 = lane + j * 32;   // float4 index 0..63 ; head = i4/16
        float4 v = mp[i4];
        float wh = (i4 < 16) ? w0 : (i4 < 32) ? w1 : (i4 < 48) ? w2 : w3;
        v.x *= wh; v.y *= wh; v.z *= wh; v.w *= wh;
        atomicAdd4(apd + i4 * 4, v);
    }
}

// ---------------- line-graph aggregation: acc[ldst] += m[lsrc] * w ----------------
// mode 0: w = wbuf[el]/segsum[ldst]   (lg branch; wbuf holds exp'd logits)
// mode 1: w = wbuf[ldst]              (g branch; wbuf prenormalized per bond)
__global__ void agg_lg(const float* __restrict__ m, const float* __restrict__ wbuf,
                       const float* __restrict__ segsum,
                       const int* __restrict__ lsrc, const int* __restrict__ ldst,
                       float* __restrict__ acc, int EL, int mode)
{
    int el   = (blockIdx.x * blockDim.x + threadIdx.x) >> 5;
    int lane = threadIdx.x & 31;
    if (el >= EL) return;
    int s = lsrc[el], d = ldst[el];
    float w0, w1, w2, w3;
    if (mode == 0) {
        const float* wp = wbuf + (size_t)el * 4;
        const float* sp = segsum + (size_t)d * 4;
        w0 = wp[0] / sp[0]; w1 = wp[1] / sp[1]; w2 = wp[2] / sp[2]; w3 = wp[3] / sp[3];
    } else {
        const float* wp = wbuf + (size_t)d * 4;
        w0 = wp[0]; w1 = wp[1]; w2 = wp[2]; w3 = wp[3];
    }
    const float4* mp = reinterpret_cast<const float4*>(m + (size_t)s * 256);
    float* apd = acc + (size_t)d * 256;
#pragma unroll
    for (int j = 0; j < 2; j++) {
        int i4 = lane + j * 32;
        float4 v = mp[i4];
        float wh = (i4 < 16) ? w0 : (i4 < 32) ? w1 : (i4 < 48) ? w2 : w3;
        v.x *= wh; v.y *= wh; v.z *= wh; v.w *= wh;
        atomicAdd4(apd + i4 * 4, v);
    }
}

// h_node[n,dd] = sum_h leaky(acc[n, h*64+dd])
__global__ void fin_node(const float* __restrict__ acc, float* __restrict__ hnode, int N)
{
    int i = blockIdx.x * blockDim.x + threadIdx.x;
    if (i >= N * 64) return;
    int n = i >> 6, dd = i & 63;
    const float* a = acc + (size_t)n * 256 + dd;
    hnode[i] = lrelu(a[0]) + lrelu(a[64]) + lrelu(a[128]) + lrelu(a[192]);
}

// out[e,dd] (+)= sum_h leaky(acc[e, h*64+dd])
__global__ void fin_out(const float* __restrict__ acc, float* __restrict__ out, int E, int add)
{
    int i = blockIdx.x * blockDim.x + threadIdx.x;
    if (i >= E * 64) return;
    int e = i >> 6, dd = i & 63;
    const float* a = acc + (size_t)e * 256 + dd;
    float s = lrelu(a[0]) + lrelu(a[64]) + lrelu(a[128]) + lrelu(a[192]);
    out[i] = add ? out[i] + s : s;
}

// ---------------- host side ----------------
static inline void gemm(const float* A, int ldA, const float* W, int ldW,
                        const float* bias, float* C, int M, int K, int accum)
{
    dim3 grid((unsigned)((M + 63) / 64), 4);
    gemm_nt<<<grid, 256>>>(A, ldA, W, ldW, bias, C, M, K, accum);
}

static inline int cdiv(long a, long b) { return (int)((a + b - 1) / b); }

extern "C" void kernel_launch(void* const* d_in, const int* in_sizes, int n_in,
                              void* d_out, int out_size)
{
    (void)in_sizes; (void)n_in; (void)out_size;
    const float* nfeats  = (const float*)d_in[0];
    const float* efeats  = (const float*)d_in[1];
    const float* xfeats  = (const float*)d_in[2];
    const float* eWni    = (const float*)d_in[3];
    const float* eWnj    = (const float*)d_in[4];
    const float* eWfij   = (const float*)d_in[5];
    const float* eWnode  = (const float*)d_in[6];
    const float* ebnode  = (const float*)d_in[7];
    const float* eattn   = (const float*)d_in[8];
    const float* ebias   = (const float*)d_in[9];
    const float* lgWni   = (const float*)d_in[10];
    const float* lgWnj   = (const float*)d_in[11];
    const float* lgWfij  = (const float*)d_in[12];
    const float* lgWnode = (const float*)d_in[13];
    const float* lgbnode = (const float*)d_in[14];
    const float* lgattn  = (const float*)d_in[15];
    const float* lgbias  = (const float*)d_in[16];
    const float* gWni    = (const float*)d_in[17];
    const float* gWnj    = (const float*)d_in[18];
    const float* gWfij   = (const float*)d_in[19];
    const float* gWnode  = (const float*)d_in[20];
    const float* gbnode  = (const float*)d_in[21];
    const float* gattn   = (const float*)d_in[22];
    const float* gbias   = (const float*)d_in[23];
    const int*   src     = (const int*)d_in[24];
    const int*   dst     = (const int*)d_in[25];
    const int*   lsrc    = (const int*)d_in[26];
    const int*   ldst    = (const int*)d_in[27];
    float* out = (float*)d_out;

    void* p;
    float *ni, *nj, *big, *mbuf, *acc, *h, *fedge, *hnode, *aggn, *cntn;
    float *aggx, *cnte, *logE, *alg, *ag, *ssum, *nedge;
    unsigned* smax;
    cudaGetSymbolAddress(&p, g_ni);    ni    = (float*)p;
    cudaGetSymbolAddress(&p, g_nj);    nj    = (float*)p;
    cudaGetSymbolAddress(&p, g_big);   big   = (float*)p;
    cudaGetSymbolAddress(&p, g_mbuf);  mbuf  = (float*)p;
    cudaGetSymbolAddress(&p, g_accb);  acc   = (float*)p;
    cudaGetSymbolAddress(&p, g_hb);    h     = (float*)p;
    cudaGetSymbolAddress(&p, g_fedge); fedge = (float*)p;
    cudaGetSymbolAddress(&p, g_hnode); hnode = (float*)p;
    cudaGetSymbolAddress(&p, g_aggn);  aggn  = (float*)p;
    cudaGetSymbolAddress(&p, g_cntn);  cntn  = (float*)p;
    cudaGetSymbolAddress(&p, g_aggx);  aggx  = (float*)p;
    cudaGetSymbolAddress(&p, g_cnte);  cnte  = (float*)p;
    cudaGetSymbolAddress(&p, g_logE);  logE  = (float*)p;
    cudaGetSymbolAddress(&p, g_alg);   alg   = (float*)p;
    cudaGetSymbolAddress(&p, g_ag);    ag    = (float*)p;
    cudaGetSymbolAddress(&p, g_smax);  smax  = (unsigned*)p;
    cudaGetSymbolAddress(&p, g_ssum);  ssum  = (float*)p;
    cudaGetSymbolAddress(&p, g_nedge); nedge = (float*)p;

    const int TPB = 256;

    // ================= Stage A: EGAT on atom graph =================
    cudaMemsetAsync(smax, 0, (size_t)NN * 4 * sizeof(unsigned));
    cudaMemsetAsync(ssum, 0, (size_t)NN * 4 * sizeof(float));
    cudaMemsetAsync(aggn, 0, (size_t)NN * 128 * sizeof(float));
    cudaMemsetAsync(cntn, 0, (size_t)NN * sizeof(float));
    gemm(nfeats, 128, eWni, 128, nullptr, ni, NN, 128, 0);
    gemm(nfeats, 128, eWnj, 128, nullptr, nj, NN, 128, 0);
    gemm(efeats, 128, eWfij, 128, nullptr, big, EE, 128, 0);   // fe
    edgeA_kernel<<<cdiv((long)EE * 32, TPB), TPB>>>(
        ni, nj, big, efeats, ebias, eattn, src, dst,
        fedge, logE, smax, aggn, cntn, EE);
    exp_kernel<<<cdiv((long)EE * 4, TPB), TPB>>>(logE, dst, smax, ssum, EE);
    div_mean<<<cdiv((long)NN * 128, TPB), TPB>>>(aggn, cntn, NN * 128, 128);
    gemm(nfeats, 128, eWnode, 256, ebnode, h, NN, 128, 0);
    gemm(aggn, 128, eWnode + 128, 256, nullptr, h, NN, 128, 1);
    cudaMemsetAsync(ni, 0, (size_t)NN * 256 * sizeof(float));  // ni dead -> node accumulator
    agg_node<<<cdiv((long)EE * 32, TPB), TPB>>>(h, logE, ssum, src, dst, ni, EE);
    fin_node<<<cdiv((long)NN * 64, TPB), TPB>>>(ni, hnode, NN);

    // ================= Stage B: line-graph branch (bond -> angle) =================
    cudaMemsetAsync(smax, 0, (size_t)EE * 4 * sizeof(unsigned));
    cudaMemsetAsync(ssum, 0, (size_t)EE * 4 * sizeof(float));
    cudaMemsetAsync(aggx, 0, (size_t)EE * 64 * sizeof(float));
    cudaMemsetAsync(cnte, 0, (size_t)EE * sizeof(float));
    gemm(fedge, 64, lgWni, 64, nullptr, mbuf, EE, 64, 0);      // lni
    gemm(fedge, 64, lgWnj, 64, nullptr, acc, EE, 64, 0);       // lnj
    gemm(xfeats, 64, lgWfij, 64, nullptr, big, ELL, 64, 0);    // lx
    edgeB_kernel<<<cdiv((long)ELL * 32, TPB), TPB>>>(
        mbuf, acc, big, xfeats, lgbias, lgattn, lsrc, ldst,
        alg, smax, aggx, cnte, ELL);
    exp_kernel<<<cdiv((long)ELL * 4, TPB), TPB>>>(alg, ldst, smax, ssum, ELL);
    div_mean<<<cdiv((long)EE * 64, TPB), TPB>>>(aggx, cnte, EE * 64, 64);
    gemm(fedge, 64, lgWnode, 128, lgbnode, mbuf, EE, 64, 0);   // m1 (overwrites lni)
    gemm(aggx, 64, lgWnode + 64, 128, nullptr, mbuf, EE, 64, 1);
    cudaMemsetAsync(acc, 0, (size_t)EE * 256 * sizeof(float)); // lnj dead -> lg accumulator
    agg_lg<<<cdiv((long)ELL * 32, TPB), TPB>>>(mbuf, alg, ssum, lsrc, ldst, acc, ELL, 0);
    fin_out<<<cdiv((long)EE * 64, TPB), TPB>>>(acc, out, EE, 0);

    // ================= Stage C: graph branch (atom -> bond) =================
    cudaMemsetAsync(smax, 0, (size_t)NN * 4 * sizeof(unsigned));
    cudaMemsetAsync(ssum, 0, (size_t)NN * 4 * sizeof(float));
    gemm(hnode, 64, gWni, 64, nullptr, ni, NN, 64, 0);         // gi
    gemm(hnode, 64, gWnj, 64, nullptr, nj, NN, 64, 0);         // gj
    gemm(fedge, 64, gWfij, 64, nullptr, big, EE, 64, 0);       // gfe
    edgeC_kernel<<<cdiv((long)EE * 32, TPB), TPB>>>(
        ni, nj, big, hnode, gbias, gattn, src, dst,
        ag, smax, nedge, EE);
    exp_kernel<<<cdiv((long)EE * 4, TPB), TPB>>>(ag, dst, smax, ssum, EE);
    norm_kernel<<<cdiv((long)EE * 4, TPB), TPB>>>(ag, dst, ssum, EE);
    gemm(nedge, 64, gWnode, 128, gbnode, mbuf, EE, 64, 0);     // m2
    gemm(fedge, 64, gWnode + 64, 128, nullptr, mbuf, EE, 64, 1);
    cudaMemsetAsync(acc, 0, (size_t)EE * 256 * sizeof(float));
    agg_lg<<<cdiv((long)ELL * 32, TPB), TPB>>>(mbuf, ag, ssum, lsrc, ldst, acc, ELL, 1);
    fin_out<<<cdiv((long)EE * 64, TPB), TPB>>>(acc, out, EE, 1);
}

// round 10
// speedup vs baseline: 1.0409x; 1.0409x over previous
#include <cuda_runtime.h>

#define NN   50000
#define EE   150000
#define ELL  300000

// ---------------- scratch (device globals; no runtime allocation) ----------------
__device__ __align__(16) float    g_ni   [(size_t)NN * 256];   // ni, then node-acc, then gi
__device__ __align__(16) float    g_nj   [(size_t)NN * 256];   // nj, then gj
__device__ __align__(16) float    g_big  [(size_t)ELL * 256];  // fe, then lx, then gfe
__device__ __align__(16) float    g_mbuf [(size_t)EE * 256];   // lni, then m1, then m2
__device__ __align__(16) float    g_accb [(size_t)EE * 256];   // lnj, then lg-acc, then g-acc
__device__ __align__(16) float    g_hb   [(size_t)NN * 256];   // node transform h
__device__ __align__(16) float    g_fedge[(size_t)EE * 64];
__device__ __align__(16) float    g_hnode[(size_t)NN * 64];
__device__ __align__(16) float    g_aggn [(size_t)NN * 128];
__device__             float      g_cntn [NN];
__device__ __align__(16) float    g_aggx [(size_t)EE * 64];
__device__             float      g_cnte [EE];
__device__             float      g_logE [(size_t)EE * 4];
__device__             float      g_alg  [(size_t)ELL * 4];
__device__             float      g_ag   [(size_t)EE * 4];
__device__             unsigned   g_smax [(size_t)EE * 4];
__device__             float      g_ssum [(size_t)EE * 4];
__device__ __align__(16) float    g_nedge[(size_t)EE * 64];

// ---------------- device helpers ----------------
__device__ __forceinline__ float lrelu(float v) { return v >= 0.f ? v : 0.01f * v; }

// monotone encoding of float for unsigned atomicMax
__device__ __forceinline__ unsigned fenc(float f) {
    unsigned u = __float_as_uint(f);
    return (u & 0x80000000u) ? ~u : (u | 0x80000000u);
}
__device__ __forceinline__ float fdec(unsigned e) {
    unsigned u = (e & 0x80000000u) ? (e ^ 0x80000000u) : ~e;
    return __uint_as_float(u);
}

__device__ __forceinline__ void atomicAdd4(float* p, float4 v) {
#if defined(__CUDA_ARCH__) && (__CUDA_ARCH__ >= 900)
    atomicAdd(reinterpret_cast<float4*>(p), v);
#else
    atomicAdd(p + 0, v.x); atomicAdd(p + 1, v.y);
    atomicAdd(p + 2, v.z); atomicAdd(p + 3, v.w);
#endif
}

__device__ __forceinline__ void warpReduce4(float& a, float& b, float& c, float& d) {
#pragma unroll
    for (int off = 16; off; off >>= 1) {
        a += __shfl_xor_sync(0xffffffffu, a, off);
        b += __shfl_xor_sync(0xffffffffu, b, off);
        c += __shfl_xor_sync(0xffffffffu, c, off);
        d += __shfl_xor_sync(0xffffffffu, d, off);
    }
}

// ---------------- GEMM: C[M,256] = A[M,K] @ W[256,K]^T (+bias, +=C) ----------------
// 128x128 tile per 256-thread block, 8x8 register blocking per thread, k-tile 16.
__global__ void __launch_bounds__(256, 2) gemm_nt(
    const float* __restrict__ A, int ldA,
    const float* __restrict__ W, int ldW,
    const float* __restrict__ bias,
    float* __restrict__ C, int M, int K, int accum)
{
    __shared__ __align__(16) float sA[16][128];
    __shared__ __align__(16) float sB[16][128];
    const int tid  = threadIdx.x;
    const int tx   = tid & 15, ty = tid >> 4;          // 16x16 thread grid
    const int row0 = blockIdx.x * 128, col0 = blockIdx.y * 128;
    const int lr   = tid >> 2;                          // 0..63
    const int lc   = (tid & 3) << 2;                    // 0,4,8,12

    float acc[8][8] = {};

    for (int k0 = 0; k0 < K; k0 += 16) {
#pragma unroll
        for (int half = 0; half < 2; half++) {
            int r = lr + half * 64;
            int gr = row0 + r;
            float4 va = make_float4(0.f, 0.f, 0.f, 0.f);
            if (gr < M) va = *reinterpret_cast<const float4*>(A + (size_t)gr * ldA + k0 + lc);
            sA[lc + 0][r] = va.x; sA[lc + 1][r] = va.y;
            sA[lc + 2][r] = va.z; sA[lc + 3][r] = va.w;
            float4 vb = *reinterpret_cast<const float4*>(W + (size_t)(col0 + r) * ldW + k0 + lc);
            sB[lc + 0][r] = vb.x; sB[lc + 1][r] = vb.y;
            sB[lc + 2][r] = vb.z; sB[lc + 3][r] = vb.w;
        }
        __syncthreads();
#pragma unroll
        for (int kk = 0; kk < 16; kk++) {
            float a[8], b[8];
            *reinterpret_cast<float4*>(&a[0]) = *reinterpret_cast<const float4*>(&sA[kk][ty * 8]);
            *reinterpret_cast<float4*>(&a[4]) = *reinterpret_cast<const float4*>(&sA[kk][ty * 8 + 4]);
            *reinterpret_cast<float4*>(&b[0]) = *reinterpret_cast<const float4*>(&sB[kk][tx * 8]);
            *reinterpret_cast<float4*>(&b[4]) = *reinterpret_cast<const float4*>(&sB[kk][tx * 8 + 4]);
#pragma unroll
            for (int i = 0; i < 8; i++)
#pragma unroll
                for (int j = 0; j < 8; j++)
                    acc[i][j] = fmaf(a[i], b[j], acc[i][j]);
        }
        __syncthreads();
    }

    float4 bv0 = make_float4(0.f, 0.f, 0.f, 0.f);
    float4 bv1 = make_float4(0.f, 0.f, 0.f, 0.f);
    if (bias) {
        bv0 = *reinterpret_cast<const float4*>(bias + col0 + tx * 8);
        bv1 = *reinterpret_cast<const float4*>(bias + col0 + tx * 8 + 4);
    }
#pragma unroll
    for (int i = 0; i < 8; i++) {
        int gr = row0 + ty * 8 + i;
        if (gr >= M) continue;
        float* cp = C + (size_t)gr * 256 + col0 + tx * 8;
        float4 r0 = make_float4(acc[i][0] + bv0.x, acc[i][1] + bv0.y,
                                acc[i][2] + bv0.z, acc[i][3] + bv0.w);
        float4 r1 = make_float4(acc[i][4] + bv1.x, acc[i][5] + bv1.y,
                                acc[i][6] + bv1.z, acc[i][7] + bv1.w);
        if (accum) {
            float4 o0 = *reinterpret_cast<const float4*>(cp);
            float4 o1 = *reinterpret_cast<const float4*>(cp + 4);
            r0.x += o0.x; r0.y += o0.y; r0.z += o0.z; r0.w += o0.w;
            r1.x += o1.x; r1.y += o1.y; r1.z += o1.z; r1.w += o1.w;
        }
        *reinterpret_cast<float4*>(cp)     = r0;
        *reinterpret_cast<float4*>(cp + 4) = r1;
    }
}

// ---------------- EGAT edge kernel (atom graph): warp per bond ----------------
__global__ void edgeA_kernel(
    const float* __restrict__ ni, const float* __restrict__ nj,
    const float* __restrict__ fe, const float* __restrict__ efeats,
    const float* __restrict__ bias, const float* __restrict__ attn,
    const int* __restrict__ src, const int* __restrict__ dst,
    float* __restrict__ fedge, float* __restrict__ logit,
    unsigned* __restrict__ segmax,
    float* __restrict__ aggn, float* __restrict__ cntn, int E)
{
    int e    = (blockIdx.x * blockDim.x + threadIdx.x) >> 5;
    int lane = threadIdx.x & 31;
    if (e >= E) return;
    int s = src[e], d = dst[e];
    const float* ap = ni + (size_t)s * 256;
    const float* bp = nj + (size_t)d * 256;
    const float* cp = fe + (size_t)e * 256;
    float l0 = 0, l1 = 0, l2 = 0, l3 = 0, f0 = 0, f1 = 0;
#pragma unroll
    for (int i = 0; i < 8; i++) {
        int dim = i * 32 + lane;
        float v = lrelu(ap[dim] + bp[dim] + cp[dim] + bias[dim]);
        float av = v * attn[dim];
        if (i < 2) l0 += av; else if (i < 4) l1 += av;
        else if (i < 6) l2 += av; else l3 += av;
        if (i & 1) f1 += v; else f0 += v;
    }
    warpReduce4(l0, l1, l2, l3);
    fedge[(size_t)e * 64 + lane]      = f0;
    fedge[(size_t)e * 64 + 32 + lane] = f1;
    if (lane < 4) {
        float l = (lane == 0) ? l0 : (lane == 1) ? l1 : (lane == 2) ? l2 : l3;
        logit[(size_t)e * 4 + lane] = l;
        atomicMax(segmax + (size_t)d * 4 + lane, fenc(l));
    }
    // segment-mean numerator of efeats (128 floats = 32 float4, one per lane)
    float4 ev = reinterpret_cast<const float4*>(efeats + (size_t)e * 128)[lane];
    atomicAdd4(aggn + (size_t)d * 128 + lane * 4, ev);
    if (lane == 0) atomicAdd(cntn + d, 1.0f);
}

// ---------------- line-graph edge kernel (bond->angle): warp per angle ----------------
__global__ void edgeB_kernel(
    const float* __restrict__ lni, const float* __restrict__ lnj,
    const float* __restrict__ lx, const float* __restrict__ xfeats,
    const float* __restrict__ bias, const float* __restrict__ attn,
    const int* __restrict__ lsrc, const int* __restrict__ ldst,
    float* __restrict__ logit, unsigned* __restrict__ segmax,
    float* __restrict__ aggx, float* __restrict__ cnte, int EL)
{
    int el   = (blockIdx.x * blockDim.x + threadIdx.x) >> 5;
    int lane = threadIdx.x & 31;
    if (el >= EL) return;
    int s = lsrc[el], d = ldst[el];
    const float* ap = lni + (size_t)s * 256;
    const float* bp = lnj + (size_t)d * 256;
    const float* cp = lx + (size_t)el * 256;
    float l0 = 0, l1 = 0, l2 = 0, l3 = 0;
#pragma unroll
    for (int i = 0; i < 8; i++) {
        int dim = i * 32 + lane;
        float v = lrelu(ap[dim] + bp[dim] + cp[dim] + bias[dim]);
        float av = v * attn[dim];
        if (i < 2) l0 += av; else if (i < 4) l1 += av;
        else if (i < 6) l2 += av; else l3 += av;
    }
    warpReduce4(l0, l1, l2, l3);
    if (lane < 4) {
        float l = (lane == 0) ? l0 : (lane == 1) ? l1 : (lane == 2) ? l2 : l3;
        logit[(size_t)el * 4 + lane] = l;
        atomicMax(segmax + (size_t)d * 4 + lane, fenc(l));
    }
    if (lane < 16) {  // 64 floats = 16 float4
        float4 xv = reinterpret_cast<const float4*>(xfeats + (size_t)el * 64)[lane];
        atomicAdd4(aggx + (size_t)d * 64 + lane * 4, xv);
    }
    if (lane == 0) atomicAdd(cnte + d, 1.0f);
}

// ---------------- graph branch edge kernel (atom->bond): warp per bond ----------------
__global__ void edgeC_kernel(
    const float* __restrict__ gi, const float* __restrict__ gj,
    const float* __restrict__ gfe, const float* __restrict__ hnode,
    const float* __restrict__ bias, const float* __restrict__ attn,
    const int* __restrict__ src, const int* __restrict__ dst,
    float* __restrict__ logit, unsigned* __restrict__ segmax,
    float* __restrict__ nedge, int E)
{
    int e    = (blockIdx.x * blockDim.x + threadIdx.x) >> 5;
    int lane = threadIdx.x & 31;
    if (e >= E) return;
    int s = src[e], d = dst[e];
    const float* ap = gi + (size_t)s * 256;
    const float* bp = gj + (size_t)d * 256;
    const float* cp = gfe + (size_t)e * 256;
    float l0 = 0, l1 = 0, l2 = 0, l3 = 0;
#pragma unroll
    for (int i = 0; i < 8; i++) {
        int dim = i * 32 + lane;
        float v = lrelu(ap[dim] + bp[dim] + cp[dim] + bias[dim]);
        float av = v * attn[dim];
        if (i < 2) l0 += av; else if (i < 4) l1 += av;
        else if (i < 6) l2 += av; else l3 += av;
    }
    warpReduce4(l0, l1, l2, l3);
    if (lane < 4) {
        float l = (lane == 0) ? l0 : (lane == 1) ? l1 : (lane == 2) ? l2 : l3;
        logit[(size_t)e * 4 + lane] = l;
        atomicMax(segmax + (size_t)d * 4 + lane, fenc(l));
    }
    if (lane < 16) {  // node_edge = h_node[src] + h_node[dst]
        float4 a = reinterpret_cast<const float4*>(hnode + (size_t)s * 64)[lane];
        float4 b = reinterpret_cast<const float4*>(hnode + (size_t)d * 64)[lane];
        a.x += b.x; a.y += b.y; a.z += b.z; a.w += b.w;
        reinterpret_cast<float4*>(nedge + (size_t)e * 64)[lane] = a;
    }
}

// ---------------- softmax exp pass: logits -> exp(logit - segmax), atomic segsum ----------------
__global__ void exp_kernel(float* __restrict__ lg, const int* __restrict__ seg,
                           const unsigned* __restrict__ segmax,
                           float* __restrict__ segsum, int M)
{
    int i = blockIdx.x * blockDim.x + threadIdx.x;
    if (i >= M * 4) return;
    int e = i >> 2, hh = i & 3;
    int d = seg[e];
    float ex = expf(lg[i] - fdec(segmax[(size_t)d * 4 + hh]));
    atomicAdd(segsum + (size_t)d * 4 + hh, ex);
    lg[i] = ex;
}

// normalize in place: w[i] /= segsum[seg]
__global__ void norm_kernel(float* __restrict__ w, const int* __restrict__ seg,
                            const float* __restrict__ segsum, int M)
{
    int i = blockIdx.x * blockDim.x + threadIdx.x;
    if (i >= M * 4) return;
    w[i] = w[i] / segsum[(size_t)seg[i >> 2] * 4 + (i & 3)];
}

// segment mean finalize: buf[i] /= max(cnt,1)
__global__ void div_mean(float* __restrict__ buf, const float* __restrict__ cnt,
                         int total, int cols)
{
    int i = blockIdx.x * blockDim.x + threadIdx.x;
    if (i >= total) return;
    buf[i] = buf[i] / fmaxf(cnt[i / cols], 1.0f);
}

// ---------------- EGAT node aggregation: acc[dst] += h[src] * att ----------------
__global__ void agg_node(const float* __restrict__ h, const float* __restrict__ ex,
                         const float* __restrict__ segsum,
                         const int* __restrict__ src, const int* __restrict__ dst,
                         float* __restrict__ acc, int E)
{
    int e    = (blockIdx.x * blockDim.x + threadIdx.x) >> 5;
    int lane = threadIdx.x & 31;
    if (e >= E) return;
    int s = src[e], d = dst[e];
    const float* wp = ex + (size_t)e * 4;
    const float* sp = segsum + (size_t)d * 4;
    float w0 = wp[0] / sp[0], w1 = wp[1] / sp[1], w2 = wp[2] / sp[2], w3 = wp[3] / sp[3];
    const float4* mp = reinterpret_cast<const float4*>(h + (size_t)s * 256);
    float* apd = acc + (size_t)d * 256;
#pragma unroll
    for (int j = 0; j < 2; j++) {
        int i4 = lane + j * 32;   // float4 index 0..63 ; head = i4/16
        float4 v = mp[i4];
        float wh = (i4 < 16) ? w0 : (i4 < 32) ? w1 : (i4 < 48) ? w2 : w3;
        v.x *= wh; v.y *= wh; v.z *= wh; v.w *= wh;
        atomicAdd4(apd + i4 * 4, v);
    }
}

// ---------------- line-graph aggregation: acc[ldst] += m[lsrc] * w ----------------
// mode 0: w = wbuf[el]/segsum[ldst]   (lg branch; wbuf holds exp'd logits)
// mode 1: w = wbuf[ldst]              (g branch; wbuf prenormalized per bond)
__global__ void agg_lg(const float* __restrict__ m, const float* __restrict__ wbuf,
                       const float* __restrict__ segsum,
                       const int* __restrict__ lsrc, const int* __restrict__ ldst,
                       float* __restrict__ acc, int EL, int mode)
{
    int el   = (blockIdx.x * blockDim.x + threadIdx.x) >> 5;
    int lane = threadIdx.x & 31;
    if (el >= EL) return;
    int s = lsrc[el], d = ldst[el];
    float w0, w1, w2, w3;
    if (mode == 0) {
        const float* wp = wbuf + (size_t)el * 4;
        const float* sp = segsum + (size_t)d * 4;
        w0 = wp[0] / sp[0]; w1 = wp[1] / sp[1]; w2 = wp[2] / sp[2]; w3 = wp[3] / sp[3];
    } else {
        const float* wp = wbuf + (size_t)d * 4;
        w0 = wp[0]; w1 = wp[1]; w2 = wp[2]; w3 = wp[3];
    }
    const float4* mp = reinterpret_cast<const float4*>(m + (size_t)s * 256);
    float* apd = acc + (size_t)d * 256;
#pragma unroll
    for (int j = 0; j < 2; j++) {
        int i4 = lane + j * 32;
        float4 v = mp[i4];
        float wh = (i4 < 16) ? w0 : (i4 < 32) ? w1 : (i4 < 48) ? w2 : w3;
        v.x *= wh; v.y *= wh; v.z *= wh; v.w *= wh;
        atomicAdd4(apd + i4 * 4, v);
    }
}

// h_node[n,dd] = sum_h leaky(acc[n, h*64+dd])
__global__ void fin_node(const float* __restrict__ acc, float* __restrict__ hnode, int N)
{
    int i = blockIdx.x * blockDim.x + threadIdx.x;
    if (i >= N * 64) return;
    int n = i >> 6, dd = i & 63;
    const float* a = acc + (size_t)n * 256 + dd;
    hnode[i] = lrelu(a[0]) + lrelu(a[64]) + lrelu(a[128]) + lrelu(a[192]);
}

// out[e,dd] (+)= sum_h leaky(acc[e, h*64+dd])
__global__ void fin_out(const float* __restrict__ acc, float* __restrict__ out, int E, int add)
{
    int i = blockIdx.x * blockDim.x + threadIdx.x;
    if (i >= E * 64) return;
    int e = i >> 6, dd = i & 63;
    const float* a = acc + (size_t)e * 256 + dd;
    float s = lrelu(a[0]) + lrelu(a[64]) + lrelu(a[128]) + lrelu(a[192]);
    out[i] = add ? out[i] + s : s;
}

// ---------------- host side ----------------
static inline void gemm(const float* A, int ldA, const float* W, int ldW,
                        const float* bias, float* C, int M, int K, int accum)
{
    dim3 grid((unsigned)((M + 127) / 128), 2);
    gemm_nt<<<grid, 256>>>(A, ldA, W, ldW, bias, C, M, K, accum);
}

static inline int cdiv(long a, long b) { return (int)((a + b - 1) / b); }

extern "C" void kernel_launch(void* const* d_in, const int* in_sizes, int n_in,
                              void* d_out, int out_size)
{
    (void)in_sizes; (void)n_in; (void)out_size;
    const float* nfeats  = (const float*)d_in[0];
    const float* efeats  = (const float*)d_in[1];
    const float* xfeats  = (const float*)d_in[2];
    const float* eWni    = (const float*)d_in[3];
    const float* eWnj    = (const float*)d_in[4];
    const float* eWfij   = (const float*)d_in[5];
    const float* eWnode  = (const float*)d_in[6];
    const float* ebnode  = (const float*)d_in[7];
    const float* eattn   = (const float*)d_in[8];
    const float* ebias   = (const float*)d_in[9];
    const float* lgWni   = (const float*)d_in[10];
    const float* lgWnj   = (const float*)d_in[11];
    const float* lgWfij  = (const float*)d_in[12];
    const float* lgWnode = (const float*)d_in[13];
    const float* lgbnode = (const float*)d_in[14];
    const float* lgattn  = (const float*)d_in[15];
    const float* lgbias  = (const float*)d_in[16];
    const float* gWni    = (const float*)d_in[17];
    const float* gWnj    = (const float*)d_in[18];
    const float* gWfij   = (const float*)d_in[19];
    const float* gWnode  = (const float*)d_in[20];
    const float* gbnode  = (const float*)d_in[21];
    const float* gattn   = (const float*)d_in[22];
    const float* gbias   = (const float*)d_in[23];
    const int*   src     = (const int*)d_in[24];
    const int*   dst     = (const int*)d_in[25];
    const int*   lsrc    = (const int*)d_in[26];
    const int*   ldst    = (const int*)d_in[27];
    float* out = (float*)d_out;

    void* p;
    float *ni, *nj, *big, *mbuf, *acc, *h, *fedge, *hnode, *aggn, *cntn;
    float *aggx, *cnte, *logE, *alg, *ag, *ssum, *nedge;
    unsigned* smax;
    cudaGetSymbolAddress(&p, g_ni);    ni    = (float*)p;
    cudaGetSymbolAddress(&p, g_nj);    nj    = (float*)p;
    cudaGetSymbolAddress(&p, g_big);   big   = (float*)p;
    cudaGetSymbolAddress(&p, g_mbuf);  mbuf  = (float*)p;
    cudaGetSymbolAddress(&p, g_accb);  acc   = (float*)p;
    cudaGetSymbolAddress(&p, g_hb);    h     = (float*)p;
    cudaGetSymbolAddress(&p, g_fedge); fedge = (float*)p;
    cudaGetSymbolAddress(&p, g_hnode); hnode = (float*)p;
    cudaGetSymbolAddress(&p, g_aggn);  aggn  = (float*)p;
    cudaGetSymbolAddress(&p, g_cntn);  cntn  = (float*)p;
    cudaGetSymbolAddress(&p, g_aggx);  aggx  = (float*)p;
    cudaGetSymbolAddress(&p, g_cnte);  cnte  = (float*)p;
    cudaGetSymbolAddress(&p, g_logE);  logE  = (float*)p;
    cudaGetSymbolAddress(&p, g_alg);   alg   = (float*)p;
    cudaGetSymbolAddress(&p, g_ag);    ag    = (float*)p;
    cudaGetSymbolAddress(&p, g_smax);  smax  = (unsigned*)p;
    cudaGetSymbolAddress(&p, g_ssum);  ssum  = (float*)p;
    cudaGetSymbolAddress(&p, g_nedge); nedge = (float*)p;

    const int TPB = 256;

    // ================= Stage A: EGAT on atom graph =================
    cudaMemsetAsync(smax, 0, (size_t)NN * 4 * sizeof(unsigned));
    cudaMemsetAsync(ssum, 0, (size_t)NN * 4 * sizeof(float));
    cudaMemsetAsync(aggn, 0, (size_t)NN * 128 * sizeof(float));
    cudaMemsetAsync(cntn, 0, (size_t)NN * sizeof(float));
    gemm(nfeats, 128, eWni, 128, nullptr, ni, NN, 128, 0);
    gemm(nfeats, 128, eWnj, 128, nullptr, nj, NN, 128, 0);
    gemm(efeats, 128, eWfij, 128, nullptr, big, EE, 128, 0);   // fe
    edgeA_kernel<<<cdiv((long)EE * 32, TPB), TPB>>>(
        ni, nj, big, efeats, ebias, eattn, src, dst,
        fedge, logE, smax, aggn, cntn, EE);
    exp_kernel<<<cdiv((long)EE * 4, TPB), TPB>>>(logE, dst, smax, ssum, EE);
    div_mean<<<cdiv((long)NN * 128, TPB), TPB>>>(aggn, cntn, NN * 128, 128);
    gemm(nfeats, 128, eWnode, 256, ebnode, h, NN, 128, 0);
    gemm(aggn, 128, eWnode + 128, 256, nullptr, h, NN, 128, 1);
    cudaMemsetAsync(ni, 0, (size_t)NN * 256 * sizeof(float));  // ni dead -> node accumulator
    agg_node<<<cdiv((long)EE * 32, TPB), TPB>>>(h, logE, ssum, src, dst, ni, EE);
    fin_node<<<cdiv((long)NN * 64, TPB), TPB>>>(ni, hnode, NN);

    // ================= Stage B: line-graph branch (bond -> angle) =================
    cudaMemsetAsync(smax, 0, (size_t)EE * 4 * sizeof(unsigned));
    cudaMemsetAsync(ssum, 0, (size_t)EE * 4 * sizeof(float));
    cudaMemsetAsync(aggx, 0, (size_t)EE * 64 * sizeof(float));
    cudaMemsetAsync(cnte, 0, (size_t)EE * sizeof(float));
    gemm(fedge, 64, lgWni, 64, nullptr, mbuf, EE, 64, 0);      // lni
    gemm(fedge, 64, lgWnj, 64, nullptr, acc, EE, 64, 0);       // lnj
    gemm(xfeats, 64, lgWfij, 64, nullptr, big, ELL, 64, 0);    // lx
    edgeB_kernel<<<cdiv((long)ELL * 32, TPB), TPB>>>(
        mbuf, acc, big, xfeats, lgbias, lgattn, lsrc, ldst,
        alg, smax, aggx, cnte, ELL);
    exp_kernel<<<cdiv((long)ELL * 4, TPB), TPB>>>(alg, ldst, smax, ssum, ELL);
    div_mean<<<cdiv((long)EE * 64, TPB), TPB>>>(aggx, cnte, EE * 64, 64);
    gemm(fedge, 64, lgWnode, 128, lgbnode, mbuf, EE, 64, 0);   // m1 (overwrites lni)
    gemm(aggx, 64, lgWnode + 64, 128, nullptr, mbuf, EE, 64, 1);
    cudaMemsetAsync(acc, 0, (size_t)EE * 256 * sizeof(float)); // lnj dead -> lg accumulator
    agg_lg<<<cdiv((long)ELL * 32, TPB), TPB>>>(mbuf, alg, ssum, lsrc, ldst, acc, ELL, 0);
    fin_out<<<cdiv((long)EE * 64, TPB), TPB>>>(acc, out, EE, 0);

    // ================= Stage C: graph branch (atom -> bond) =================
    cudaMemsetAsync(smax, 0, (size_t)NN * 4 * sizeof(unsigned));
    cudaMemsetAsync(ssum, 0, (size_t)NN * 4 * sizeof(float));
    gemm(hnode, 64, gWni, 64, nullptr, ni, NN, 64, 0);         // gi
    gemm(hnode, 64, gWnj, 64, nullptr, nj, NN, 64, 0);         // gj
    gemm(fedge, 64, gWfij, 64, nullptr, big, EE, 64, 0);       // gfe
    edgeC_kernel<<<cdiv((long)EE * 32, TPB), TPB>>>(
        ni, nj, big, hnode, gbias, gattn, src, dst,
        ag, smax, nedge, EE);
    exp_kernel<<<cdiv((long)EE * 4, TPB), TPB>>>(ag, dst, smax, ssum, EE);
    norm_kernel<<<cdiv((long)EE * 4, TPB), TPB>>>(ag, dst, ssum, EE);
    gemm(nedge, 64, gWnode, 128, gbnode, mbuf, EE, 64, 0);     // m2
    gemm(fedge, 64, gWnode + 64, 128, nullptr, mbuf, EE, 64, 1);
    cudaMemsetAsync(acc, 0, (size_t)EE * 256 * sizeof(float));
    agg_lg<<<cdiv((long)ELL * 32, TPB), TPB>>>(mbuf, ag, ssum, lsrc, ldst, acc, ELL, 1);
    fin_out<<<cdiv((long)EE * 64, TPB), TPB>>>(acc, out, EE, 1);
}

// round 11
// speedup vs baseline: 1.0429x; 1.0019x over previous
#include <cuda_runtime.h>

#define NN   50000
#define EE   150000
#define ELL  300000

// ---------------- scratch (device globals; no runtime allocation) ----------------
__device__ __align__(16) float    g_ni   [(size_t)NN * 256];   // ni, then node-acc, then gi
__device__ __align__(16) float    g_nj   [(size_t)NN * 256];   // nj, then gj
__device__ __align__(16) float    g_big  [(size_t)ELL * 256];  // fe, then lx, then gfe
__device__ __align__(16) float    g_mbuf [(size_t)EE * 256];   // lni, then m1, then m2
__device__ __align__(16) float    g_accb [(size_t)EE * 256];   // lnj, then lg-acc, then g-acc
__device__ __align__(16) float    g_hb   [(size_t)NN * 256];   // node transform h
__device__ __align__(16) float    g_fedge[(size_t)EE * 64];
__device__ __align__(16) float    g_hnode[(size_t)NN * 64];
__device__ __align__(16) float    g_aggn [(size_t)NN * 128];
__device__             float      g_cntn [NN];
__device__ __align__(16) float    g_aggx [(size_t)EE * 64];
__device__             float      g_cnte [EE];
__device__             float      g_logE [(size_t)EE * 4];
__device__             float      g_alg  [(size_t)ELL * 4];
__device__             float      g_ag   [(size_t)EE * 4];
__device__             unsigned   g_smax [(size_t)EE * 4];
__device__             float      g_ssum [(size_t)EE * 4];
__device__ __align__(16) float    g_nedge[(size_t)EE * 64];

// ---------------- device helpers ----------------
__device__ __forceinline__ float lrelu(float v) { return v >= 0.f ? v : 0.01f * v; }

// monotone encoding of float for unsigned atomicMax
__device__ __forceinline__ unsigned fenc(float f) {
    unsigned u = __float_as_uint(f);
    return (u & 0x80000000u) ? ~u : (u | 0x80000000u);
}
__device__ __forceinline__ float fdec(unsigned e) {
    unsigned u = (e & 0x80000000u) ? (e ^ 0x80000000u) : ~e;
    return __uint_as_float(u);
}

__device__ __forceinline__ void atomicAdd4(float* p, float4 v) {
#if defined(__CUDA_ARCH__) && (__CUDA_ARCH__ >= 900)
    atomicAdd(reinterpret_cast<float4*>(p), v);
#else
    atomicAdd(p + 0, v.x); atomicAdd(p + 1, v.y);
    atomicAdd(p + 2, v.z); atomicAdd(p + 3, v.w);
#endif
}

__device__ __forceinline__ void warpReduce4(float& a, float& b, float& c, float& d) {
#pragma unroll
    for (int off = 16; off; off >>= 1) {
        a += __shfl_xor_sync(0xffffffffu, a, off);
        b += __shfl_xor_sync(0xffffffffu, b, off);
        c += __shfl_xor_sync(0xffffffffu, c, off);
        d += __shfl_xor_sync(0xffffffffu, d, off);
    }
}

// ---------------- GEMM: C[M,256] = A[M,K] @ W[256,K]^T (+bias, +=C) ----------------
// 128x128 tile per 256-thread block, 8x8 register blocking per thread, k-tile 16.
__global__ void __launch_bounds__(256, 2) gemm_nt(
    const float* __restrict__ A, int ldA,
    const float* __restrict__ W, int ldW,
    const float* __restrict__ bias,
    float* __restrict__ C, int M, int K, int accum)
{
    __shared__ __align__(16) float sA[16][128];
    __shared__ __align__(16) float sB[16][128];
    const int tid  = threadIdx.x;
    const int tx   = tid & 15, ty = tid >> 4;          // 16x16 thread grid
    const int row0 = blockIdx.x * 128, col0 = blockIdx.y * 128;
    const int lr   = tid >> 2;                          // 0..63
    const int lc   = (tid & 3) << 2;                    // 0,4,8,12

    float acc[8][8] = {};

    for (int k0 = 0; k0 < K; k0 += 16) {
#pragma unroll
        for (int half = 0; half < 2; half++) {
            int r = lr + half * 64;
            int gr = row0 + r;
            float4 va = make_float4(0.f, 0.f, 0.f, 0.f);
            if (gr < M) va = *reinterpret_cast<const float4*>(A + (size_t)gr * ldA + k0 + lc);
            sA[lc + 0][r] = va.x; sA[lc + 1][r] = va.y;
            sA[lc + 2][r] = va.z; sA[lc + 3][r] = va.w;
            float4 vb = *reinterpret_cast<const float4*>(W + (size_t)(col0 + r) * ldW + k0 + lc);
            sB[lc + 0][r] = vb.x; sB[lc + 1][r] = vb.y;
            sB[lc + 2][r] = vb.z; sB[lc + 3][r] = vb.w;
        }
        __syncthreads();
#pragma unroll
        for (int kk = 0; kk < 16; kk++) {
            float a[8], b[8];
            *reinterpret_cast<float4*>(&a[0]) = *reinterpret_cast<const float4*>(&sA[kk][ty * 8]);
            *reinterpret_cast<float4*>(&a[4]) = *reinterpret_cast<const float4*>(&sA[kk][ty * 8 + 4]);
            *reinterpret_cast<float4*>(&b[0]) = *reinterpret_cast<const float4*>(&sB[kk][tx * 8]);
            *reinterpret_cast<float4*>(&b[4]) = *reinterpret_cast<const float4*>(&sB[kk][tx * 8 + 4]);
#pragma unroll
            for (int i = 0; i < 8; i++)
#pragma unroll
                for (int j = 0; j < 8; j++)
                    acc[i][j] = fmaf(a[i], b[j], acc[i][j]);
        }
        __syncthreads();
    }

    float4 bv0 = make_float4(0.f, 0.f, 0.f, 0.f);
    float4 bv1 = make_float4(0.f, 0.f, 0.f, 0.f);
    if (bias) {
        bv0 = *reinterpret_cast<const float4*>(bias + col0 + tx * 8);
        bv1 = *reinterpret_cast<const float4*>(bias + col0 + tx * 8 + 4);
    }
#pragma unroll
    for (int i = 0; i < 8; i++) {
        int gr = row0 + ty * 8 + i;
        if (gr >= M) continue;
        float* cp = C + (size_t)gr * 256 + col0 + tx * 8;
        float4 r0 = make_float4(acc[i][0] + bv0.x, acc[i][1] + bv0.y,
                                acc[i][2] + bv0.z, acc[i][3] + bv0.w);
        float4 r1 = make_float4(acc[i][4] + bv1.x, acc[i][5] + bv1.y,
                                acc[i][6] + bv1.z, acc[i][7] + bv1.w);
        if (accum) {
            float4 o0 = *reinterpret_cast<const float4*>(cp);
            float4 o1 = *reinterpret_cast<const float4*>(cp + 4);
            r0.x += o0.x; r0.y += o0.y; r0.z += o0.z; r0.w += o0.w;
            r1.x += o1.x; r1.y += o1.y; r1.z += o1.z; r1.w += o1.w;
        }
        *reinterpret_cast<float4*>(cp)     = r0;
        *reinterpret_cast<float4*>(cp + 4) = r1;
    }
}

// ---------------- EGAT edge kernel (atom graph): warp per bond ----------------
__global__ void edgeA_kernel(
    const float* __restrict__ ni, const float* __restrict__ nj,
    const float* __restrict__ fe, const float* __restrict__ efeats,
    const float* __restrict__ bias, const float* __restrict__ attn,
    const int* __restrict__ src, const int* __restrict__ dst,
    float* __restrict__ fedge, float* __restrict__ logit,
    unsigned* __restrict__ segmax,
    float* __restrict__ aggn, float* __restrict__ cntn, int E)
{
    int e    = (blockIdx.x * blockDim.x + threadIdx.x) >> 5;
    int lane = threadIdx.x & 31;
    if (e >= E) return;
    int s = src[e], d = dst[e];
    const float* ap = ni + (size_t)s * 256;
    const float* bp = nj + (size_t)d * 256;
    const float* cp = fe + (size_t)e * 256;
    float l0 = 0, l1 = 0, l2 = 0, l3 = 0, f0 = 0, f1 = 0;
#pragma unroll
    for (int i = 0; i < 8; i++) {
        int dim = i * 32 + lane;
        float v = lrelu(ap[dim] + bp[dim] + cp[dim] + bias[dim]);
        float av = v * attn[dim];
        if (i < 2) l0 += av; else if (i < 4) l1 += av;
        else if (i < 6) l2 += av; else l3 += av;
        if (i & 1) f1 += v; else f0 += v;
    }
    warpReduce4(l0, l1, l2, l3);
    fedge[(size_t)e * 64 + lane]      = f0;
    fedge[(size_t)e * 64 + 32 + lane] = f1;
    if (lane < 4) {
        float l = (lane == 0) ? l0 : (lane == 1) ? l1 : (lane == 2) ? l2 : l3;
        logit[(size_t)e * 4 + lane] = l;
        atomicMax(segmax + (size_t)d * 4 + lane, fenc(l));
    }
    // segment-mean numerator of efeats (128 floats = 32 float4, one per lane)
    float4 ev = reinterpret_cast<const float4*>(efeats + (size_t)e * 128)[lane];
    atomicAdd4(aggn + (size_t)d * 128 + lane * 4, ev);
    if (lane == 0) atomicAdd(cntn + d, 1.0f);
}

// ---------------- line-graph edge kernel (bond->angle): warp per angle ----------------
__global__ void edgeB_kernel(
    const float* __restrict__ lni, const float* __restrict__ lnj,
    const float* __restrict__ lx, const float* __restrict__ xfeats,
    const float* __restrict__ bias, const float* __restrict__ attn,
    const int* __restrict__ lsrc, const int* __restrict__ ldst,
    float* __restrict__ logit, unsigned* __restrict__ segmax,
    float* __restrict__ aggx, float* __restrict__ cnte, int EL)
{
    int el   = (blockIdx.x * blockDim.x + threadIdx.x) >> 5;
    int lane = threadIdx.x & 31;
    if (el >= EL) return;
    int s = lsrc[el], d = ldst[el];
    const float* ap = lni + (size_t)s * 256;
    const float* bp = lnj + (size_t)d * 256;
    const float* cp = lx + (size_t)el * 256;
    float l0 = 0, l1 = 0, l2 = 0, l3 = 0;
#pragma unroll
    for (int i = 0; i < 8; i++) {
        int dim = i * 32 + lane;
        float v = lrelu(ap[dim] + bp[dim] + cp[dim] + bias[dim]);
        float av = v * attn[dim];
        if (i < 2) l0 += av; else if (i < 4) l1 += av;
        else if (i < 6) l2 += av; else l3 += av;
    }
    warpReduce4(l0, l1, l2, l3);
    if (lane < 4) {
        float l = (lane == 0) ? l0 : (lane == 1) ? l1 : (lane == 2) ? l2 : l3;
        logit[(size_t)el * 4 + lane] = l;
        atomicMax(segmax + (size_t)d * 4 + lane, fenc(l));
    }
    if (lane < 16) {  // 64 floats = 16 float4
        float4 xv = reinterpret_cast<const float4*>(xfeats + (size_t)el * 64)[lane];
        atomicAdd4(aggx + (size_t)d * 64 + lane * 4, xv);
    }
    if (lane == 0) atomicAdd(cnte + d, 1.0f);
}

// ---------------- graph branch edge kernel (atom->bond): warp per bond ----------------
__global__ void edgeC_kernel(
    const float* __restrict__ gi, const float* __restrict__ gj,
    const float* __restrict__ gfe, const float* __restrict__ hnode,
    const float* __restrict__ bias, const float* __restrict__ attn,
    const int* __restrict__ src, const int* __restrict__ dst,
    float* __restrict__ logit, unsigned* __restrict__ segmax,
    float* __restrict__ nedge, int E)
{
    int e    = (blockIdx.x * blockDim.x + threadIdx.x) >> 5;
    int lane = threadIdx.x & 31;
    if (e >= E) return;
    int s = src[e], d = dst[e];
    const float* ap = gi + (size_t)s * 256;
    const float* bp = gj + (size_t)d * 256;
    const float* cp = gfe + (size_t)e * 256;
    float l0 = 0, l1 = 0, l2 = 0, l3 = 0;
#pragma unroll
    for (int i = 0; i < 8; i++) {
        int dim = i * 32 + lane;
        float v = lrelu(ap[dim] + bp[dim] + cp[dim] + bias[dim]);
        float av = v * attn[dim];
        if (i < 2) l0 += av; else if (i < 4) l1 += av;
        else if (i < 6) l2 += av; else l3 += av;
    }
    warpReduce4(l0, l1, l2, l3);
    if (lane < 4) {
        float l = (lane == 0) ? l0 : (lane == 1) ? l1 : (lane == 2) ? l2 : l3;
        logit[(size_t)e * 4 + lane] = l;
        atomicMax(segmax + (size_t)d * 4 + lane, fenc(l));
    }
    if (lane < 16) {  // node_edge = h_node[src] + h_node[dst]
        float4 a = reinterpret_cast<const float4*>(hnode + (size_t)s * 64)[lane];
        float4 b = reinterpret_cast<const float4*>(hnode + (size_t)d * 64)[lane];
        a.x += b.x; a.y += b.y; a.z += b.z; a.w += b.w;
        reinterpret_cast<float4*>(nedge + (size_t)e * 64)[lane] = a;
    }
}

// ---------------- softmax exp pass: logits -> exp(logit - segmax), atomic segsum ----------------
__global__ void exp_kernel(float* __restrict__ lg, const int* __restrict__ seg,
                           const unsigned* __restrict__ segmax,
                           float* __restrict__ segsum, int M)
{
    int i = blockIdx.x * blockDim.x + threadIdx.x;
    if (i >= M * 4) return;
    int e = i >> 2, hh = i & 3;
    int d = seg[e];
    float ex = expf(lg[i] - fdec(segmax[(size_t)d * 4 + hh]));
    atomicAdd(segsum + (size_t)d * 4 + hh, ex);
    lg[i] = ex;
}

// normalize in place: w[i] /= segsum[seg]
__global__ void norm_kernel(float* __restrict__ w, const int* __restrict__ seg,
                            const float* __restrict__ segsum, int M)
{
    int i = blockIdx.x * blockDim.x + threadIdx.x;
    if (i >= M * 4) return;
    w[i] = w[i] / segsum[(size_t)seg[i >> 2] * 4 + (i & 3)];
}

// segment mean finalize: buf[i] /= max(cnt,1)
__global__ void div_mean(float* __restrict__ buf, const float* __restrict__ cnt,
                         int total, int cols)
{
    int i = blockIdx.x * blockDim.x + threadIdx.x;
    if (i >= total) return;
    buf[i] = buf[i] / fmaxf(cnt[i / cols], 1.0f);
}

// ---------------- EGAT node aggregation: acc[dst] += h[src] * att ----------------
__global__ void agg_node(const float* __restrict__ h, const float* __restrict__ ex,
                         const float* __restrict__ segsum,
                         const int* __restrict__ src, const int* __restrict__ dst,
                         float* __restrict__ acc, int E)
{
    int e    = (blockIdx.x * blockDim.x + threadIdx.x) >> 5;
    int lane = threadIdx.x & 31;
    if (e >= E) return;
    int s = src[e], d = dst[e];
    const float* wp = ex + (size_t)e * 4;
    const float* sp = segsum + (size_t)d * 4;
    float w0 = wp[0] / sp[0], w1 = wp[1] / sp[1], w2 = wp[2] / sp[2], w3 = wp[3] / sp[3];
    const float4* mp = reinterpret_cast<const float4*>(h + (size_t)s * 256);
    float* apd = acc + (size_t)d * 256;
#pragma unroll
    for (int j = 0; j < 2; j++) {
        int i4 = lane + j * 32;   // float4 index 0..63 ; head = i4/16
        float4 v = mp[i4];
        float wh = (i4 < 16) ? w0 : (i4 < 32) ? w1 : (i4 < 48) ? w2 : w3;
        v.x *= wh; v.y *= wh; v.z *= wh; v.w *= wh;
        atomicAdd4(apd + i4 * 4, v);
    }
}

// ---------------- line-graph aggregation: acc[ldst] += m[lsrc] * w ----------------
// mode 0: w = wbuf[el]/segsum[ldst]   (lg branch; wbuf holds exp'd logits)
// mode 1: w = wbuf[ldst]              (g branch; wbuf prenormalized per bond)
__global__ void agg_lg(const float* __restrict__ m, const float* __restrict__ wbuf,
                       const float* __restrict__ segsum,
                       const int* __restrict__ lsrc, const int* __restrict__ ldst,
                       float* __restrict__ acc, int EL, int mode)
{
    int el   = (blockIdx.x * blockDim.x + threadIdx.x) >> 5;
    int lane = threadIdx.x & 31;
    if (el >= EL) return;
    int s = lsrc[el], d = ldst[el];
    float w0, w1, w2, w3;
    if (mode == 0) {
        const float* wp = wbuf + (size_t)el * 4;
        const float* sp = segsum + (size_t)d * 4;
        w0 = wp[0] / sp[0]; w1 = wp[1] / sp[1]; w2 = wp[2] / sp[2]; w3 = wp[3] / sp[3];
    } else {
        const float* wp = wbuf + (size_t)d * 4;
        w0 = wp[0]; w1 = wp[1]; w2 = wp[2]; w3 = wp[3];
    }
    const float4* mp = reinterpret_cast<const float4*>(m + (size_t)s * 256);
    float* apd = acc + (size_t)d * 256;
#pragma unroll
    for (int j = 0; j < 2; j++) {
        int i4 = lane + j * 32;
        float4 v = mp[i4];
        float wh = (i4 < 16) ? w0 : (i4 < 32) ? w1 : (i4 < 48) ? w2 : w3;
        v.x *= wh; v.y *= wh; v.z *= wh; v.w *= wh;
        atomicAdd4(apd + i4 * 4, v);
    }
}

// h_node[n,dd] = sum_h leaky(acc[n, h*64+dd])
__global__ void fin_node(const float* __restrict__ acc, float* __restrict__ hnode, int N)
{
    int i = blockIdx.x * blockDim.x + threadIdx.x;
    if (i >= N * 64) return;
    int n = i >> 6, dd = i & 63;
    const float* a = acc + (size_t)n * 256 + dd;
    hnode[i] = lrelu(a[0]) + lrelu(a[64]) + lrelu(a[128]) + lrelu(a[192]);
}

// out[e,dd] (+)= sum_h leaky(acc[e, h*64+dd])
__global__ void fin_out(const float* __restrict__ acc, float* __restrict__ out, int E, int add)
{
    int i = blockIdx.x * blockDim.x + threadIdx.x;
    if (i >= E * 64) return;
    int e = i >> 6, dd = i & 63;
    const float* a = acc + (size_t)e * 256 + dd;
    float s = lrelu(a[0]) + lrelu(a[64]) + lrelu(a[128]) + lrelu(a[192]);
    out[i] = add ? out[i] + s : s;
}

// ---------------- host side ----------------
static inline void gemm(const float* A, int ldA, const float* W, int ldW,
                        const float* bias, float* C, int M, int K, int accum)
{
    dim3 grid((unsigned)((M + 127) / 128), 2);
    gemm_nt<<<grid, 256>>>(A, ldA, W, ldW, bias, C, M, K, accum);
}

static inline int cdiv(long a, long b) { return (int)((a + b - 1) / b); }

extern "C" void kernel_launch(void* const* d_in, const int* in_sizes, int n_in,
                              void* d_out, int out_size)
{
    (void)in_sizes; (void)n_in; (void)out_size;
    const float* nfeats  = (const float*)d_in[0];
    const float* efeats  = (const float*)d_in[1];
    const float* xfeats  = (const float*)d_in[2];
    const float* eWni    = (const float*)d_in[3];
    const float* eWnj    = (const float*)d_in[4];
    const float* eWfij   = (const float*)d_in[5];
    const float* eWnode  = (const float*)d_in[6];
    const float* ebnode  = (const float*)d_in[7];
    const float* eattn   = (const float*)d_in[8];
    const float* ebias   = (const float*)d_in[9];
    const float* lgWni   = (const float*)d_in[10];
    const float* lgWnj   = (const float*)d_in[11];
    const float* lgWfij  = (const float*)d_in[12];
    const float* lgWnode = (const float*)d_in[13];
    const float* lgbnode = (const float*)d_in[14];
    const float* lgattn  = (const float*)d_in[15];
    const float* lgbias  = (const float*)d_in[16];
    const float* gWni    = (const float*)d_in[17];
    const float* gWnj    = (const float*)d_in[18];
    const float* gWfij   = (const float*)d_in[19];
    const float* gWnode  = (const float*)d_in[20];
    const float* gbnode  = (const float*)d_in[21];
    const float* gattn   = (const float*)d_in[22];
    const float* gbias   = (const float*)d_in[23];
    const int*   src     = (const int*)d_in[24];
    const int*   dst     = (const int*)d_in[25];
    const int*   lsrc    = (const int*)d_in[26];
    const int*   ldst    = (const int*)d_in[27];
    float* out = (float*)d_out;

    void* p;
    float *ni, *nj, *big, *mbuf, *acc, *h, *fedge, *hnode, *aggn, *cntn;
    float *aggx, *cnte, *logE, *alg, *ag, *ssum, *nedge;
    unsigned* smax;
    cudaGetSymbolAddress(&p, g_ni);    ni    = (float*)p;
    cudaGetSymbolAddress(&p, g_nj);    nj    = (float*)p;
    cudaGetSymbolAddress(&p, g_big);   big   = (float*)p;
    cudaGetSymbolAddress(&p, g_mbuf);  mbuf  = (float*)p;
    cudaGetSymbolAddress(&p, g_accb);  acc   = (float*)p;
    cudaGetSymbolAddress(&p, g_hb);    h     = (float*)p;
    cudaGetSymbolAddress(&p, g_fedge); fedge = (float*)p;
    cudaGetSymbolAddress(&p, g_hnode); hnode = (float*)p;
    cudaGetSymbolAddress(&p, g_aggn);  aggn  = (float*)p;
    cudaGetSymbolAddress(&p, g_cntn);  cntn  = (float*)p;
    cudaGetSymbolAddress(&p, g_aggx);  aggx  = (float*)p;
    cudaGetSymbolAddress(&p, g_cnte);  cnte  = (float*)p;
    cudaGetSymbolAddress(&p, g_logE);  logE  = (float*)p;
    cudaGetSymbolAddress(&p, g_alg);   alg   = (float*)p;
    cudaGetSymbolAddress(&p, g_ag);    ag    = (float*)p;
    cudaGetSymbolAddress(&p, g_smax);  smax  = (unsigned*)p;
    cudaGetSymbolAddress(&p, g_ssum);  ssum  = (float*)p;
    cudaGetSymbolAddress(&p, g_nedge); nedge = (float*)p;

    const int TPB = 256;

    // ================= Stage A: EGAT on atom graph =================
    cudaMemsetAsync(smax, 0, (size_t)NN * 4 * sizeof(unsigned));
    cudaMemsetAsync(ssum, 0, (size_t)NN * 4 * sizeof(float));
    cudaMemsetAsync(aggn, 0, (size_t)NN * 128 * sizeof(float));
    cudaMemsetAsync(cntn, 0, (size_t)NN * sizeof(float));
    gemm(nfeats, 128, eWni, 128, nullptr, ni, NN, 128, 0);
    gemm(nfeats, 128, eWnj, 128, nullptr, nj, NN, 128, 0);
    gemm(efeats, 128, eWfij, 128, nullptr, big, EE, 128, 0);   // fe
    edgeA_kernel<<<cdiv((long)EE * 32, TPB), TPB>>>(
        ni, nj, big, efeats, ebias, eattn, src, dst,
        fedge, logE, smax, aggn, cntn, EE);
    exp_kernel<<<cdiv((long)EE * 4, TPB), TPB>>>(logE, dst, smax, ssum, EE);
    div_mean<<<cdiv((long)NN * 128, TPB), TPB>>>(aggn, cntn, NN * 128, 128);
    gemm(nfeats, 128, eWnode, 256, ebnode, h, NN, 128, 0);
    gemm(aggn, 128, eWnode + 128, 256, nullptr, h, NN, 128, 1);
    cudaMemsetAsync(ni, 0, (size_t)NN * 256 * sizeof(float));  // ni dead -> node accumulator
    agg_node<<<cdiv((long)EE * 32, TPB), TPB>>>(h, logE, ssum, src, dst, ni, EE);
    fin_node<<<cdiv((long)NN * 64, TPB), TPB>>>(ni, hnode, NN);

    // ================= Stage B: line-graph branch (bond -> angle) =================
    cudaMemsetAsync(smax, 0, (size_t)EE * 4 * sizeof(unsigned));
    cudaMemsetAsync(ssum, 0, (size_t)EE * 4 * sizeof(float));
    cudaMemsetAsync(aggx, 0, (size_t)EE * 64 * sizeof(float));
    cudaMemsetAsync(cnte, 0, (size_t)EE * sizeof(float));
    gemm(fedge, 64, lgWni, 64, nullptr, mbuf, EE, 64, 0);      // lni
    gemm(fedge, 64, lgWnj, 64, nullptr, acc, EE, 64, 0);       // lnj
    gemm(xfeats, 64, lgWfij, 64, nullptr, big, ELL, 64, 0);    // lx
    edgeB_kernel<<<cdiv((long)ELL * 32, TPB), TPB>>>(
        mbuf, acc, big, xfeats, lgbias, lgattn, lsrc, ldst,
        alg, smax, aggx, cnte, ELL);
    exp_kernel<<<cdiv((long)ELL * 4, TPB), TPB>>>(alg, ldst, smax, ssum, ELL);
    div_mean<<<cdiv((long)EE * 64, TPB), TPB>>>(aggx, cnte, EE * 64, 64);
    gemm(fedge, 64, lgWnode, 128, lgbnode, mbuf, EE, 64, 0);   // m1 (overwrites lni)
    gemm(aggx, 64, lgWnode + 64, 128, nullptr, mbuf, EE, 64, 1);
    cudaMemsetAsync(acc, 0, (size_t)EE * 256 * sizeof(float)); // lnj dead -> lg accumulator
    agg_lg<<<cdiv((long)ELL * 32, TPB), TPB>>>(mbuf, alg, ssum, lsrc, ldst, acc, ELL, 0);
    fin_out<<<cdiv((long)EE * 64, TPB), TPB>>>(acc, out, EE, 0);

    // ================= Stage C: graph branch (atom -> bond) =================
    cudaMemsetAsync(smax, 0, (size_t)NN * 4 * sizeof(unsigned));
    cudaMemsetAsync(ssum, 0, (size_t)NN * 4 * sizeof(float));
    gemm(hnode, 64, gWni, 64, nullptr, ni, NN, 64, 0);         // gi
    gemm(hnode, 64, gWnj, 64, nullptr, nj, NN, 64, 0);         // gj
    gemm(fedge, 64, gWfij, 64, nullptr, big, EE, 64, 0);       // gfe
    edgeC_kernel<<<cdiv((long)EE * 32, TPB), TPB>>>(
        ni, nj, big, hnode, gbias, gattn, src, dst,
        ag, smax, nedge, EE);
    exp_kernel<<<cdiv((long)EE * 4, TPB), TPB>>>(ag, dst, smax, ssum, EE);
    norm_kernel<<<cdiv((long)EE * 4, TPB), TPB>>>(ag, dst, ssum, EE);
    gemm(nedge, 64, gWnode, 128, gbnode, mbuf, EE, 64, 0);     // m2
    gemm(fedge, 64, gWnode + 64, 128, nullptr, mbuf, EE, 64, 1);
    cudaMemsetAsync(acc, 0, (size_t)EE * 256 * sizeof(float));
    agg_lg<<<cdiv((long)ELL * 32, TPB), TPB>>>(mbuf, ag, ssum, lsrc, ldst, acc, ELL, 1);
    fin_out<<<cdiv((long)EE * 64, TPB), TPB>>>(acc, out, EE, 1);
}

// round 13
// speedup vs baseline: 1.5028x; 1.4410x over previous
#include <cuda_runtime.h>
#include <cuda_bf16.h>

#define NN   50000
#define EE   150000
#define ELL  300000

// ---------------- scratch (device globals; no runtime allocation) ----------------
__device__ __align__(16) float    g_ni   [(size_t)NN * 256];   // ni, then node-acc, then gi
__device__ __align__(16) float    g_nj   [(size_t)NN * 256];   // nj, then gj
__device__ __align__(16) float    g_big  [(size_t)ELL * 256];  // fe, then lx, then gfe
__device__ __align__(16) float    g_mbuf [(size_t)EE * 256];   // lni, then m1, then m2
__device__ __align__(16) float    g_accb [(size_t)EE * 256];   // lnj, then lg-acc, then g-acc
__device__ __align__(16) float    g_hb   [(size_t)NN * 256];   // node transform h
__device__ __align__(16) float    g_fedge[(size_t)EE * 64];
__device__ __align__(16) float    g_hnode[(size_t)NN * 64];
__device__ __align__(16) float    g_aggn [(size_t)NN * 128];
__device__             float      g_cntn [NN];
__device__ __align__(16) float    g_aggx [(size_t)EE * 64];
__device__             float      g_cnte [EE];
__device__             float      g_logE [(size_t)EE * 4];
__device__             float      g_alg  [(size_t)ELL * 4];
__device__             float      g_ag   [(size_t)EE * 4];
__device__             unsigned   g_smax [(size_t)EE * 4];
__device__             float      g_ssum [(size_t)EE * 4];
__device__ __align__(16) float    g_nedge[(size_t)EE * 64];

// ---------------- device helpers ----------------
__device__ __forceinline__ float lrelu(float v) { return v >= 0.f ? v : 0.01f * v; }

__device__ __forceinline__ unsigned fenc(float f) {
    unsigned u = __float_as_uint(f);
    return (u & 0x80000000u) ? ~u : (u | 0x80000000u);
}
__device__ __forceinline__ float fdec(unsigned e) {
    unsigned u = (e & 0x80000000u) ? (e ^ 0x80000000u) : ~e;
    return __uint_as_float(u);
}

__device__ __forceinline__ void atomicAdd4(float* p, float4 v) {
#if defined(__CUDA_ARCH__) && (__CUDA_ARCH__ >= 900)
    atomicAdd(reinterpret_cast<float4*>(p), v);
#else
    atomicAdd(p + 0, v.x); atomicAdd(p + 1, v.y);
    atomicAdd(p + 2, v.z); atomicAdd(p + 3, v.w);
#endif
}

__device__ __forceinline__ void warpReduce4(float& a, float& b, float& c, float& d) {
#pragma unroll
    for (int off = 16; off; off >>= 1) {
        a += __shfl_xor_sync(0xffffffffu, a, off);
        b += __shfl_xor_sync(0xffffffffu, b, off);
        c += __shfl_xor_sync(0xffffffffu, c, off);
        d += __shfl_xor_sync(0xffffffffu, d, off);
    }
}

// ---------------- tensor-core primitives ----------------
__device__ __forceinline__ void ldsm4(unsigned& r0, unsigned& r1, unsigned& r2, unsigned& r3,
                                      unsigned addr) {
    asm volatile("ldmatrix.sync.aligned.m8n8.x4.shared.b16 {%0,%1,%2,%3}, [%4];"
                 : "=r"(r0), "=r"(r1), "=r"(r2), "=r"(r3) : "r"(addr));
}
__device__ __forceinline__ void mma_bf16(float* c, const unsigned* a, unsigned b0, unsigned b1) {
    asm volatile("mma.sync.aligned.m16n8k16.row.col.f32.bf16.bf16.f32 "
                 "{%0,%1,%2,%3}, {%4,%5,%6,%7}, {%8,%9}, {%0,%1,%2,%3};"
                 : "+f"(c[0]), "+f"(c[1]), "+f"(c[2]), "+f"(c[3])
                 : "r"(a[0]), "r"(a[1]), "r"(a[2]), "r"(a[3]), "r"(b0), "r"(b1));
}

// split fp32 pair into bf16x2 hi + bf16x2 lo
__device__ __forceinline__ void cvt2(float x, float y, unsigned& hi, unsigned& lo) {
    __nv_bfloat162 h = __floats2bfloat162_rn(x, y);
    float rx = x - __bfloat162float(h.x);
    float ry = y - __bfloat162float(h.y);
    __nv_bfloat162 l = __floats2bfloat162_rn(rx, ry);
    hi = *reinterpret_cast<unsigned*>(&h);
    lo = *reinterpret_cast<unsigned*>(&l);
}

// ---------------- GEMM: C[M,256] = A[M,K] @ W[256,K]^T (+bias, +=C) ----------------
// bf16-split tensor-core GEMM: C = Ah*Bh + Ah*Bl + Al*Bh (fp32 accum).
// 128x128 block tile, 8 warps (2x4), 64x32 warp tile, BK=32.
// Both A ([m][k]) and B ([n][k]) tiles are loaded with NON-transposed ldmatrix:
//   A fragment wants (m=L/4, k=2*(L%4)+i); B fragment wants (n=L/4, k=2*(L%4)+i).
#define SROW 40   // padded row length in bf16 (80B row stride: 16B-aligned, conflict-free)
__global__ void __launch_bounds__(256, 2) gemm_tc(
    const float* __restrict__ A, int ldA,
    const float* __restrict__ W, int ldW,
    const float* __restrict__ bias,
    float* __restrict__ C, int M, int K, int accum)
{
    __shared__ __align__(16) __nv_bfloat16 sAh[128][SROW];
    __shared__ __align__(16) __nv_bfloat16 sAl[128][SROW];
    __shared__ __align__(16) __nv_bfloat16 sBh[128][SROW];
    __shared__ __align__(16) __nv_bfloat16 sBl[128][SROW];

    const int t    = threadIdx.x;
    const int lane = t & 31;
    const int warp = t >> 5;
    const int wm   = warp & 1;          // 0..1  -> 64-row slice
    const int wn   = warp >> 1;         // 0..3  -> 32-col slice
    const int row0 = blockIdx.x * 128;
    const int col0 = blockIdx.y * 128;

    const unsigned uAh = (unsigned)__cvta_generic_to_shared(&sAh[0][0]);
    const unsigned uAl = (unsigned)__cvta_generic_to_shared(&sAl[0][0]);
    const unsigned uBh = (unsigned)__cvta_generic_to_shared(&sBh[0][0]);
    const unsigned uBl = (unsigned)__cvta_generic_to_shared(&sBl[0][0]);

    // ldmatrix per-lane address components (lane group g = matrix id, r = row in tile)
    const unsigned g = lane >> 3, r = lane & 7;
    // A x4: m0=(m0-7,k0-7) m1=(m8-15,k0-7) m2=(m0-7,k8-15) m3=(m8-15,k8-15)
    const unsigned aoff = ((wm * 64 + ((g & 1) << 3) + r) * SROW + ((g >> 1) << 3)) * 2;
    // B x4: m0=(n0-7,k0-7) m1=(n0-7,k8-15) m2=(n8-15,k0-7) m3=(n8-15,k8-15)
    const unsigned boff = ((wn * 32 + ((g >> 1) << 3) + r) * SROW + ((g & 1) << 3)) * 2;

    // loader indices: thread t loads 16 consecutive floats of one row
    const int lrow = t >> 1;
    const int lcol = (t & 1) << 4;
    const bool aval = (row0 + lrow) < M;
    const float* apg = A + (size_t)(row0 + lrow) * ldA + lcol;
    const float* bpg = W + (size_t)(col0 + lrow) * ldW + lcol;
    unsigned* dAh = reinterpret_cast<unsigned*>(&sAh[lrow][lcol]);
    unsigned* dAl = reinterpret_cast<unsigned*>(&sAl[lrow][lcol]);
    unsigned* dBh = reinterpret_cast<unsigned*>(&sBh[lrow][lcol]);
    unsigned* dBl = reinterpret_cast<unsigned*>(&sBl[lrow][lcol]);

    float acc[4][4][4] = {};

    for (int k0 = 0; k0 < K; k0 += 32) {
        // ---- fill smem (fp32 -> bf16 hi/lo) ----
#pragma unroll
        for (int i = 0; i < 4; i++) {
            float4 v = aval ? *reinterpret_cast<const float4*>(apg + k0 + 4 * i)
                            : make_float4(0.f, 0.f, 0.f, 0.f);
            unsigned h0, l0, h1, l1;
            cvt2(v.x, v.y, h0, l0); cvt2(v.z, v.w, h1, l1);
            dAh[2 * i] = h0; dAh[2 * i + 1] = h1;
            dAl[2 * i] = l0; dAl[2 * i + 1] = l1;
        }
#pragma unroll
        for (int i = 0; i < 4; i++) {
            float4 v = *reinterpret_cast<const float4*>(bpg + k0 + 4 * i);
            unsigned h0, l0, h1, l1;
            cvt2(v.x, v.y, h0, l0); cvt2(v.z, v.w, h1, l1);
            dBh[2 * i] = h0; dBh[2 * i + 1] = h1;
            dBl[2 * i] = l0; dBl[2 * i + 1] = l1;
        }
        __syncthreads();

        // ---- compute ----
#pragma unroll
        for (int kk = 0; kk < 32; kk += 16) {
            unsigned ah[4][4], al[4][4];
#pragma unroll
            for (int mt = 0; mt < 4; mt++) {
                unsigned ad = aoff + mt * (16 * SROW * 2) + kk * 2;
                ldsm4(ah[mt][0], ah[mt][1], ah[mt][2], ah[mt][3], uAh + ad);
                ldsm4(al[mt][0], al[mt][1], al[mt][2], al[mt][3], uAl + ad);
            }
#pragma unroll
            for (int nt2 = 0; nt2 < 2; nt2++) {
                unsigned bh[4], bl[4];
                unsigned bd = boff + nt2 * (16 * SROW * 2) + kk * 2;
                ldsm4(bh[0], bh[1], bh[2], bh[3], uBh + bd);
                ldsm4(bl[0], bl[1], bl[2], bl[3], uBl + bd);
#pragma unroll
                for (int mt = 0; mt < 4; mt++) {
#pragma unroll
                    for (int tn = 0; tn < 2; tn++) {
                        float* c = acc[mt][nt2 * 2 + tn];
                        mma_bf16(c, ah[mt], bh[tn * 2], bh[tn * 2 + 1]);
                        mma_bf16(c, ah[mt], bl[tn * 2], bl[tn * 2 + 1]);
                        mma_bf16(c, al[mt], bh[tn * 2], bh[tn * 2 + 1]);
                    }
                }
            }
        }
        __syncthreads();
    }

    // ---- epilogue ----
#pragma unroll
    for (int mt = 0; mt < 4; mt++) {
#pragma unroll
        for (int nt = 0; nt < 4; nt++) {
            int row = row0 + wm * 64 + mt * 16 + (lane >> 2);
            int col = col0 + wn * 32 + nt * 8 + ((lane & 3) << 1);
            float b0 = 0.f, b1 = 0.f;
            if (bias) { b0 = bias[col]; b1 = bias[col + 1]; }
            float* c = acc[mt][nt];
            if (row < M) {
                float* p = C + (size_t)row * 256 + col;
                float2 o = accum ? *reinterpret_cast<float2*>(p) : make_float2(0.f, 0.f);
                *reinterpret_cast<float2*>(p) = make_float2(o.x + c[0] + b0, o.y + c[1] + b1);
            }
            if (row + 8 < M) {
                float* p = C + (size_t)(row + 8) * 256 + col;
                float2 o = accum ? *reinterpret_cast<float2*>(p) : make_float2(0.f, 0.f);
                *reinterpret_cast<float2*>(p) = make_float2(o.x + c[2] + b0, o.y + c[3] + b1);
            }
        }
    }
}

// ---------------- EGAT edge kernel (atom graph): warp per bond ----------------
__global__ void edgeA_kernel(
    const float* __restrict__ ni, const float* __restrict__ nj,
    const float* __restrict__ fe, const float* __restrict__ efeats,
    const float* __restrict__ bias, const float* __restrict__ attn,
    const int* __restrict__ src, const int* __restrict__ dst,
    float* __restrict__ fedge, float* __restrict__ logit,
    unsigned* __restrict__ segmax,
    float* __restrict__ aggn, float* __restrict__ cntn, int E)
{
    int e    = (blockIdx.x * blockDim.x + threadIdx.x) >> 5;
    int lane = threadIdx.x & 31;
    if (e >= E) return;
    int s = src[e], d = dst[e];
    const float* ap = ni + (size_t)s * 256;
    const float* bp = nj + (size_t)d * 256;
    const float* cp = fe + (size_t)e * 256;
    float l0 = 0, l1 = 0, l2 = 0, l3 = 0, f0 = 0, f1 = 0;
#pragma unroll
    for (int i = 0; i < 8; i++) {
        int dim = i * 32 + lane;
        float v = lrelu(ap[dim] + bp[dim] + cp[dim] + bias[dim]);
        float av = v * attn[dim];
        if (i < 2) l0 += av; else if (i < 4) l1 += av;
        else if (i < 6) l2 += av; else l3 += av;
        if (i & 1) f1 += v; else f0 += v;
    }
    warpReduce4(l0, l1, l2, l3);
    fedge[(size_t)e * 64 + lane]      = f0;
    fedge[(size_t)e * 64 + 32 + lane] = f1;
    if (lane < 4) {
        float l = (lane == 0) ? l0 : (lane == 1) ? l1 : (lane == 2) ? l2 : l3;
        logit[(size_t)e * 4 + lane] = l;
        atomicMax(segmax + (size_t)d * 4 + lane, fenc(l));
    }
    float4 ev = reinterpret_cast<const float4*>(efeats + (size_t)e * 128)[lane];
    atomicAdd4(aggn + (size_t)d * 128 + lane * 4, ev);
    if (lane == 0) atomicAdd(cntn + d, 1.0f);
}

// ---------------- line-graph edge kernel (bond->angle): warp per angle ----------------
__global__ void edgeB_kernel(
    const float* __restrict__ lni, const float* __restrict__ lnj,
    const float* __restrict__ lx, const float* __restrict__ xfeats,
    const float* __restrict__ bias, const float* __restrict__ attn,
    const int* __restrict__ lsrc, const int* __restrict__ ldst,
    float* __restrict__ logit, unsigned* __restrict__ segmax,
    float* __restrict__ aggx, float* __restrict__ cnte, int EL)
{
    int el   = (blockIdx.x * blockDim.x + threadIdx.x) >> 5;
    int lane = threadIdx.x & 31;
    if (el >= EL) return;
    int s = lsrc[el], d = ldst[el];
    const float* ap = lni + (size_t)s * 256;
    const float* bp = lnj + (size_t)d * 256;
    const float* cp = lx + (size_t)el * 256;
    float l0 = 0, l1 = 0, l2 = 0, l3 = 0;
#pragma unroll
    for (int i = 0; i < 8; i++) {
        int dim = i * 32 + lane;
        float v = lrelu(ap[dim] + bp[dim] + cp[dim] + bias[dim]);
        float av = v * attn[dim];
        if (i < 2) l0 += av; else if (i < 4) l1 += av;
        else if (i < 6) l2 += av; else l3 += av;
    }
    warpReduce4(l0, l1, l2, l3);
    if (lane < 4) {
        float l = (lane == 0) ? l0 : (lane == 1) ? l1 : (lane == 2) ? l2 : l3;
        logit[(size_t)el * 4 + lane] = l;
        atomicMax(segmax + (size_t)d * 4 + lane, fenc(l));
    }
    if (lane < 16) {
        float4 xv = reinterpret_cast<const float4*>(xfeats + (size_t)el * 64)[lane];
        atomicAdd4(aggx + (size_t)d * 64 + lane * 4, xv);
    }
    if (lane == 0) atomicAdd(cnte + d, 1.0f);
}

// ---------------- graph branch edge kernel (atom->bond): warp per bond ----------------
__global__ void edgeC_kernel(
    const float* __restrict__ gi, const float* __restrict__ gj,
    const float* __restrict__ gfe, const float* __restrict__ hnode,
    const float* __restrict__ bias, const float* __restrict__ attn,
    const int* __restrict__ src, const int* __restrict__ dst,
    float* __restrict__ logit, unsigned* __restrict__ segmax,
    float* __restrict__ nedge, int E)
{
    int e    = (blockIdx.x * blockDim.x + threadIdx.x) >> 5;
    int lane = threadIdx.x & 31;
    if (e >= E) return;
    int s = src[e], d = dst[e];
    const float* ap = gi + (size_t)s * 256;
    const float* bp = gj + (size_t)d * 256;
    const float* cp = gfe + (size_t)e * 256;
    float l0 = 0, l1 = 0, l2 = 0, l3 = 0;
#pragma unroll
    for (int i = 0; i < 8; i++) {
        int dim = i * 32 + lane;
        float v = lrelu(ap[dim] + bp[dim] + cp[dim] + bias[dim]);
        float av = v * attn[dim];
        if (i < 2) l0 += av; else if (i < 4) l1 += av;
        else if (i < 6) l2 += av; else l3 += av;
    }
    warpReduce4(l0, l1, l2, l3);
    if (lane < 4) {
        float l = (lane == 0) ? l0 : (lane == 1) ? l1 : (lane == 2) ? l2 : l3;
        logit[(size_t)e * 4 + lane] = l;
        atomicMax(segmax + (size_t)d * 4 + lane, fenc(l));
    }
    if (lane < 16) {
        float4 a = reinterpret_cast<const float4*>(hnode + (size_t)s * 64)[lane];
        float4 b = reinterpret_cast<const float4*>(hnode + (size_t)d * 64)[lane];
        a.x += b.x; a.y += b.y; a.z += b.z; a.w += b.w;
        reinterpret_cast<float4*>(nedge + (size_t)e * 64)[lane] = a;
    }
}

// ---------------- softmax exp pass ----------------
__global__ void exp_kernel(float* __restrict__ lg, const int* __restrict__ seg,
                           const unsigned* __restrict__ segmax,
                           float* __restrict__ segsum, int M)
{
    int i = blockIdx.x * blockDim.x + threadIdx.x;
    if (i >= M * 4) return;
    int e = i >> 2, hh = i & 3;
    int d = seg[e];
    float ex = expf(lg[i] - fdec(segmax[(size_t)d * 4 + hh]));
    atomicAdd(segsum + (size_t)d * 4 + hh, ex);
    lg[i] = ex;
}

__global__ void norm_kernel(float* __restrict__ w, const int* __restrict__ seg,
                            const float* __restrict__ segsum, int M)
{
    int i = blockIdx.x * blockDim.x + threadIdx.x;
    if (i >= M * 4) return;
    w[i] = w[i] / segsum[(size_t)seg[i >> 2] * 4 + (i & 3)];
}

__global__ void div_mean(float* __restrict__ buf, const float* __restrict__ cnt,
                         int total, int cols)
{
    int i = blockIdx.x * blockDim.x + threadIdx.x;
    if (i >= total) return;
    buf[i] = buf[i] / fmaxf(cnt[i / cols], 1.0f);
}

// ---------------- EGAT node aggregation ----------------
__global__ void agg_node(const float* __restrict__ h, const float* __restrict__ ex,
                         const float* __restrict__ segsum,
                         const int* __restrict__ src, const int* __restrict__ dst,
                         float* __restrict__ acc, int E)
{
    int e    = (blockIdx.x * blockDim.x + threadIdx.x) >> 5;
    int lane = threadIdx.x & 31;
    if (e >= E) return;
    int s = src[e], d = dst[e];
    const float* wp = ex + (size_t)e * 4;
    const float* sp = segsum + (size_t)d * 4;
    float w0 = wp[0] / sp[0], w1 = wp[1] / sp[1], w2 = wp[2] / sp[2], w3 = wp[3] / sp[3];
    const float4* mp = reinterpret_cast<const float4*>(h + (size_t)s * 256);
    float* apd = acc + (size_t)d * 256;
#pragma unroll
    for (int j = 0; j < 2; j++) {
        int i4 = lane + j * 32;
        float4 v = mp[i4];
        float wh = (i4 < 16) ? w0 : (i4 < 32) ? w1 : (i4 < 48) ? w2 : w3;
        v.x *= wh; v.y *= wh; v.z *= wh; v.w *= wh;
        atomicAdd4(apd + i4 * 4, v);
    }
}

// ---------------- line-graph aggregation ----------------
__global__ void agg_lg(const float* __restrict__ m, const float* __restrict__ wbuf,
                       const float* __restrict__ segsum,
                       const int* __restrict__ lsrc, const int* __restrict__ ldst,
                       float* __restrict__ acc, int EL, int mode)
{
    int el   = (blockIdx.x * blockDim.x + threadIdx.x) >> 5;
    int lane = threadIdx.x & 31;
    if (el >= EL) return;
    int s = lsrc[el], d = ldst[el];
    float w0, w1, w2, w3;
    if (mode == 0) {
        const float* wp = wbuf + (size_t)el * 4;
        const float* sp = segsum + (size_t)d * 4;
        w0 = wp[0] / sp[0]; w1 = wp[1] / sp[1]; w2 = wp[2] / sp[2]; w3 = wp[3] / sp[3];
    } else {
        const float* wp = wbuf + (size_t)d * 4;
        w0 = wp[0]; w1 = wp[1]; w2 = wp[2]; w3 = wp[3];
    }
    const float4* mp = reinterpret_cast<const float4*>(m + (size_t)s * 256);
    float* apd = acc + (size_t)d * 256;
#pragma unroll
    for (int j = 0; j < 2; j++) {
        int i4 = lane + j * 32;
        float4 v = mp[i4];
        float wh = (i4 < 16) ? w0 : (i4 < 32) ? w1 : (i4 < 48) ? w2 : w3;
        v.x *= wh; v.y *= wh; v.z *= wh; v.w *= wh;
        atomicAdd4(apd + i4 * 4, v);
    }
}

__global__ void fin_node(const float* __restrict__ acc, float* __restrict__ hnode, int N)
{
    int i = blockIdx.x * blockDim.x + threadIdx.x;
    if (i >= N * 64) return;
    int n = i >> 6, dd = i & 63;
    const float* a = acc + (size_t)n * 256 + dd;
    hnode[i] = lrelu(a[0]) + lrelu(a[64]) + lrelu(a[128]) + lrelu(a[192]);
}

__global__ void fin_out(const float* __restrict__ acc, float* __restrict__ out, int E, int add)
{
    int i = blockIdx.x * blockDim.x + threadIdx.x;
    if (i >= E * 64) return;
    int e = i >> 6, dd = i & 63;
    const float* a = acc + (size_t)e * 256 + dd;
    float s = lrelu(a[0]) + lrelu(a[64]) + lrelu(a[128]) + lrelu(a[192]);
    out[i] = add ? out[i] + s : s;
}

// ---------------- host side ----------------
static inline void gemm(const float* A, int ldA, const float* W, int ldW,
                        const float* bias, float* C, int M, int K, int accum)
{
    dim3 grid((unsigned)((M + 127) / 128), 2);
    gemm_tc<<<grid, 256>>>(A, ldA, W, ldW, bias, C, M, K, accum);
}

static inline int cdiv(long a, long b) { return (int)((a + b - 1) / b); }

extern "C" void kernel_launch(void* const* d_in, const int* in_sizes, int n_in,
                              void* d_out, int out_size)
{
    (void)in_sizes; (void)n_in; (void)out_size;
    const float* nfeats  = (const float*)d_in[0];
    const float* efeats  = (const float*)d_in[1];
    const float* xfeats  = (const float*)d_in[2];
    const float* eWni    = (const float*)d_in[3];
    const float* eWnj    = (const float*)d_in[4];
    const float* eWfij   = (const float*)d_in[5];
    const float* eWnode  = (const float*)d_in[6];
    const float* ebnode  = (const float*)d_in[7];
    const float* eattn   = (const float*)d_in[8];
    const float* ebias   = (const float*)d_in[9];
    const float* lgWni   = (const float*)d_in[10];
    const float* lgWnj   = (const float*)d_in[11];
    const float* lgWfij  = (const float*)d_in[12];
    const float* lgWnode = (const float*)d_in[13];
    const float* lgbnode = (const float*)d_in[14];
    const float* lgattn  = (const float*)d_in[15];
    const float* lgbias  = (const float*)d_in[16];
    const float* gWni    = (const float*)d_in[17];
    const float* gWnj    = (const float*)d_in[18];
    const float* gWfij   = (const float*)d_in[19];
    const float* gWnode  = (const float*)d_in[20];
    const float* gbnode  = (const float*)d_in[21];
    const float* gattn   = (const float*)d_in[22];
    const float* gbias   = (const float*)d_in[23];
    const int*   src     = (const int*)d_in[24];
    const int*   dst     = (const int*)d_in[25];
    const int*   lsrc    = (const int*)d_in[26];
    const int*   ldst    = (const int*)d_in[27];
    float* out = (float*)d_out;

    void* p;
    float *ni, *nj, *big, *mbuf, *acc, *h, *fedge, *hnode, *aggn, *cntn;
    float *aggx, *cnte, *logE, *alg, *ag, *ssum, *nedge;
    unsigned* smax;
    cudaGetSymbolAddress(&p, g_ni);    ni    = (float*)p;
    cudaGetSymbolAddress(&p, g_nj);    nj    = (float*)p;
    cudaGetSymbolAddress(&p, g_big);   big   = (float*)p;
    cudaGetSymbolAddress(&p, g_mbuf);  mbuf  = (float*)p;
    cudaGetSymbolAddress(&p, g_accb);  acc   = (float*)p;
    cudaGetSymbolAddress(&p, g_hb);    h     = (float*)p;
    cudaGetSymbolAddress(&p, g_fedge); fedge = (float*)p;
    cudaGetSymbolAddress(&p, g_hnode); hnode = (float*)p;
    cudaGetSymbolAddress(&p, g_aggn);  aggn  = (float*)p;
    cudaGetSymbolAddress(&p, g_cntn);  cntn  = (float*)p;
    cudaGetSymbolAddress(&p, g_aggx);  aggx  = (float*)p;
    cudaGetSymbolAddress(&p, g_cnte);  cnte  = (float*)p;
    cudaGetSymbolAddress(&p, g_logE);  logE  = (float*)p;
    cudaGetSymbolAddress(&p, g_alg);   alg   = (float*)p;
    cudaGetSymbolAddress(&p, g_ag);    ag    = (float*)p;
    cudaGetSymbolAddress(&p, g_smax);  smax  = (unsigned*)p;
    cudaGetSymbolAddress(&p, g_ssum);  ssum  = (float*)p;
    cudaGetSymbolAddress(&p, g_nedge); nedge = (float*)p;

    const int TPB = 256;

    // ================= Stage A: EGAT on atom graph =================
    cudaMemsetAsync(smax, 0, (size_t)NN * 4 * sizeof(unsigned));
    cudaMemsetAsync(ssum, 0, (size_t)NN * 4 * sizeof(float));
    cudaMemsetAsync(aggn, 0, (size_t)NN * 128 * sizeof(float));
    cudaMemsetAsync(cntn, 0, (size_t)NN * sizeof(float));
    gemm(nfeats, 128, eWni, 128, nullptr, ni, NN, 128, 0);
    gemm(nfeats, 128, eWnj, 128, nullptr, nj, NN, 128, 0);
    gemm(efeats, 128, eWfij, 128, nullptr, big, EE, 128, 0);   // fe
    edgeA_kernel<<<cdiv((long)EE * 32, TPB), TPB>>>(
        ni, nj, big, efeats, ebias, eattn, src, dst,
        fedge, logE, smax, aggn, cntn, EE);
    exp_kernel<<<cdiv((long)EE * 4, TPB), TPB>>>(logE, dst, smax, ssum, EE);
    div_mean<<<cdiv((long)NN * 128, TPB), TPB>>>(aggn, cntn, NN * 128, 128);
    gemm(nfeats, 128, eWnode, 256, ebnode, h, NN, 128, 0);
    gemm(aggn, 128, eWnode + 128, 256, nullptr, h, NN, 128, 1);
    cudaMemsetAsync(ni, 0, (size_t)NN * 256 * sizeof(float));  // ni dead -> node accumulator
    agg_node<<<cdiv((long)EE * 32, TPB), TPB>>>(h, logE, ssum, src, dst, ni, EE);
    fin_node<<<cdiv((long)NN * 64, TPB), TPB>>>(ni, hnode, NN);

    // ================= Stage B: line-graph branch (bond -> angle) =================
    cudaMemsetAsync(smax, 0, (size_t)EE * 4 * sizeof(unsigned));
    cudaMemsetAsync(ssum, 0, (size_t)EE * 4 * sizeof(float));
    cudaMemsetAsync(aggx, 0, (size_t)EE * 64 * sizeof(float));
    cudaMemsetAsync(cnte, 0, (size_t)EE * sizeof(float));
    gemm(fedge, 64, lgWni, 64, nullptr, mbuf, EE, 64, 0);      // lni
    gemm(fedge, 64, lgWnj, 64, nullptr, acc, EE, 64, 0);       // lnj
    gemm(xfeats, 64, lgWfij, 64, nullptr, big, ELL, 64, 0);    // lx
    edgeB_kernel<<<cdiv((long)ELL * 32, TPB), TPB>>>(
        mbuf, acc, big, xfeats, lgbias, lgattn, lsrc, ldst,
        alg, smax, aggx, cnte, ELL);
    exp_kernel<<<cdiv((long)ELL * 4, TPB), TPB>>>(alg, ldst, smax, ssum, ELL);
    div_mean<<<cdiv((long)EE * 64, TPB), TPB>>>(aggx, cnte, EE * 64, 64);
    gemm(fedge, 64, lgWnode, 128, lgbnode, mbuf, EE, 64, 0);   // m1 (overwrites lni)
    gemm(aggx, 64, lgWnode + 64, 128, nullptr, mbuf, EE, 64, 1);
    cudaMemsetAsync(acc, 0, (size_t)EE * 256 * sizeof(float)); // lnj dead -> lg accumulator
    agg_lg<<<cdiv((long)ELL * 32, TPB), TPB>>>(mbuf, alg, ssum, lsrc, ldst, acc, ELL, 0);
    fin_out<<<cdiv((long)EE * 64, TPB), TPB>>>(acc, out, EE, 0);

    // ================= Stage C: graph branch (atom -> bond) =================
    cudaMemsetAsync(smax, 0, (size_t)NN * 4 * sizeof(unsigned));
    cudaMemsetAsync(ssum, 0, (size_t)NN * 4 * sizeof(float));
    gemm(hnode, 64, gWni, 64, nullptr, ni, NN, 64, 0);         // gi
    gemm(hnode, 64, gWnj, 64, nullptr, nj, NN, 64, 0);         // gj
    gemm(fedge, 64, gWfij, 64, nullptr, big, EE, 64, 0);       // gfe
    edgeC_kernel<<<cdiv((long)EE * 32, TPB), TPB>>>(
        ni, nj, big, hnode, gbias, gattn, src, dst,
        ag, smax, nedge, EE);
    exp_kernel<<<cdiv((long)EE * 4, TPB), TPB>>>(ag, dst, smax, ssum, EE);
    norm_kernel<<<cdiv((long)EE * 4, TPB), TPB>>>(ag, dst, ssum, EE);
    gemm(nedge, 64, gWnode, 128, gbnode, mbuf, EE, 64, 0);     // m2
    gemm(fedge, 64, gWnode + 64, 128, nullptr, mbuf, EE, 64, 1);
    cudaMemsetAsync(acc, 0, (size_t)EE * 256 * sizeof(float));
    agg_lg<<<cdiv((long)ELL * 32, TPB), TPB>>>(mbuf, ag, ssum, lsrc, ldst, acc, ELL, 1);
    fin_out<<<cdiv((long)EE * 64, TPB), TPB>>>(acc, out, EE, 1);
}

// round 14
// speedup vs baseline: 1.5093x; 1.0043x over previous
#include <cuda_runtime.h>
#include <cuda_bf16.h>

#define NN   50000
#define EE   150000
#define ELL  300000

// ---------------- scratch (device globals; no runtime allocation) ----------------
__device__ __align__(16) float    g_ni   [(size_t)NN * 256];   // ni, then node-acc, then gi
__device__ __align__(16) float    g_nj   [(size_t)NN * 256];   // nj, then gj
__device__ __align__(16) float    g_big  [(size_t)ELL * 256];  // fe, then lx, then gfe
__device__ __align__(16) float    g_mbuf [(size_t)EE * 256];   // lni, then m1, then m2
__device__ __align__(16) float    g_accb [(size_t)EE * 256];   // lnj, then lg-acc, then g-acc
__device__ __align__(16) float    g_hb   [(size_t)NN * 256];   // node transform h
__device__ __align__(16) float    g_fedge[(size_t)EE * 64];
__device__ __align__(16) float    g_hnode[(size_t)NN * 64];
__device__ __align__(16) float    g_aggn [(size_t)NN * 128];
__device__             float      g_cntn [NN];
__device__ __align__(16) float    g_aggx [(size_t)EE * 64];
__device__             float      g_cnte [EE];
__device__             float      g_logE [(size_t)EE * 4];
__device__             float      g_alg  [(size_t)ELL * 4];
__device__             float      g_ag   [(size_t)EE * 4];
__device__             unsigned   g_smax [(size_t)EE * 4];
__device__             float      g_ssum [(size_t)EE * 4];
__device__ __align__(16) float    g_nedge[(size_t)EE * 64];

// ---------------- device helpers ----------------
__device__ __forceinline__ float lrelu(float v) { return v >= 0.f ? v : 0.01f * v; }

__device__ __forceinline__ unsigned fenc(float f) {
    unsigned u = __float_as_uint(f);
    return (u & 0x80000000u) ? ~u : (u | 0x80000000u);
}
__device__ __forceinline__ float fdec(unsigned e) {
    unsigned u = (e & 0x80000000u) ? (e ^ 0x80000000u) : ~e;
    return __uint_as_float(u);
}

__device__ __forceinline__ void atomicAdd4(float* p, float4 v) {
#if defined(__CUDA_ARCH__) && (__CUDA_ARCH__ >= 900)
    atomicAdd(reinterpret_cast<float4*>(p), v);
#else
    atomicAdd(p + 0, v.x); atomicAdd(p + 1, v.y);
    atomicAdd(p + 2, v.z); atomicAdd(p + 3, v.w);
#endif
}

__device__ __forceinline__ void warpReduce4(float& a, float& b, float& c, float& d) {
#pragma unroll
    for (int off = 16; off; off >>= 1) {
        a += __shfl_xor_sync(0xffffffffu, a, off);
        b += __shfl_xor_sync(0xffffffffu, b, off);
        c += __shfl_xor_sync(0xffffffffu, c, off);
        d += __shfl_xor_sync(0xffffffffu, d, off);
    }
}

// ---------------- tensor-core primitives ----------------
__device__ __forceinline__ void ldsm4(unsigned& r0, unsigned& r1, unsigned& r2, unsigned& r3,
                                      unsigned addr) {
    asm volatile("ldmatrix.sync.aligned.m8n8.x4.shared.b16 {%0,%1,%2,%3}, [%4];"
                 : "=r"(r0), "=r"(r1), "=r"(r2), "=r"(r3) : "r"(addr));
}
__device__ __forceinline__ void mma_bf16(float* c, const unsigned* a, unsigned b0, unsigned b1) {
    asm volatile("mma.sync.aligned.m16n8k16.row.col.f32.bf16.bf16.f32 "
                 "{%0,%1,%2,%3}, {%4,%5,%6,%7}, {%8,%9}, {%0,%1,%2,%3};"
                 : "+f"(c[0]), "+f"(c[1]), "+f"(c[2]), "+f"(c[3])
                 : "r"(a[0]), "r"(a[1]), "r"(a[2]), "r"(a[3]), "r"(b0), "r"(b1));
}

// split fp32 pair into bf16x2 hi + bf16x2 lo
__device__ __forceinline__ void cvt2(float x, float y, unsigned& hi, unsigned& lo) {
    __nv_bfloat162 h = __floats2bfloat162_rn(x, y);
    float rx = x - __bfloat162float(h.x);
    float ry = y - __bfloat162float(h.y);
    __nv_bfloat162 l = __floats2bfloat162_rn(rx, ry);
    hi = *reinterpret_cast<unsigned*>(&h);
    lo = *reinterpret_cast<unsigned*>(&l);
}

// ---------------- GEMM: C[M,256] = A[M,K] @ W[256,K]^T (+bias, +=C) ----------------
// bf16-split tensor-core GEMM: C = Ah*Bh + Ah*Bl + Al*Bh (fp32 accum).
// 128x128 block tile, 8 warps (2x4), 64x32 warp tile, BK=32.
// Both A ([m][k]) and B ([n][k]) tiles are loaded with NON-transposed ldmatrix:
//   A fragment wants (m=L/4, k=2*(L%4)+i); B fragment wants (n=L/4, k=2*(L%4)+i).
#define SROW 40   // padded row length in bf16 (80B row stride: 16B-aligned, conflict-free)
__global__ void __launch_bounds__(256, 2) gemm_tc(
    const float* __restrict__ A, int ldA,
    const float* __restrict__ W, int ldW,
    const float* __restrict__ bias,
    float* __restrict__ C, int M, int K, int accum)
{
    __shared__ __align__(16) __nv_bfloat16 sAh[128][SROW];
    __shared__ __align__(16) __nv_bfloat16 sAl[128][SROW];
    __shared__ __align__(16) __nv_bfloat16 sBh[128][SROW];
    __shared__ __align__(16) __nv_bfloat16 sBl[128][SROW];

    const int t    = threadIdx.x;
    const int lane = t & 31;
    const int warp = t >> 5;
    const int wm   = warp & 1;          // 0..1  -> 64-row slice
    const int wn   = warp >> 1;         // 0..3  -> 32-col slice
    const int row0 = blockIdx.x * 128;
    const int col0 = blockIdx.y * 128;

    const unsigned uAh = (unsigned)__cvta_generic_to_shared(&sAh[0][0]);
    const unsigned uAl = (unsigned)__cvta_generic_to_shared(&sAl[0][0]);
    const unsigned uBh = (unsigned)__cvta_generic_to_shared(&sBh[0][0]);
    const unsigned uBl = (unsigned)__cvta_generic_to_shared(&sBl[0][0]);

    // ldmatrix per-lane address components (lane group g = matrix id, r = row in tile)
    const unsigned g = lane >> 3, r = lane & 7;
    // A x4: m0=(m0-7,k0-7) m1=(m8-15,k0-7) m2=(m0-7,k8-15) m3=(m8-15,k8-15)
    const unsigned aoff = ((wm * 64 + ((g & 1) << 3) + r) * SROW + ((g >> 1) << 3)) * 2;
    // B x4: m0=(n0-7,k0-7) m1=(n0-7,k8-15) m2=(n8-15,k0-7) m3=(n8-15,k8-15)
    const unsigned boff = ((wn * 32 + ((g >> 1) << 3) + r) * SROW + ((g & 1) << 3)) * 2;

    // loader indices: thread t loads 16 consecutive floats of one row
    const int lrow = t >> 1;
    const int lcol = (t & 1) << 4;
    const bool aval = (row0 + lrow) < M;
    const float* apg = A + (size_t)(row0 + lrow) * ldA + lcol;
    const float* bpg = W + (size_t)(col0 + lrow) * ldW + lcol;
    unsigned* dAh = reinterpret_cast<unsigned*>(&sAh[lrow][lcol]);
    unsigned* dAl = reinterpret_cast<unsigned*>(&sAl[lrow][lcol]);
    unsigned* dBh = reinterpret_cast<unsigned*>(&sBh[lrow][lcol]);
    unsigned* dBl = reinterpret_cast<unsigned*>(&sBl[lrow][lcol]);

    float acc[4][4][4] = {};

    for (int k0 = 0; k0 < K; k0 += 32) {
        // ---- fill smem (fp32 -> bf16 hi/lo) ----
#pragma unroll
        for (int i = 0; i < 4; i++) {
            float4 v = aval ? *reinterpret_cast<const float4*>(apg + k0 + 4 * i)
                            : make_float4(0.f, 0.f, 0.f, 0.f);
            unsigned h0, l0, h1, l1;
            cvt2(v.x, v.y, h0, l0); cvt2(v.z, v.w, h1, l1);
            dAh[2 * i] = h0; dAh[2 * i + 1] = h1;
            dAl[2 * i] = l0; dAl[2 * i + 1] = l1;
        }
#pragma unroll
        for (int i = 0; i < 4; i++) {
            float4 v = *reinterpret_cast<const float4*>(bpg + k0 + 4 * i);
            unsigned h0, l0, h1, l1;
            cvt2(v.x, v.y, h0, l0); cvt2(v.z, v.w, h1, l1);
            dBh[2 * i] = h0; dBh[2 * i + 1] = h1;
            dBl[2 * i] = l0; dBl[2 * i + 1] = l1;
        }
        __syncthreads();

        // ---- compute ----
#pragma unroll
        for (int kk = 0; kk < 32; kk += 16) {
            unsigned ah[4][4], al[4][4];
#pragma unroll
            for (int mt = 0; mt < 4; mt++) {
                unsigned ad = aoff + mt * (16 * SROW * 2) + kk * 2;
                ldsm4(ah[mt][0], ah[mt][1], ah[mt][2], ah[mt][3], uAh + ad);
                ldsm4(al[mt][0], al[mt][1], al[mt][2], al[mt][3], uAl + ad);
            }
#pragma unroll
            for (int nt2 = 0; nt2 < 2; nt2++) {
                unsigned bh[4], bl[4];
                unsigned bd = boff + nt2 * (16 * SROW * 2) + kk * 2;
                ldsm4(bh[0], bh[1], bh[2], bh[3], uBh + bd);
                ldsm4(bl[0], bl[1], bl[2], bl[3], uBl + bd);
#pragma unroll
                for (int mt = 0; mt < 4; mt++) {
#pragma unroll
                    for (int tn = 0; tn < 2; tn++) {
                        float* c = acc[mt][nt2 * 2 + tn];
                        mma_bf16(c, ah[mt], bh[tn * 2], bh[tn * 2 + 1]);
                        mma_bf16(c, ah[mt], bl[tn * 2], bl[tn * 2 + 1]);
                        mma_bf16(c, al[mt], bh[tn * 2], bh[tn * 2 + 1]);
                    }
                }
            }
        }
        __syncthreads();
    }

    // ---- epilogue ----
#pragma unroll
    for (int mt = 0; mt < 4; mt++) {
#pragma unroll
        for (int nt = 0; nt < 4; nt++) {
            int row = row0 + wm * 64 + mt * 16 + (lane >> 2);
            int col = col0 + wn * 32 + nt * 8 + ((lane & 3) << 1);
            float b0 = 0.f, b1 = 0.f;
            if (bias) { b0 = bias[col]; b1 = bias[col + 1]; }
            float* c = acc[mt][nt];
            if (row < M) {
                float* p = C + (size_t)row * 256 + col;
                float2 o = accum ? *reinterpret_cast<float2*>(p) : make_float2(0.f, 0.f);
                *reinterpret_cast<float2*>(p) = make_float2(o.x + c[0] + b0, o.y + c[1] + b1);
            }
            if (row + 8 < M) {
                float* p = C + (size_t)(row + 8) * 256 + col;
                float2 o = accum ? *reinterpret_cast<float2*>(p) : make_float2(0.f, 0.f);
                *reinterpret_cast<float2*>(p) = make_float2(o.x + c[2] + b0, o.y + c[3] + b1);
            }
        }
    }
}

// ---------------- EGAT edge kernel (atom graph): warp per bond ----------------
__global__ void edgeA_kernel(
    const float* __restrict__ ni, const float* __restrict__ nj,
    const float* __restrict__ fe, const float* __restrict__ efeats,
    const float* __restrict__ bias, const float* __restrict__ attn,
    const int* __restrict__ src, const int* __restrict__ dst,
    float* __restrict__ fedge, float* __restrict__ logit,
    unsigned* __restrict__ segmax,
    float* __restrict__ aggn, float* __restrict__ cntn, int E)
{
    int e    = (blockIdx.x * blockDim.x + threadIdx.x) >> 5;
    int lane = threadIdx.x & 31;
    if (e >= E) return;
    int s = src[e], d = dst[e];
    const float* ap = ni + (size_t)s * 256;
    const float* bp = nj + (size_t)d * 256;
    const float* cp = fe + (size_t)e * 256;
    float l0 = 0, l1 = 0, l2 = 0, l3 = 0, f0 = 0, f1 = 0;
#pragma unroll
    for (int i = 0; i < 8; i++) {
        int dim = i * 32 + lane;
        float v = lrelu(ap[dim] + bp[dim] + cp[dim] + bias[dim]);
        float av = v * attn[dim];
        if (i < 2) l0 += av; else if (i < 4) l1 += av;
        else if (i < 6) l2 += av; else l3 += av;
        if (i & 1) f1 += v; else f0 += v;
    }
    warpReduce4(l0, l1, l2, l3);
    fedge[(size_t)e * 64 + lane]      = f0;
    fedge[(size_t)e * 64 + 32 + lane] = f1;
    if (lane < 4) {
        float l = (lane == 0) ? l0 : (lane == 1) ? l1 : (lane == 2) ? l2 : l3;
        logit[(size_t)e * 4 + lane] = l;
        atomicMax(segmax + (size_t)d * 4 + lane, fenc(l));
    }
    float4 ev = reinterpret_cast<const float4*>(efeats + (size_t)e * 128)[lane];
    atomicAdd4(aggn + (size_t)d * 128 + lane * 4, ev);
    if (lane == 0) atomicAdd(cntn + d, 1.0f);
}

// ---------------- line-graph edge kernel (bond->angle): warp per angle ----------------
__global__ void edgeB_kernel(
    const float* __restrict__ lni, const float* __restrict__ lnj,
    const float* __restrict__ lx, const float* __restrict__ xfeats,
    const float* __restrict__ bias, const float* __restrict__ attn,
    const int* __restrict__ lsrc, const int* __restrict__ ldst,
    float* __restrict__ logit, unsigned* __restrict__ segmax,
    float* __restrict__ aggx, float* __restrict__ cnte, int EL)
{
    int el   = (blockIdx.x * blockDim.x + threadIdx.x) >> 5;
    int lane = threadIdx.x & 31;
    if (el >= EL) return;
    int s = lsrc[el], d = ldst[el];
    const float* ap = lni + (size_t)s * 256;
    const float* bp = lnj + (size_t)d * 256;
    const float* cp = lx + (size_t)el * 256;
    float l0 = 0, l1 = 0, l2 = 0, l3 = 0;
#pragma unroll
    for (int i = 0; i < 8; i++) {
        int dim = i * 32 + lane;
        float v = lrelu(ap[dim] + bp[dim] + cp[dim] + bias[dim]);
        float av = v * attn[dim];
        if (i < 2) l0 += av; else if (i < 4) l1 += av;
        else if (i < 6) l2 += av; else l3 += av;
    }
    warpReduce4(l0, l1, l2, l3);
    if (lane < 4) {
        float l = (lane == 0) ? l0 : (lane == 1) ? l1 : (lane == 2) ? l2 : l3;
        logit[(size_t)el * 4 + lane] = l;
        atomicMax(segmax + (size_t)d * 4 + lane, fenc(l));
    }
    if (lane < 16) {
        float4 xv = reinterpret_cast<const float4*>(xfeats + (size_t)el * 64)[lane];
        atomicAdd4(aggx + (size_t)d * 64 + lane * 4, xv);
    }
    if (lane == 0) atomicAdd(cnte + d, 1.0f);
}

// ---------------- graph branch edge kernel (atom->bond): warp per bond ----------------
__global__ void edgeC_kernel(
    const float* __restrict__ gi, const float* __restrict__ gj,
    const float* __restrict__ gfe, const float* __restrict__ hnode,
    const float* __restrict__ bias, const float* __restrict__ attn,
    const int* __restrict__ src, const int* __restrict__ dst,
    float* __restrict__ logit, unsigned* __restrict__ segmax,
    float* __restrict__ nedge, int E)
{
    int e    = (blockIdx.x * blockDim.x + threadIdx.x) >> 5;
    int lane = threadIdx.x & 31;
    if (e >= E) return;
    int s = src[e], d = dst[e];
    const float* ap = gi + (size_t)s * 256;
    const float* bp = gj + (size_t)d * 256;
    const float* cp = gfe + (size_t)e * 256;
    float l0 = 0, l1 = 0, l2 = 0, l3 = 0;
#pragma unroll
    for (int i = 0; i < 8; i++) {
        int dim = i * 32 + lane;
        float v = lrelu(ap[dim] + bp[dim] + cp[dim] + bias[dim]);
        float av = v * attn[dim];
        if (i < 2) l0 += av; else if (i < 4) l1 += av;
        else if (i < 6) l2 += av; else l3 += av;
    }
    warpReduce4(l0, l1, l2, l3);
    if (lane < 4) {
        float l = (lane == 0) ? l0 : (lane == 1) ? l1 : (lane == 2) ? l2 : l3;
        logit[(size_t)e * 4 + lane] = l;
        atomicMax(segmax + (size_t)d * 4 + lane, fenc(l));
    }
    if (lane < 16) {
        float4 a = reinterpret_cast<const float4*>(hnode + (size_t)s * 64)[lane];
        float4 b = reinterpret_cast<const float4*>(hnode + (size_t)d * 64)[lane];
        a.x += b.x; a.y += b.y; a.z += b.z; a.w += b.w;
        reinterpret_cast<float4*>(nedge + (size_t)e * 64)[lane] = a;
    }
}

// ---------------- softmax exp pass ----------------
__global__ void exp_kernel(float* __restrict__ lg, const int* __restrict__ seg,
                           const unsigned* __restrict__ segmax,
                           float* __restrict__ segsum, int M)
{
    int i = blockIdx.x * blockDim.x + threadIdx.x;
    if (i >= M * 4) return;
    int e = i >> 2, hh = i & 3;
    int d = seg[e];
    float ex = expf(lg[i] - fdec(segmax[(size_t)d * 4 + hh]));
    atomicAdd(segsum + (size_t)d * 4 + hh, ex);
    lg[i] = ex;
}

__global__ void norm_kernel(float* __restrict__ w, const int* __restrict__ seg,
                            const float* __restrict__ segsum, int M)
{
    int i = blockIdx.x * blockDim.x + threadIdx.x;
    if (i >= M * 4) return;
    w[i] = w[i] / segsum[(size_t)seg[i >> 2] * 4 + (i & 3)];
}

__global__ void div_mean(float* __restrict__ buf, const float* __restrict__ cnt,
                         int total, int cols)
{
    int i = blockIdx.x * blockDim.x + threadIdx.x;
    if (i >= total) return;
    buf[i] = buf[i] / fmaxf(cnt[i / cols], 1.0f);
}

// ---------------- EGAT node aggregation ----------------
__global__ void agg_node(const float* __restrict__ h, const float* __restrict__ ex,
                         const float* __restrict__ segsum,
                         const int* __restrict__ src, const int* __restrict__ dst,
                         float* __restrict__ acc, int E)
{
    int e    = (blockIdx.x * blockDim.x + threadIdx.x) >> 5;
    int lane = threadIdx.x & 31;
    if (e >= E) return;
    int s = src[e], d = dst[e];
    const float* wp = ex + (size_t)e * 4;
    const float* sp = segsum + (size_t)d * 4;
    float w0 = wp[0] / sp[0], w1 = wp[1] / sp[1], w2 = wp[2] / sp[2], w3 = wp[3] / sp[3];
    const float4* mp = reinterpret_cast<const float4*>(h + (size_t)s * 256);
    float* apd = acc + (size_t)d * 256;
#pragma unroll
    for (int j = 0; j < 2; j++) {
        int i4 = lane + j * 32;
        float4 v = mp[i4];
        float wh = (i4 < 16) ? w0 : (i4 < 32) ? w1 : (i4 < 48) ? w2 : w3;
        v.x *= wh; v.y *= wh; v.z *= wh; v.w *= wh;
        atomicAdd4(apd + i4 * 4, v);
    }
}

// ---------------- line-graph aggregation ----------------
__global__ void agg_lg(const float* __restrict__ m, const float* __restrict__ wbuf,
                       const float* __restrict__ segsum,
                       const int* __restrict__ lsrc, const int* __restrict__ ldst,
                       float* __restrict__ acc, int EL, int mode)
{
    int el   = (blockIdx.x * blockDim.x + threadIdx.x) >> 5;
    int lane = threadIdx.x & 31;
    if (el >= EL) return;
    int s = lsrc[el], d = ldst[el];
    float w0, w1, w2, w3;
    if (mode == 0) {
        const float* wp = wbuf + (size_t)el * 4;
        const float* sp = segsum + (size_t)d * 4;
        w0 = wp[0] / sp[0]; w1 = wp[1] / sp[1]; w2 = wp[2] / sp[2]; w3 = wp[3] / sp[3];
    } else {
        const float* wp = wbuf + (size_t)d * 4;
        w0 = wp[0]; w1 = wp[1]; w2 = wp[2]; w3 = wp[3];
    }
    const float4* mp = reinterpret_cast<const float4*>(m + (size_t)s * 256);
    float* apd = acc + (size_t)d * 256;
#pragma unroll
    for (int j = 0; j < 2; j++) {
        int i4 = lane + j * 32;
        float4 v = mp[i4];
        float wh = (i4 < 16) ? w0 : (i4 < 32) ? w1 : (i4 < 48) ? w2 : w3;
        v.x *= wh; v.y *= wh; v.z *= wh; v.w *= wh;
        atomicAdd4(apd + i4 * 4, v);
    }
}

__global__ void fin_node(const float* __restrict__ acc, float* __restrict__ hnode, int N)
{
    int i = blockIdx.x * blockDim.x + threadIdx.x;
    if (i >= N * 64) return;
    int n = i >> 6, dd = i & 63;
    const float* a = acc + (size_t)n * 256 + dd;
    hnode[i] = lrelu(a[0]) + lrelu(a[64]) + lrelu(a[128]) + lrelu(a[192]);
}

__global__ void fin_out(const float* __restrict__ acc, float* __restrict__ out, int E, int add)
{
    int i = blockIdx.x * blockDim.x + threadIdx.x;
    if (i >= E * 64) return;
    int e = i >> 6, dd = i & 63;
    const float* a = acc + (size_t)e * 256 + dd;
    float s = lrelu(a[0]) + lrelu(a[64]) + lrelu(a[128]) + lrelu(a[192]);
    out[i] = add ? out[i] + s : s;
}

// ---------------- host side ----------------
static inline void gemm(const float* A, int ldA, const float* W, int ldW,
                        const float* bias, float* C, int M, int K, int accum)
{
    dim3 grid((unsigned)((M + 127) / 128), 2);
    gemm_tc<<<grid, 256>>>(A, ldA, W, ldW, bias, C, M, K, accum);
}

static inline int cdiv(long a, long b) { return (int)((a + b - 1) / b); }

extern "C" void kernel_launch(void* const* d_in, const int* in_sizes, int n_in,
                              void* d_out, int out_size)
{
    (void)in_sizes; (void)n_in; (void)out_size;
    const float* nfeats  = (const float*)d_in[0];
    const float* efeats  = (const float*)d_in[1];
    const float* xfeats  = (const float*)d_in[2];
    const float* eWni    = (const float*)d_in[3];
    const float* eWnj    = (const float*)d_in[4];
    const float* eWfij   = (const float*)d_in[5];
    const float* eWnode  = (const float*)d_in[6];
    const float* ebnode  = (const float*)d_in[7];
    const float* eattn   = (const float*)d_in[8];
    const float* ebias   = (const float*)d_in[9];
    const float* lgWni   = (const float*)d_in[10];
    const float* lgWnj   = (const float*)d_in[11];
    const float* lgWfij  = (const float*)d_in[12];
    const float* lgWnode = (const float*)d_in[13];
    const float* lgbnode = (const float*)d_in[14];
    const float* lgattn  = (const float*)d_in[15];
    const float* lgbias  = (const float*)d_in[16];
    const float* gWni    = (const float*)d_in[17];
    const float* gWnj    = (const float*)d_in[18];
    const float* gWfij   = (const float*)d_in[19];
    const float* gWnode  = (const float*)d_in[20];
    const float* gbnode  = (const float*)d_in[21];
    const float* gattn   = (const float*)d_in[22];
    const float* gbias   = (const float*)d_in[23];
    const int*   src     = (const int*)d_in[24];
    const int*   dst     = (const int*)d_in[25];
    const int*   lsrc    = (const int*)d_in[26];
    const int*   ldst    = (const int*)d_in[27];
    float* out = (float*)d_out;

    void* p;
    float *ni, *nj, *big, *mbuf, *acc, *h, *fedge, *hnode, *aggn, *cntn;
    float *aggx, *cnte, *logE, *alg, *ag, *ssum, *nedge;
    unsigned* smax;
    cudaGetSymbolAddress(&p, g_ni);    ni    = (float*)p;
    cudaGetSymbolAddress(&p, g_nj);    nj    = (float*)p;
    cudaGetSymbolAddress(&p, g_big);   big   = (float*)p;
    cudaGetSymbolAddress(&p, g_mbuf);  mbuf  = (float*)p;
    cudaGetSymbolAddress(&p, g_accb);  acc   = (float*)p;
    cudaGetSymbolAddress(&p, g_hb);    h     = (float*)p;
    cudaGetSymbolAddress(&p, g_fedge); fedge = (float*)p;
    cudaGetSymbolAddress(&p, g_hnode); hnode = (float*)p;
    cudaGetSymbolAddress(&p, g_aggn);  aggn  = (float*)p;
    cudaGetSymbolAddress(&p, g_cntn);  cntn  = (float*)p;
    cudaGetSymbolAddress(&p, g_aggx);  aggx  = (float*)p;
    cudaGetSymbolAddress(&p, g_cnte);  cnte  = (float*)p;
    cudaGetSymbolAddress(&p, g_logE);  logE  = (float*)p;
    cudaGetSymbolAddress(&p, g_alg);   alg   = (float*)p;
    cudaGetSymbolAddress(&p, g_ag);    ag    = (float*)p;
    cudaGetSymbolAddress(&p, g_smax);  smax  = (unsigned*)p;
    cudaGetSymbolAddress(&p, g_ssum);  ssum  = (float*)p;
    cudaGetSymbolAddress(&p, g_nedge); nedge = (float*)p;

    const int TPB = 256;

    // ================= Stage A: EGAT on atom graph =================
    cudaMemsetAsync(smax, 0, (size_t)NN * 4 * sizeof(unsigned));
    cudaMemsetAsync(ssum, 0, (size_t)NN * 4 * sizeof(float));
    cudaMemsetAsync(aggn, 0, (size_t)NN * 128 * sizeof(float));
    cudaMemsetAsync(cntn, 0, (size_t)NN * sizeof(float));
    gemm(nfeats, 128, eWni, 128, nullptr, ni, NN, 128, 0);
    gemm(nfeats, 128, eWnj, 128, nullptr, nj, NN, 128, 0);
    gemm(efeats, 128, eWfij, 128, nullptr, big, EE, 128, 0);   // fe
    edgeA_kernel<<<cdiv((long)EE * 32, TPB), TPB>>>(
        ni, nj, big, efeats, ebias, eattn, src, dst,
        fedge, logE, smax, aggn, cntn, EE);
    exp_kernel<<<cdiv((long)EE * 4, TPB), TPB>>>(logE, dst, smax, ssum, EE);
    div_mean<<<cdiv((long)NN * 128, TPB), TPB>>>(aggn, cntn, NN * 128, 128);
    gemm(nfeats, 128, eWnode, 256, ebnode, h, NN, 128, 0);
    gemm(aggn, 128, eWnode + 128, 256, nullptr, h, NN, 128, 1);
    cudaMemsetAsync(ni, 0, (size_t)NN * 256 * sizeof(float));  // ni dead -> node accumulator
    agg_node<<<cdiv((long)EE * 32, TPB), TPB>>>(h, logE, ssum, src, dst, ni, EE);
    fin_node<<<cdiv((long)NN * 64, TPB), TPB>>>(ni, hnode, NN);

    // ================= Stage B: line-graph branch (bond -> angle) =================
    cudaMemsetAsync(smax, 0, (size_t)EE * 4 * sizeof(unsigned));
    cudaMemsetAsync(ssum, 0, (size_t)EE * 4 * sizeof(float));
    cudaMemsetAsync(aggx, 0, (size_t)EE * 64 * sizeof(float));
    cudaMemsetAsync(cnte, 0, (size_t)EE * sizeof(float));
    gemm(fedge, 64, lgWni, 64, nullptr, mbuf, EE, 64, 0);      // lni
    gemm(fedge, 64, lgWnj, 64, nullptr, acc, EE, 64, 0);       // lnj
    gemm(xfeats, 64, lgWfij, 64, nullptr, big, ELL, 64, 0);    // lx
    edgeB_kernel<<<cdiv((long)ELL * 32, TPB), TPB>>>(
        mbuf, acc, big, xfeats, lgbias, lgattn, lsrc, ldst,
        alg, smax, aggx, cnte, ELL);
    exp_kernel<<<cdiv((long)ELL * 4, TPB), TPB>>>(alg, ldst, smax, ssum, ELL);
    div_mean<<<cdiv((long)EE * 64, TPB), TPB>>>(aggx, cnte, EE * 64, 64);
    gemm(fedge, 64, lgWnode, 128, lgbnode, mbuf, EE, 64, 0);   // m1 (overwrites lni)
    gemm(aggx, 64, lgWnode + 64, 128, nullptr, mbuf, EE, 64, 1);
    cudaMemsetAsync(acc, 0, (size_t)EE * 256 * sizeof(float)); // lnj dead -> lg accumulator
    agg_lg<<<cdiv((long)ELL * 32, TPB), TPB>>>(mbuf, alg, ssum, lsrc, ldst, acc, ELL, 0);
    fin_out<<<cdiv((long)EE * 64, TPB), TPB>>>(acc, out, EE, 0);

    // ================= Stage C: graph branch (atom -> bond) =================
    cudaMemsetAsync(smax, 0, (size_t)NN * 4 * sizeof(unsigned));
    cudaMemsetAsync(ssum, 0, (size_t)NN * 4 * sizeof(float));
    gemm(hnode, 64, gWni, 64, nullptr, ni, NN, 64, 0);         // gi
    gemm(hnode, 64, gWnj, 64, nullptr, nj, NN, 64, 0);         // gj
    gemm(fedge, 64, gWfij, 64, nullptr, big, EE, 64, 0);       // gfe
    edgeC_kernel<<<cdiv((long)EE * 32, TPB), TPB>>>(
        ni, nj, big, hnode, gbias, gattn, src, dst,
        ag, smax, nedge, EE);
    exp_kernel<<<cdiv((long)EE * 4, TPB), TPB>>>(ag, dst, smax, ssum, EE);
    norm_kernel<<<cdiv((long)EE * 4, TPB), TPB>>>(ag, dst, ssum, EE);
    gemm(nedge, 64, gWnode, 128, gbnode, mbuf, EE, 64, 0);     // m2
    gemm(fedge, 64, gWnode + 64, 128, nullptr, mbuf, EE, 64, 1);
    cudaMemsetAsync(acc, 0, (size_t)EE * 256 * sizeof(float));
    agg_lg<<<cdiv((long)ELL * 32, TPB), TPB>>>(mbuf, ag, ssum, lsrc, ldst, acc, ELL, 1);
    fin_out<<<cdiv((long)EE * 64, TPB), TPB>>>(acc, out, EE, 1);
}

// round 15
// speedup vs baseline: 1.7151x; 1.1364x over previous
#include <cuda_runtime.h>
#include <cuda_bf16.h>

#define NN   50000
#define EE   150000
#define ELL  300000

typedef __nv_bfloat16 bf;

// ---------------- scratch (device globals; no runtime allocation) ----------------
__device__ __align__(16) float    g_ni   [(size_t)NN * 256];   // ni, then node-acc, then gi
__device__ __align__(16) float    g_nj   [(size_t)NN * 256];   // nj, then gj
__device__ __align__(16) float    g_big  [(size_t)ELL * 256];  // fe, then lx, then gfe
__device__ __align__(16) float    g_mbuf [(size_t)EE * 256];   // lni, then m1, then m2
__device__ __align__(16) float    g_accb [(size_t)EE * 256];   // lnj, then lg-acc, then g-acc
__device__ __align__(16) float    g_hb   [(size_t)NN * 256];   // node transform h
__device__ __align__(16) float    g_hnode[(size_t)NN * 64];
__device__ __align__(16) float    g_aggn [(size_t)NN * 128];
__device__             float      g_cntn [NN];
__device__ __align__(16) float    g_aggx [(size_t)EE * 64];
__device__             float      g_cnte [EE];
__device__             float      g_logE [(size_t)EE * 4];
__device__             float      g_alg  [(size_t)ELL * 4];
__device__             float      g_ag   [(size_t)EE * 4];
__device__             unsigned   g_smax [(size_t)EE * 4];
__device__             float      g_ssum [(size_t)EE * 4];

// bf16 hi/lo operand buffers
__device__ __align__(16) bf g_nfh [(size_t)NN  * 128];
__device__ __align__(16) bf g_nfl [(size_t)NN  * 128];
__device__ __align__(16) bf g_efh [(size_t)EE  * 128];
__device__ __align__(16) bf g_efl [(size_t)EE  * 128];
__device__ __align__(16) bf g_xfh [(size_t)ELL * 64];
__device__ __align__(16) bf g_xfl [(size_t)ELL * 64];
__device__ __align__(16) bf g_agnh[(size_t)NN  * 128];
__device__ __align__(16) bf g_agnl[(size_t)NN  * 128];
__device__ __align__(16) bf g_feh [(size_t)EE  * 64];
__device__ __align__(16) bf g_fel [(size_t)EE  * 64];
__device__ __align__(16) bf g_agxh[(size_t)EE  * 64];
__device__ __align__(16) bf g_agxl[(size_t)EE  * 64];
__device__ __align__(16) bf g_hnh [(size_t)NN  * 64];
__device__ __align__(16) bf g_hnl [(size_t)NN  * 64];
__device__ __align__(16) bf g_neh [(size_t)EE  * 64];
__device__ __align__(16) bf g_nel [(size_t)EE  * 64];
__device__ __align__(16) bf g_wh  [327680];
__device__ __align__(16) bf g_wl  [327680];

// weight offsets in g_wh/g_wl (elements)
#define OFF_EWNI   0
#define OFF_EWNJ   32768
#define OFF_EWFIJ  65536
#define OFF_EWNODE 98304
#define OFF_LWNI   163840
#define OFF_LWNJ   180224
#define OFF_LWFIJ  196608
#define OFF_LWNODE 212992
#define OFF_GWNI   245760
#define OFF_GWNJ   262144
#define OFF_GWFIJ  278528
#define OFF_GWNODE 294912

// ---------------- device helpers ----------------
__device__ __forceinline__ float lrelu(float v) { return v >= 0.f ? v : 0.01f * v; }

__device__ __forceinline__ unsigned fenc(float f) {
    unsigned u = __float_as_uint(f);
    return (u & 0x80000000u) ? ~u : (u | 0x80000000u);
}
__device__ __forceinline__ float fdec(unsigned e) {
    unsigned u = (e & 0x80000000u) ? (e ^ 0x80000000u) : ~e;
    return __uint_as_float(u);
}

__device__ __forceinline__ void atomicAdd4(float* p, float4 v) {
#if defined(__CUDA_ARCH__) && (__CUDA_ARCH__ >= 900)
    atomicAdd(reinterpret_cast<float4*>(p), v);
#else
    atomicAdd(p + 0, v.x); atomicAdd(p + 1, v.y);
    atomicAdd(p + 2, v.z); atomicAdd(p + 3, v.w);
#endif
}

__device__ __forceinline__ void warpReduce4(float& a, float& b, float& c, float& d) {
#pragma unroll
    for (int off = 16; off; off >>= 1) {
        a += __shfl_xor_sync(0xffffffffu, a, off);
        b += __shfl_xor_sync(0xffffffffu, b, off);
        c += __shfl_xor_sync(0xffffffffu, c, off);
        d += __shfl_xor_sync(0xffffffffu, d, off);
    }
}

// split fp32 pair into bf16x2 hi + bf16x2 lo
__device__ __forceinline__ void cvt2(float x, float y, unsigned& hi, unsigned& lo) {
    __nv_bfloat162 h = __floats2bfloat162_rn(x, y);
    float rx = x - __bfloat162float(h.x);
    float ry = y - __bfloat162float(h.y);
    __nv_bfloat162 l = __floats2bfloat162_rn(rx, ry);
    hi = *reinterpret_cast<unsigned*>(&h);
    lo = *reinterpret_cast<unsigned*>(&l);
}

// ---------------- tensor-core primitives ----------------
__device__ __forceinline__ void ldsm4(unsigned& r0, unsigned& r1, unsigned& r2, unsigned& r3,
                                      unsigned addr) {
    asm volatile("ldmatrix.sync.aligned.m8n8.x4.shared.b16 {%0,%1,%2,%3}, [%4];"
                 : "=r"(r0), "=r"(r1), "=r"(r2), "=r"(r3) : "r"(addr));
}
__device__ __forceinline__ void mma_bf16(float* c, const unsigned* a, unsigned b0, unsigned b1) {
    asm volatile("mma.sync.aligned.m16n8k16.row.col.f32.bf16.bf16.f32 "
                 "{%0,%1,%2,%3}, {%4,%5,%6,%7}, {%8,%9}, {%0,%1,%2,%3};"
                 : "+f"(c[0]), "+f"(c[1]), "+f"(c[2]), "+f"(c[3])
                 : "r"(a[0]), "r"(a[1]), "r"(a[2]), "r"(a[3]), "r"(b0), "r"(b1));
}

// ---------------- fp32 -> bf16 hi/lo conversion ----------------
__global__ void cvt_hilo(const float* __restrict__ x, bf* __restrict__ hi,
                         bf* __restrict__ lo, long n)
{
    long i = ((long)blockIdx.x * blockDim.x + threadIdx.x) * 4;
    if (i >= n) return;
    float4 v = *reinterpret_cast<const float4*>(x + i);
    unsigned h0, l0, h1, l1;
    cvt2(v.x, v.y, h0, l0); cvt2(v.z, v.w, h1, l1);
    uint2 H = make_uint2(h0, h1), L = make_uint2(l0, l1);
    *reinterpret_cast<uint2*>(hi + i) = H;
    *reinterpret_cast<uint2*>(lo + i) = L;
}

// ---------------- GEMM: C[M,256] = [A|A2][M,K] @ W[256,K]^T (+bias, +=C) ----------------
// bf16-split tensor-core GEMM: C = Ah*Bh + Ah*Bl + Al*Bh (fp32 accum).
// All operands pre-split to bf16 hi/lo. A switches to A2 at k >= Ksplit (concat GEMM).
// 128x128 block tile, 8 warps (2x4), 64x32 warp tile, BK=32.
#define SROW 40   // padded row length in bf16 (80B row stride: 16B-aligned, conflict-free)
__global__ void __launch_bounds__(256, 2) gemm_bf(
    const bf* __restrict__ Ah, const bf* __restrict__ Al,
    const bf* __restrict__ A2h, const bf* __restrict__ A2l, int ldA, int Ksplit,
    const bf* __restrict__ Wh, const bf* __restrict__ Wl, int ldW,
    const float* __restrict__ bias,
    float* __restrict__ C, int M, int K, int accum)
{
    __shared__ __align__(16) bf sAh[128][SROW];
    __shared__ __align__(16) bf sAl[128][SROW];
    __shared__ __align__(16) bf sBh[128][SROW];
    __shared__ __align__(16) bf sBl[128][SROW];

    const int t    = threadIdx.x;
    const int lane = t & 31;
    const int warp = t >> 5;
    const int wm   = warp & 1;
    const int wn   = warp >> 1;
    const int row0 = blockIdx.x * 128;
    const int col0 = blockIdx.y * 128;

    const unsigned uAh = (unsigned)__cvta_generic_to_shared(&sAh[0][0]);
    const unsigned uAl = (unsigned)__cvta_generic_to_shared(&sAl[0][0]);
    const unsigned uBh = (unsigned)__cvta_generic_to_shared(&sBh[0][0]);
    const unsigned uBl = (unsigned)__cvta_generic_to_shared(&sBl[0][0]);

    const unsigned g = lane >> 3, r = lane & 7;
    const unsigned aoff = ((wm * 64 + ((g & 1) << 3) + r) * SROW + ((g >> 1) << 3)) * 2;
    const unsigned boff = ((wn * 32 + ((g >> 1) << 3) + r) * SROW + ((g & 1) << 3)) * 2;

    const int lrow = t >> 1;
    const int lcol = (t & 1) << 4;   // 0 or 16 (bf16 elements)
    const bool aval = (row0 + lrow) < M;

    float acc[4][4][4] = {};

    for (int k0 = 0; k0 < K; k0 += 32) {
        const bf* pAh = (k0 < Ksplit) ? Ah : A2h;
        const bf* pAl = (k0 < Ksplit) ? Al : A2l;
        int ka = (k0 < Ksplit) ? k0 : (k0 - Ksplit);

        uint4 z = make_uint4(0u, 0u, 0u, 0u);
        uint4 a0 = z, a1 = z, a2 = z, a3 = z;
        if (aval) {
            const uint4* ph = reinterpret_cast<const uint4*>(pAh + (size_t)(row0 + lrow) * ldA + ka + lcol);
            const uint4* pl = reinterpret_cast<const uint4*>(pAl + (size_t)(row0 + lrow) * ldA + ka + lcol);
            a0 = ph[0]; a1 = ph[1]; a2 = pl[0]; a3 = pl[1];
        }
        *reinterpret_cast<uint4*>(&sAh[lrow][lcol])     = a0;
        *reinterpret_cast<uint4*>(&sAh[lrow][lcol + 8]) = a1;
        *reinterpret_cast<uint4*>(&sAl[lrow][lcol])     = a2;
        *reinterpret_cast<uint4*>(&sAl[lrow][lcol + 8]) = a3;
        {
            const uint4* ph = reinterpret_cast<const uint4*>(Wh + (size_t)(col0 + lrow) * ldW + k0 + lcol);
            const uint4* pl = reinterpret_cast<const uint4*>(Wl + (size_t)(col0 + lrow) * ldW + k0 + lcol);
            uint4 b0 = ph[0], b1 = ph[1], b2 = pl[0], b3 = pl[1];
            *reinterpret_cast<uint4*>(&sBh[lrow][lcol])     = b0;
            *reinterpret_cast<uint4*>(&sBh[lrow][lcol + 8]) = b1;
            *reinterpret_cast<uint4*>(&sBl[lrow][lcol])     = b2;
            *reinterpret_cast<uint4*>(&sBl[lrow][lcol + 8]) = b3;
        }
        __syncthreads();

#pragma unroll
        for (int kk = 0; kk < 32; kk += 16) {
            unsigned ah[4][4], al[4][4];
#pragma unroll
            for (int mt = 0; mt < 4; mt++) {
                unsigned ad = aoff + mt * (16 * SROW * 2) + kk * 2;
                ldsm4(ah[mt][0], ah[mt][1], ah[mt][2], ah[mt][3], uAh + ad);
                ldsm4(al[mt][0], al[mt][1], al[mt][2], al[mt][3], uAl + ad);
            }
#pragma unroll
            for (int nt2 = 0; nt2 < 2; nt2++) {
                unsigned bh[4], bl[4];
                unsigned bd = boff + nt2 * (16 * SROW * 2) + kk * 2;
                ldsm4(bh[0], bh[1], bh[2], bh[3], uBh + bd);
                ldsm4(bl[0], bl[1], bl[2], bl[3], uBl + bd);
#pragma unroll
                for (int mt = 0; mt < 4; mt++) {
#pragma unroll
                    for (int tn = 0; tn < 2; tn++) {
                        float* c = acc[mt][nt2 * 2 + tn];
                        mma_bf16(c, ah[mt], bh[tn * 2], bh[tn * 2 + 1]);
                        mma_bf16(c, ah[mt], bl[tn * 2], bl[tn * 2 + 1]);
                        mma_bf16(c, al[mt], bh[tn * 2], bh[tn * 2 + 1]);
                    }
                }
            }
        }
        __syncthreads();
    }

    // ---- epilogue ----
#pragma unroll
    for (int mt = 0; mt < 4; mt++) {
#pragma unroll
        for (int nt = 0; nt < 4; nt++) {
            int row = row0 + wm * 64 + mt * 16 + (lane >> 2);
            int col = col0 + wn * 32 + nt * 8 + ((lane & 3) << 1);
            float b0 = 0.f, b1 = 0.f;
            if (bias) { b0 = bias[col]; b1 = bias[col + 1]; }
            float* c = acc[mt][nt];
            if (row < M) {
                float* p = C + (size_t)row * 256 + col;
                float2 o = accum ? *reinterpret_cast<float2*>(p) : make_float2(0.f, 0.f);
                *reinterpret_cast<float2*>(p) = make_float2(o.x + c[0] + b0, o.y + c[1] + b1);
            }
            if (row + 8 < M) {
                float* p = C + (size_t)(row + 8) * 256 + col;
                float2 o = accum ? *reinterpret_cast<float2*>(p) : make_float2(0.f, 0.f);
                *reinterpret_cast<float2*>(p) = make_float2(o.x + c[2] + b0, o.y + c[3] + b1);
            }
        }
    }
}

// ---------------- EGAT edge kernel (atom graph): warp per bond ----------------
__global__ void edgeA_kernel(
    const float* __restrict__ ni, const float* __restrict__ nj,
    const float* __restrict__ fe, const float* __restrict__ efeats,
    const float* __restrict__ bias, const float* __restrict__ attn,
    const int* __restrict__ src, const int* __restrict__ dst,
    bf* __restrict__ feh, bf* __restrict__ fel,
    float* __restrict__ logit, unsigned* __restrict__ segmax,
    float* __restrict__ aggn, float* __restrict__ cntn, int E)
{
    int e    = (blockIdx.x * blockDim.x + threadIdx.x) >> 5;
    int lane = threadIdx.x & 31;
    if (e >= E) return;
    int s = src[e], d = dst[e];
    const float* ap = ni + (size_t)s * 256;
    const float* bp = nj + (size_t)d * 256;
    const float* cp = fe + (size_t)e * 256;
    float l0 = 0, l1 = 0, l2 = 0, l3 = 0, f0 = 0, f1 = 0;
#pragma unroll
    for (int i = 0; i < 8; i++) {
        int dim = i * 32 + lane;
        float v = lrelu(ap[dim] + bp[dim] + cp[dim] + bias[dim]);
        float av = v * attn[dim];
        if (i < 2) l0 += av; else if (i < 4) l1 += av;
        else if (i < 6) l2 += av; else l3 += av;
        if (i & 1) f1 += v; else f0 += v;
    }
    warpReduce4(l0, l1, l2, l3);
    // f_edge in bf16 hi/lo (only consumed by tensor-core GEMMs)
    {
        bf h0 = __float2bfloat16(f0);
        bf h1 = __float2bfloat16(f1);
        feh[(size_t)e * 64 + lane]      = h0;
        feh[(size_t)e * 64 + 32 + lane] = h1;
        fel[(size_t)e * 64 + lane]      = __float2bfloat16(f0 - __bfloat162float(h0));
        fel[(size_t)e * 64 + 32 + lane] = __float2bfloat16(f1 - __bfloat162float(h1));
    }
    if (lane < 4) {
        float l = (lane == 0) ? l0 : (lane == 1) ? l1 : (lane == 2) ? l2 : l3;
        logit[(size_t)e * 4 + lane] = l;
        atomicMax(segmax + (size_t)d * 4 + lane, fenc(l));
    }
    float4 ev = reinterpret_cast<const float4*>(efeats + (size_t)e * 128)[lane];
    atomicAdd4(aggn + (size_t)d * 128 + lane * 4, ev);
    if (lane == 0) atomicAdd(cntn + d, 1.0f);
}

// ---------------- line-graph edge kernel (bond->angle): warp per angle ----------------
__global__ void edgeB_kernel(
    const float* __restrict__ lni, const float* __restrict__ lnj,
    const float* __restrict__ lx, const float* __restrict__ xfeats,
    const float* __restrict__ bias, const float* __restrict__ attn,
    const int* __restrict__ lsrc, const int* __restrict__ ldst,
    float* __restrict__ logit, unsigned* __restrict__ segmax,
    float* __restrict__ aggx, float* __restrict__ cnte, int EL)
{
    int el   = (blockIdx.x * blockDim.x + threadIdx.x) >> 5;
    int lane = threadIdx.x & 31;
    if (el >= EL) return;
    int s = lsrc[el], d = ldst[el];
    const float* ap = lni + (size_t)s * 256;
    const float* bp = lnj + (size_t)d * 256;
    const float* cp = lx + (size_t)el * 256;
    float l0 = 0, l1 = 0, l2 = 0, l3 = 0;
#pragma unroll
    for (int i = 0; i < 8; i++) {
        int dim = i * 32 + lane;
        float v = lrelu(ap[dim] + bp[dim] + cp[dim] + bias[dim]);
        float av = v * attn[dim];
        if (i < 2) l0 += av; else if (i < 4) l1 += av;
        else if (i < 6) l2 += av; else l3 += av;
    }
    warpReduce4(l0, l1, l2, l3);
    if (lane < 4) {
        float l = (lane == 0) ? l0 : (lane == 1) ? l1 : (lane == 2) ? l2 : l3;
        logit[(size_t)el * 4 + lane] = l;
        atomicMax(segmax + (size_t)d * 4 + lane, fenc(l));
    }
    if (lane < 16) {
        float4 xv = reinterpret_cast<const float4*>(xfeats + (size_t)el * 64)[lane];
        atomicAdd4(aggx + (size_t)d * 64 + lane * 4, xv);
    }
    if (lane == 0) atomicAdd(cnte + d, 1.0f);
}

// ---------------- graph branch edge kernel (atom->bond): warp per bond ----------------
__global__ void edgeC_kernel(
    const float* __restrict__ gi, const float* __restrict__ gj,
    const float* __restrict__ gfe, const float* __restrict__ hnode,
    const float* __restrict__ bias, const float* __restrict__ attn,
    const int* __restrict__ src, const int* __restrict__ dst,
    float* __restrict__ logit, unsigned* __restrict__ segmax,
    bf* __restrict__ neh, bf* __restrict__ nel, int E)
{
    int e    = (blockIdx.x * blockDim.x + threadIdx.x) >> 5;
    int lane = threadIdx.x & 31;
    if (e >= E) return;
    int s = src[e], d = dst[e];
    const float* ap = gi + (size_t)s * 256;
    const float* bp = gj + (size_t)d * 256;
    const float* cp = gfe + (size_t)e * 256;
    float l0 = 0, l1 = 0, l2 = 0, l3 = 0;
#pragma unroll
    for (int i = 0; i < 8; i++) {
        int dim = i * 32 + lane;
        float v = lrelu(ap[dim] + bp[dim] + cp[dim] + bias[dim]);
        float av = v * attn[dim];
        if (i < 2) l0 += av; else if (i < 4) l1 += av;
        else if (i < 6) l2 += av; else l3 += av;
    }
    warpReduce4(l0, l1, l2, l3);
    if (lane < 4) {
        float l = (lane == 0) ? l0 : (lane == 1) ? l1 : (lane == 2) ? l2 : l3;
        logit[(size_t)e * 4 + lane] = l;
        atomicMax(segmax + (size_t)d * 4 + lane, fenc(l));
    }
    if (lane < 16) {  // node_edge = h_node[src] + h_node[dst], stored as bf16 hi/lo
        float4 a = reinterpret_cast<const float4*>(hnode + (size_t)s * 64)[lane];
        float4 b = reinterpret_cast<const float4*>(hnode + (size_t)d * 64)[lane];
        a.x += b.x; a.y += b.y; a.z += b.z; a.w += b.w;
        unsigned h0, l0u, h1, l1u;
        cvt2(a.x, a.y, h0, l0u); cvt2(a.z, a.w, h1, l1u);
        *reinterpret_cast<uint2*>(neh + (size_t)e * 64 + lane * 4) = make_uint2(h0, h1);
        *reinterpret_cast<uint2*>(nel + (size_t)e * 64 + lane * 4) = make_uint2(l0u, l1u);
    }
}

// ---------------- softmax exp pass ----------------
__global__ void exp_kernel(float* __restrict__ lg, const int* __restrict__ seg,
                           const unsigned* __restrict__ segmax,
                           float* __restrict__ segsum, int M)
{
    int i = blockIdx.x * blockDim.x + threadIdx.x;
    if (i >= M * 4) return;
    int e = i >> 2, hh = i & 3;
    int d = seg[e];
    float ex = expf(lg[i] - fdec(segmax[(size_t)d * 4 + hh]));
    atomicAdd(segsum + (size_t)d * 4 + hh, ex);
    lg[i] = ex;
}

__global__ void norm_kernel(float* __restrict__ w, const int* __restrict__ seg,
                            const float* __restrict__ segsum, int M)
{
    int i = blockIdx.x * blockDim.x + threadIdx.x;
    if (i >= M * 4) return;
    w[i] = w[i] / segsum[(size_t)seg[i >> 2] * 4 + (i & 3)];
}

// segment-mean finalize + bf16 hi/lo split (aggn/aggx are only GEMM inputs)
__global__ void div_mean_cvt(const float* __restrict__ buf, const float* __restrict__ cnt,
                             bf* __restrict__ hi, bf* __restrict__ lo, long total, int cols)
{
    long i = ((long)blockIdx.x * blockDim.x + threadIdx.x) * 4;
    if (i >= total) return;
    float inv = 1.0f / fmaxf(cnt[i / cols], 1.0f);
    float4 v = *reinterpret_cast<const float4*>(buf + i);
    v.x *= inv; v.y *= inv; v.z *= inv; v.w *= inv;
    unsigned h0, l0, h1, l1;
    cvt2(v.x, v.y, h0, l0); cvt2(v.z, v.w, h1, l1);
    *reinterpret_cast<uint2*>(hi + i) = make_uint2(h0, h1);
    *reinterpret_cast<uint2*>(lo + i) = make_uint2(l0, l1);
}

// ---------------- EGAT node aggregation ----------------
__global__ void agg_node(const float* __restrict__ h, const float* __restrict__ ex,
                         const float* __restrict__ segsum,
                         const int* __restrict__ src, const int* __restrict__ dst,
                         float* __restrict__ acc, int E)
{
    int e    = (blockIdx.x * blockDim.x + threadIdx.x) >> 5;
    int lane = threadIdx.x & 31;
    if (e >= E) return;
    int s = src[e], d = dst[e];
    const float* wp = ex + (size_t)e * 4;
    const float* sp = segsum + (size_t)d * 4;
    float w0 = wp[0] / sp[0], w1 = wp[1] / sp[1], w2 = wp[2] / sp[2], w3 = wp[3] / sp[3];
    const float4* mp = reinterpret_cast<const float4*>(h + (size_t)s * 256);
    float* apd = acc + (size_t)d * 256;
#pragma unroll
    for (int j = 0; j < 2; j++) {
        int i4 = lane + j * 32;
        float4 v = mp[i4];
        float wh = (i4 < 16) ? w0 : (i4 < 32) ? w1 : (i4 < 48) ? w2 : w3;
        v.x *= wh; v.y *= wh; v.z *= wh; v.w *= wh;
        atomicAdd4(apd + i4 * 4, v);
    }
}

// ---------------- line-graph aggregation ----------------
__global__ void agg_lg(const float* __restrict__ m, const float* __restrict__ wbuf,
                       const float* __restrict__ segsum,
                       const int* __restrict__ lsrc, const int* __restrict__ ldst,
                       float* __restrict__ acc, int EL, int mode)
{
    int el   = (blockIdx.x * blockDim.x + threadIdx.x) >> 5;
    int lane = threadIdx.x & 31;
    if (el >= EL) return;
    int s = lsrc[el], d = ldst[el];
    float w0, w1, w2, w3;
    if (mode == 0) {
        const float* wp = wbuf + (size_t)el * 4;
        const float* sp = segsum + (size_t)d * 4;
        w0 = wp[0] / sp[0]; w1 = wp[1] / sp[1]; w2 = wp[2] / sp[2]; w3 = wp[3] / sp[3];
    } else {
        const float* wp = wbuf + (size_t)d * 4;
        w0 = wp[0]; w1 = wp[1]; w2 = wp[2]; w3 = wp[3];
    }
    const float4* mp = reinterpret_cast<const float4*>(m + (size_t)s * 256);
    float* apd = acc + (size_t)d * 256;
#pragma unroll
    for (int j = 0; j < 2; j++) {
        int i4 = lane + j * 32;
        float4 v = mp[i4];
        float wh = (i4 < 16) ? w0 : (i4 < 32) ? w1 : (i4 < 48) ? w2 : w3;
        v.x *= wh; v.y *= wh; v.z *= wh; v.w *= wh;
        atomicAdd4(apd + i4 * 4, v);
    }
}

// h_node = sum_h leaky(acc); emits fp32 (for edgeC gather) + bf16 hi/lo (for GEMMs)
__global__ void fin_node(const float* __restrict__ acc, float* __restrict__ hnode,
                         bf* __restrict__ hnh, bf* __restrict__ hnl, int N)
{
    int i = blockIdx.x * blockDim.x + threadIdx.x;
    if (i >= N * 64) return;
    int n = i >> 6, dd = i & 63;
    const float* a = acc + (size_t)n * 256 + dd;
    float s = lrelu(a[0]) + lrelu(a[64]) + lrelu(a[128]) + lrelu(a[192]);
    hnode[i] = s;
    bf h = __float2bfloat16(s);
    hnh[i] = h;
    hnl[i] = __float2bfloat16(s - __bfloat162float(h));
}

__global__ void fin_out(const float* __restrict__ acc, float* __restrict__ out, int E, int add)
{
    int i = blockIdx.x * blockDim.x + threadIdx.x;
    if (i >= E * 64) return;
    int e = i >> 6, dd = i & 63;
    const float* a = acc + (size_t)e * 256 + dd;
    float s = lrelu(a[0]) + lrelu(a[64]) + lrelu(a[128]) + lrelu(a[192]);
    out[i] = add ? out[i] + s : s;
}

// ---------------- host side ----------------
static inline int cdiv(long a, long b) { return (int)((a + b - 1) / b); }

static inline void gemm(const bf* Ah, const bf* Al, const bf* A2h, const bf* A2l,
                        int ldA, int Ksplit, const bf* Wh, const bf* Wl, int ldW,
                        const float* bias, float* C, int M, int K, int accum)
{
    dim3 grid((unsigned)((M + 127) / 128), 2);
    gemm_bf<<<grid, 256>>>(Ah, Al, A2h, A2l, ldA, Ksplit, Wh, Wl, ldW, bias, C, M, K, accum);
}

static inline void cvt(const float* x, bf* hi, bf* lo, long n)
{
    cvt_hilo<<<cdiv(n / 4, 256), 256>>>(x, hi, lo, n);
}

extern "C" void kernel_launch(void* const* d_in, const int* in_sizes, int n_in,
                              void* d_out, int out_size)
{
    (void)in_sizes; (void)n_in; (void)out_size;
    const float* nfeats  = (const float*)d_in[0];
    const float* efeats  = (const float*)d_in[1];
    const float* xfeats  = (const float*)d_in[2];
    const float* eWni    = (const float*)d_in[3];
    const float* eWnj    = (const float*)d_in[4];
    const float* eWfij   = (const float*)d_in[5];
    const float* eWnode  = (const float*)d_in[6];
    const float* ebnode  = (const float*)d_in[7];
    const float* eattn   = (const float*)d_in[8];
    const float* ebias   = (const float*)d_in[9];
    const float* lgWni   = (const float*)d_in[10];
    const float* lgWnj   = (const float*)d_in[11];
    const float* lgWfij  = (const float*)d_in[12];
    const float* lgWnode = (const float*)d_in[13];
    const float* lgbnode = (const float*)d_in[14];
    const float* lgattn  = (const float*)d_in[15];
    const float* lgbias  = (const float*)d_in[16];
    const float* gWni    = (const float*)d_in[17];
    const float* gWnj    = (const float*)d_in[18];
    const float* gWfij   = (const float*)d_in[19];
    const float* gWnode  = (const float*)d_in[20];
    const float* gbnode  = (const float*)d_in[21];
    const float* gattn   = (const float*)d_in[22];
    const float* gbias   = (const float*)d_in[23];
    const int*   src     = (const int*)d_in[24];
    const int*   dst     = (const int*)d_in[25];
    const int*   lsrc    = (const int*)d_in[26];
    const int*   ldst    = (const int*)d_in[27];
    float* out = (float*)d_out;

    void* p;
    float *ni, *nj, *big, *mbuf, *acc, *h, *hnode, *aggn, *cntn;
    float *aggx, *cnte, *logE, *alg, *ag, *ssum;
    unsigned* smax;
    bf *nfh, *nfl, *efh, *efl, *xfh, *xfl, *agnh, *agnl, *feh, *fel;
    bf *agxh, *agxl, *hnh, *hnl, *neh, *nel, *wh, *wl;
    cudaGetSymbolAddress(&p, g_ni);    ni    = (float*)p;
    cudaGetSymbolAddress(&p, g_nj);    nj    = (float*)p;
    cudaGetSymbolAddress(&p, g_big);   big   = (float*)p;
    cudaGetSymbolAddress(&p, g_mbuf);  mbuf  = (float*)p;
    cudaGetSymbolAddress(&p, g_accb);  acc   = (float*)p;
    cudaGetSymbolAddress(&p, g_hb);    h     = (float*)p;
    cudaGetSymbolAddress(&p, g_hnode); hnode = (float*)p;
    cudaGetSymbolAddress(&p, g_aggn);  aggn  = (float*)p;
    cudaGetSymbolAddress(&p, g_cntn);  cntn  = (float*)p;
    cudaGetSymbolAddress(&p, g_aggx);  aggx  = (float*)p;
    cudaGetSymbolAddress(&p, g_cnte);  cnte  = (float*)p;
    cudaGetSymbolAddress(&p, g_logE);  logE  = (float*)p;
    cudaGetSymbolAddress(&p, g_alg);   alg   = (float*)p;
    cudaGetSymbolAddress(&p, g_ag);    ag    = (float*)p;
    cudaGetSymbolAddress(&p, g_smax);  smax  = (unsigned*)p;
    cudaGetSymbolAddress(&p, g_ssum);  ssum  = (float*)p;
    cudaGetSymbolAddress(&p, g_nfh);   nfh   = (bf*)p;
    cudaGetSymbolAddress(&p, g_nfl);   nfl   = (bf*)p;
    cudaGetSymbolAddress(&p, g_efh);   efh   = (bf*)p;
    cudaGetSymbolAddress(&p, g_efl);   efl   = (bf*)p;
    cudaGetSymbolAddress(&p, g_xfh);   xfh   = (bf*)p;
    cudaGetSymbolAddress(&p, g_xfl);   xfl   = (bf*)p;
    cudaGetSymbolAddress(&p, g_agnh);  agnh  = (bf*)p;
    cudaGetSymbolAddress(&p, g_agnl);  agnl  = (bf*)p;
    cudaGetSymbolAddress(&p, g_feh);   feh   = (bf*)p;
    cudaGetSymbolAddress(&p, g_fel);   fel   = (bf*)p;
    cudaGetSymbolAddress(&p, g_agxh);  agxh  = (bf*)p;
    cudaGetSymbolAddress(&p, g_agxl);  agxl  = (bf*)p;
    cudaGetSymbolAddress(&p, g_hnh);   hnh   = (bf*)p;
    cudaGetSymbolAddress(&p, g_hnl);   hnl   = (bf*)p;
    cudaGetSymbolAddress(&p, g_neh);   neh   = (bf*)p;
    cudaGetSymbolAddress(&p, g_nel);   nel   = (bf*)p;
    cudaGetSymbolAddress(&p, g_wh);    wh    = (bf*)p;
    cudaGetSymbolAddress(&p, g_wl);    wl    = (bf*)p;

    const int TPB = 256;

    // ---- one-time operand conversions ----
    cvt(nfeats, nfh, nfl, (long)NN * 128);
    cvt(efeats, efh, efl, (long)EE * 128);
    cvt(xfeats, xfh, xfl, (long)ELL * 64);
    cvt(eWni,    wh + OFF_EWNI,   wl + OFF_EWNI,   32768);
    cvt(eWnj,    wh + OFF_EWNJ,   wl + OFF_EWNJ,   32768);
    cvt(eWfij,   wh + OFF_EWFIJ,  wl + OFF_EWFIJ,  32768);
    cvt(eWnode,  wh + OFF_EWNODE, wl + OFF_EWNODE, 65536);
    cvt(lgWni,   wh + OFF_LWNI,   wl + OFF_LWNI,   16384);
    cvt(lgWnj,   wh + OFF_LWNJ,   wl + OFF_LWNJ,   16384);
    cvt(lgWfij,  wh + OFF_LWFIJ,  wl + OFF_LWFIJ,  16384);
    cvt(lgWnode, wh + OFF_LWNODE, wl + OFF_LWNODE, 32768);
    cvt(gWni,    wh + OFF_GWNI,   wl + OFF_GWNI,   16384);
    cvt(gWnj,    wh + OFF_GWNJ,   wl + OFF_GWNJ,   16384);
    cvt(gWfij,   wh + OFF_GWFIJ,  wl + OFF_GWFIJ,  16384);
    cvt(gWnode,  wh + OFF_GWNODE, wl + OFF_GWNODE, 32768);

    // ================= Stage A: EGAT on atom graph =================
    cudaMemsetAsync(smax, 0, (size_t)NN * 4 * sizeof(unsigned));
    cudaMemsetAsync(ssum, 0, (size_t)NN * 4 * sizeof(float));
    cudaMemsetAsync(aggn, 0, (size_t)NN * 128 * sizeof(float));
    cudaMemsetAsync(cntn, 0, (size_t)NN * sizeof(float));
    gemm(nfh, nfl, nfh, nfl, 128, 128, wh + OFF_EWNI,  wl + OFF_EWNI,  128, nullptr, ni,  NN, 128, 0);
    gemm(nfh, nfl, nfh, nfl, 128, 128, wh + OFF_EWNJ,  wl + OFF_EWNJ,  128, nullptr, nj,  NN, 128, 0);
    gemm(efh, efl, efh, efl, 128, 128, wh + OFF_EWFIJ, wl + OFF_EWFIJ, 128, nullptr, big, EE, 128, 0);
    edgeA_kernel<<<cdiv((long)EE * 32, TPB), TPB>>>(
        ni, nj, big, efeats, ebias, eattn, src, dst,
        feh, fel, logE, smax, aggn, cntn, EE);
    exp_kernel<<<cdiv((long)EE * 4, TPB), TPB>>>(logE, dst, smax, ssum, EE);
    div_mean_cvt<<<cdiv((long)NN * 128 / 4, TPB), TPB>>>(aggn, cntn, agnh, agnl, (long)NN * 128, 128);
    gemm(nfh, nfl, agnh, agnl, 128, 128, wh + OFF_EWNODE, wl + OFF_EWNODE, 256, ebnode, h, NN, 256, 0);
    cudaMemsetAsync(ni, 0, (size_t)NN * 256 * sizeof(float));  // ni dead -> node accumulator
    agg_node<<<cdiv((long)EE * 32, TPB), TPB>>>(h, logE, ssum, src, dst, ni, EE);
    fin_node<<<cdiv((long)NN * 64, TPB), TPB>>>(ni, hnode, hnh, hnl, NN);

    // ================= Stage B: line-graph branch (bond -> angle) =================
    cudaMemsetAsync(smax, 0, (size_t)EE * 4 * sizeof(unsigned));
    cudaMemsetAsync(ssum, 0, (size_t)EE * 4 * sizeof(float));
    cudaMemsetAsync(aggx, 0, (size_t)EE * 64 * sizeof(float));
    cudaMemsetAsync(cnte, 0, (size_t)EE * sizeof(float));
    gemm(feh, fel, feh, fel, 64, 64, wh + OFF_LWNI,  wl + OFF_LWNI,  64, nullptr, mbuf, EE,  64, 0);
    gemm(feh, fel, feh, fel, 64, 64, wh + OFF_LWNJ,  wl + OFF_LWNJ,  64, nullptr, acc,  EE,  64, 0);
    gemm(xfh, xfl, xfh, xfl, 64, 64, wh + OFF_LWFIJ, wl + OFF_LWFIJ, 64, nullptr, big,  ELL, 64, 0);
    edgeB_kernel<<<cdiv((long)ELL * 32, TPB), TPB>>>(
        mbuf, acc, big, xfeats, lgbias, lgattn, lsrc, ldst,
        alg, smax, aggx, cnte, ELL);
    exp_kernel<<<cdiv((long)ELL * 4, TPB), TPB>>>(alg, ldst, smax, ssum, ELL);
    div_mean_cvt<<<cdiv((long)EE * 64 / 4, TPB), TPB>>>(aggx, cnte, agxh, agxl, (long)EE * 64, 64);
    gemm(feh, fel, agxh, agxl, 64, 64, wh + OFF_LWNODE, wl + OFF_LWNODE, 128, lgbnode, mbuf, EE, 128, 0);
    cudaMemsetAsync(acc, 0, (size_t)EE * 256 * sizeof(float));
    agg_lg<<<cdiv((long)ELL * 32, TPB), TPB>>>(mbuf, alg, ssum, lsrc, ldst, acc, ELL, 0);
    fin_out<<<cdiv((long)EE * 64, TPB), TPB>>>(acc, out, EE, 0);

    // ================= Stage C: graph branch (atom -> bond) =================
    cudaMemsetAsync(smax, 0, (size_t)NN * 4 * sizeof(unsigned));
    cudaMemsetAsync(ssum, 0, (size_t)NN * 4 * sizeof(float));
    gemm(hnh, hnl, hnh, hnl, 64, 64, wh + OFF_GWNI,  wl + OFF_GWNI,  64, nullptr, ni,  NN, 64, 0);
    gemm(hnh, hnl, hnh, hnl, 64, 64, wh + OFF_GWNJ,  wl + OFF_GWNJ,  64, nullptr, nj,  NN, 64, 0);
    gemm(feh, fel, feh, fel, 64, 64, wh + OFF_GWFIJ, wl + OFF_GWFIJ, 64, nullptr, big, EE, 64, 0);
    edgeC_kernel<<<cdiv((long)EE * 32, TPB), TPB>>>(
        ni, nj, big, hnode, gbias, gattn, src, dst,
        ag, smax, neh, nel, EE);
    exp_kernel<<<cdiv((long)EE * 4, TPB), TPB>>>(ag, dst, smax, ssum, EE);
    norm_kernel<<<cdiv((long)EE * 4, TPB), TPB>>>(ag, dst, ssum, EE);
    gemm(neh, nel, feh, fel, 64, 64, wh + OFF_GWNODE, wl + OFF_GWNODE, 128, gbnode, mbuf, EE, 128, 0);
    cudaMemsetAsync(acc, 0, (size_t)EE * 256 * sizeof(float));
    agg_lg<<<cdiv((long)ELL * 32, TPB), TPB>>>(mbuf, ag, ssum, lsrc, ldst, acc, ELL, 1);
    fin_out<<<cdiv((long)EE * 64, TPB), TPB>>>(acc, out, EE, 1);
}

// round 16
// speedup vs baseline: 1.7930x; 1.0454x over previous
#include <cuda_runtime.h>
#include <cuda_bf16.h>

#define NN   50000
#define EE   150000
#define ELL  300000

typedef __nv_bfloat16 bf;

// ---------------- scratch (device globals; no runtime allocation) ----------------
__device__ __align__(16) float    g_ni   [(size_t)NN * 256];   // ni, then node-acc, then gi
__device__ __align__(16) float    g_nj   [(size_t)NN * 256];   // nj, then gj
__device__ __align__(16) float    g_big  [(size_t)ELL * 256];  // fe, then lx, then gfe
__device__ __align__(16) float    g_mbuf [(size_t)EE * 256];   // lni, then m1, then m2
__device__ __align__(16) float    g_accb [(size_t)EE * 256];   // lnj, then lg-acc, then g-acc
__device__ __align__(16) float    g_hb   [(size_t)NN * 256];   // node transform h
__device__ __align__(16) float    g_hnode[(size_t)NN * 64];
__device__ __align__(16) float    g_aggn [(size_t)NN * 128];
__device__             float      g_cntn [NN];
__device__ __align__(16) float    g_aggx [(size_t)EE * 64];
__device__             float      g_cnte [EE];
__device__             float      g_logE [(size_t)EE * 4];
__device__             float      g_alg  [(size_t)ELL * 4];
__device__             float      g_ag   [(size_t)EE * 4];
__device__             unsigned   g_smax [(size_t)EE * 4];
__device__             float      g_ssum [(size_t)EE * 4];

// bf16 hi/lo operand buffers
__device__ __align__(16) bf g_nfh [(size_t)NN  * 128];
__device__ __align__(16) bf g_nfl [(size_t)NN  * 128];
__device__ __align__(16) bf g_efh [(size_t)EE  * 128];
__device__ __align__(16) bf g_efl [(size_t)EE  * 128];
__device__ __align__(16) bf g_xfh [(size_t)ELL * 64];
__device__ __align__(16) bf g_xfl [(size_t)ELL * 64];
__device__ __align__(16) bf g_agnh[(size_t)NN  * 128];
__device__ __align__(16) bf g_agnl[(size_t)NN  * 128];
__device__ __align__(16) bf g_feh [(size_t)EE  * 64];
__device__ __align__(16) bf g_fel [(size_t)EE  * 64];
__device__ __align__(16) bf g_agxh[(size_t)EE  * 64];
__device__ __align__(16) bf g_agxl[(size_t)EE  * 64];
__device__ __align__(16) bf g_hnh [(size_t)NN  * 64];
__device__ __align__(16) bf g_hnl [(size_t)NN  * 64];
__device__ __align__(16) bf g_neh [(size_t)EE  * 64];
__device__ __align__(16) bf g_nel [(size_t)EE  * 64];
__device__ __align__(16) bf g_wh  [327680];
__device__ __align__(16) bf g_wl  [327680];

// weight offsets in g_wh/g_wl (elements)
#define OFF_EWNI   0
#define OFF_EWNJ   32768
#define OFF_EWFIJ  65536
#define OFF_EWNODE 98304
#define OFF_LWNI   163840
#define OFF_LWNJ   180224
#define OFF_LWFIJ  196608
#define OFF_LWNODE 212992
#define OFF_GWNI   245760
#define OFF_GWNJ   262144
#define OFF_GWFIJ  278528
#define OFF_GWNODE 294912

// ---------------- device helpers ----------------
__device__ __forceinline__ float lrelu(float v) { return v >= 0.f ? v : 0.01f * v; }

__device__ __forceinline__ unsigned fenc(float f) {
    unsigned u = __float_as_uint(f);
    return (u & 0x80000000u) ? ~u : (u | 0x80000000u);
}
__device__ __forceinline__ float fdec(unsigned e) {
    unsigned u = (e & 0x80000000u) ? (e ^ 0x80000000u) : ~e;
    return __uint_as_float(u);
}

__device__ __forceinline__ void atomicAdd4(float* p, float4 v) {
#if defined(__CUDA_ARCH__) && (__CUDA_ARCH__ >= 900)
    atomicAdd(reinterpret_cast<float4*>(p), v);
#else
    atomicAdd(p + 0, v.x); atomicAdd(p + 1, v.y);
    atomicAdd(p + 2, v.z); atomicAdd(p + 3, v.w);
#endif
}

__device__ __forceinline__ void warpReduce4(float& a, float& b, float& c, float& d) {
#pragma unroll
    for (int off = 16; off; off >>= 1) {
        a += __shfl_xor_sync(0xffffffffu, a, off);
        b += __shfl_xor_sync(0xffffffffu, b, off);
        c += __shfl_xor_sync(0xffffffffu, c, off);
        d += __shfl_xor_sync(0xffffffffu, d, off);
    }
}

// split fp32 pair into bf16x2 hi + bf16x2 lo
__device__ __forceinline__ void cvt2(float x, float y, unsigned& hi, unsigned& lo) {
    __nv_bfloat162 h = __floats2bfloat162_rn(x, y);
    float rx = x - __bfloat162float(h.x);
    float ry = y - __bfloat162float(h.y);
    __nv_bfloat162 l = __floats2bfloat162_rn(rx, ry);
    hi = *reinterpret_cast<unsigned*>(&h);
    lo = *reinterpret_cast<unsigned*>(&l);
}

// ---------------- tensor-core primitives ----------------
__device__ __forceinline__ void ldsm4(unsigned& r0, unsigned& r1, unsigned& r2, unsigned& r3,
                                      unsigned addr) {
    asm volatile("ldmatrix.sync.aligned.m8n8.x4.shared.b16 {%0,%1,%2,%3}, [%4];"
                 : "=r"(r0), "=r"(r1), "=r"(r2), "=r"(r3) : "r"(addr));
}
__device__ __forceinline__ void mma_bf16(float* c, const unsigned* a, unsigned b0, unsigned b1) {
    asm volatile("mma.sync.aligned.m16n8k16.row.col.f32.bf16.bf16.f32 "
                 "{%0,%1,%2,%3}, {%4,%5,%6,%7}, {%8,%9}, {%0,%1,%2,%3};"
                 : "+f"(c[0]), "+f"(c[1]), "+f"(c[2]), "+f"(c[3])
                 : "r"(a[0]), "r"(a[1]), "r"(a[2]), "r"(a[3]), "r"(b0), "r"(b1));
}
// 16B cp.async with zfill (src_bytes = 16 or 0)
__device__ __forceinline__ void cpa(unsigned dst, const bf* src, unsigned src_bytes) {
    asm volatile("cp.async.cg.shared.global [%0], [%1], 16, %2;"
                 :: "r"(dst), "l"(src), "r"(src_bytes));
}

// ---------------- fp32 -> bf16 hi/lo conversion ----------------
__global__ void cvt_hilo(const float* __restrict__ x, bf* __restrict__ hi,
                         bf* __restrict__ lo, long n)
{
    long i = ((long)blockIdx.x * blockDim.x + threadIdx.x) * 4;
    if (i >= n) return;
    float4 v = *reinterpret_cast<const float4*>(x + i);
    unsigned h0, l0, h1, l1;
    cvt2(v.x, v.y, h0, l0); cvt2(v.z, v.w, h1, l1);
    uint2 H = make_uint2(h0, h1), L = make_uint2(l0, l1);
    *reinterpret_cast<uint2*>(hi + i) = H;
    *reinterpret_cast<uint2*>(lo + i) = L;
}

// ---------------- GEMM: C[M,256] = [A|A2][M,K] @ W[256,K]^T (+bias, +=C) ----------------
// bf16-split tensor-core GEMM: C = Ah*Bh + Ah*Bl + Al*Bh (fp32 accum).
// 2-stage cp.async double-buffered pipeline; dynamic smem (2 x 40KB stages).
// 128x128 block tile, 8 warps (2x4), 64x32 warp tile, BK=32.
#define SROW 40                        // padded row length in bf16
#define STAGE_ELEM (4 * 128 * SROW)    // elements per stage (Ah,Al,Bh,Bl)
#define STAGE_BYTES (STAGE_ELEM * 2)
__global__ void __launch_bounds__(256, 2) gemm_bf(
    const bf* __restrict__ Ah, const bf* __restrict__ Al,
    const bf* __restrict__ A2h, const bf* __restrict__ A2l, int ldA, int Ksplit,
    const bf* __restrict__ Wh, const bf* __restrict__ Wl, int ldW,
    const float* __restrict__ bias,
    float* __restrict__ C, int M, int K, int accum)
{
    extern __shared__ __align__(16) bf dsm[];
    const unsigned sbase = (unsigned)__cvta_generic_to_shared(dsm);

    const int t    = threadIdx.x;
    const int lane = t & 31;
    const int warp = t >> 5;
    const int wm   = warp & 1;
    const int wn   = warp >> 1;
    const int row0 = blockIdx.x * 128;
    const int col0 = blockIdx.y * 128;

    const unsigned g = lane >> 3, r = lane & 7;
    const unsigned aoff = ((wm * 64 + ((g & 1) << 3) + r) * SROW + ((g >> 1) << 3)) * 2;
    const unsigned boff = ((wn * 32 + ((g >> 1) << 3) + r) * SROW + ((g & 1) << 3)) * 2;

    const int lrow = t >> 1;
    const int lcol = (t & 1) << 4;   // 0 or 16 (bf16 elements)
    const int arow = row0 + lrow;
    const unsigned abytes = (arow < M) ? 16u : 0u;
    const int acl = (arow < M) ? arow : (M - 1);   // clamped (valid) gather row

    const int ntiles = K >> 5;

    // per-thread smem fill offsets (bytes, within a stage)
    const unsigned dA = (lrow * SROW + lcol) * 2;
    const unsigned dB = (2 * 128 * SROW + lrow * SROW + lcol) * 2;

    auto load_tile = [&](int kt, int st) {
        int k0 = kt << 5;
        const bf* pAh = (k0 < Ksplit) ? Ah : A2h;
        const bf* pAl = (k0 < Ksplit) ? Al : A2l;
        int ka = (k0 < Ksplit) ? k0 : (k0 - Ksplit);
        unsigned sb = sbase + st * STAGE_BYTES;
        const bf* sAh = pAh + (size_t)acl * ldA + ka + lcol;
        const bf* sAl = pAl + (size_t)acl * ldA + ka + lcol;
        cpa(sb + dA,                      sAh,     abytes);
        cpa(sb + dA + 16,                 sAh + 8, abytes);
        cpa(sb + dA + 128 * SROW * 2,     sAl,     abytes);
        cpa(sb + dA + 128 * SROW * 2 + 16, sAl + 8, abytes);
        const bf* sBh = Wh + (size_t)(col0 + lrow) * ldW + k0 + lcol;
        const bf* sBl = Wl + (size_t)(col0 + lrow) * ldW + k0 + lcol;
        cpa(sb + dB,                      sBh,     16);
        cpa(sb + dB + 16,                 sBh + 8, 16);
        cpa(sb + dB + 128 * SROW * 2,     sBl,     16);
        cpa(sb + dB + 128 * SROW * 2 + 16, sBl + 8, 16);
        asm volatile("cp.async.commit_group;");
    };

    float acc[4][4][4] = {};

    load_tile(0, 0);

    for (int kt = 0; kt < ntiles; kt++) {
        int st = kt & 1;
        if (kt + 1 < ntiles) {
            load_tile(kt + 1, st ^ 1);
            asm volatile("cp.async.wait_group 1;");
        } else {
            asm volatile("cp.async.wait_group 0;");
        }
        __syncthreads();

        unsigned base = sbase + st * STAGE_BYTES;
        unsigned uAh = base;
        unsigned uAl = base + 128 * SROW * 2;
        unsigned uBh = base + 2 * 128 * SROW * 2;
        unsigned uBl = base + 3 * 128 * SROW * 2;

#pragma unroll
        for (int kk = 0; kk < 32; kk += 16) {
            unsigned ah[4][4], al[4][4];
#pragma unroll
            for (int mt = 0; mt < 4; mt++) {
                unsigned ad = aoff + mt * (16 * SROW * 2) + kk * 2;
                ldsm4(ah[mt][0], ah[mt][1], ah[mt][2], ah[mt][3], uAh + ad);
                ldsm4(al[mt][0], al[mt][1], al[mt][2], al[mt][3], uAl + ad);
            }
#pragma unroll
            for (int nt2 = 0; nt2 < 2; nt2++) {
                unsigned bh[4], bl[4];
                unsigned bd = boff + nt2 * (16 * SROW * 2) + kk * 2;
                ldsm4(bh[0], bh[1], bh[2], bh[3], uBh + bd);
                ldsm4(bl[0], bl[1], bl[2], bl[3], uBl + bd);
#pragma unroll
                for (int mt = 0; mt < 4; mt++) {
#pragma unroll
                    for (int tn = 0; tn < 2; tn++) {
                        float* c = acc[mt][nt2 * 2 + tn];
                        mma_bf16(c, ah[mt], bh[tn * 2], bh[tn * 2 + 1]);
                        mma_bf16(c, ah[mt], bl[tn * 2], bl[tn * 2 + 1]);
                        mma_bf16(c, al[mt], bh[tn * 2], bh[tn * 2 + 1]);
                    }
                }
            }
        }
        __syncthreads();
    }

    // ---- epilogue ----
#pragma unroll
    for (int mt = 0; mt < 4; mt++) {
#pragma unroll
        for (int nt = 0; nt < 4; nt++) {
            int row = row0 + wm * 64 + mt * 16 + (lane >> 2);
            int col = col0 + wn * 32 + nt * 8 + ((lane & 3) << 1);
            float b0 = 0.f, b1 = 0.f;
            if (bias) { b0 = bias[col]; b1 = bias[col + 1]; }
            float* c = acc[mt][nt];
            if (row < M) {
                float* p = C + (size_t)row * 256 + col;
                float2 o = accum ? *reinterpret_cast<float2*>(p) : make_float2(0.f, 0.f);
                *reinterpret_cast<float2*>(p) = make_float2(o.x + c[0] + b0, o.y + c[1] + b1);
            }
            if (row + 8 < M) {
                float* p = C + (size_t)(row + 8) * 256 + col;
                float2 o = accum ? *reinterpret_cast<float2*>(p) : make_float2(0.f, 0.f);
                *reinterpret_cast<float2*>(p) = make_float2(o.x + c[2] + b0, o.y + c[3] + b1);
            }
        }
    }
}

// ---------------- EGAT edge kernel (atom graph): warp per bond ----------------
__global__ void edgeA_kernel(
    const float* __restrict__ ni, const float* __restrict__ nj,
    const float* __restrict__ fe, const float* __restrict__ efeats,
    const float* __restrict__ bias, const float* __restrict__ attn,
    const int* __restrict__ src, const int* __restrict__ dst,
    bf* __restrict__ feh, bf* __restrict__ fel,
    float* __restrict__ logit, unsigned* __restrict__ segmax,
    float* __restrict__ aggn, float* __restrict__ cntn, int E)
{
    int e    = (blockIdx.x * blockDim.x + threadIdx.x) >> 5;
    int lane = threadIdx.x & 31;
    if (e >= E) return;
    int s = src[e], d = dst[e];
    const float* ap = ni + (size_t)s * 256;
    const float* bp = nj + (size_t)d * 256;
    const float* cp = fe + (size_t)e * 256;
    float l0 = 0, l1 = 0, l2 = 0, l3 = 0, f0 = 0, f1 = 0;
#pragma unroll
    for (int i = 0; i < 8; i++) {
        int dim = i * 32 + lane;
        float v = lrelu(ap[dim] + bp[dim] + cp[dim] + bias[dim]);
        float av = v * attn[dim];
        if (i < 2) l0 += av; else if (i < 4) l1 += av;
        else if (i < 6) l2 += av; else l3 += av;
        if (i & 1) f1 += v; else f0 += v;
    }
    warpReduce4(l0, l1, l2, l3);
    {
        bf h0 = __float2bfloat16(f0);
        bf h1 = __float2bfloat16(f1);
        feh[(size_t)e * 64 + lane]      = h0;
        feh[(size_t)e * 64 + 32 + lane] = h1;
        fel[(size_t)e * 64 + lane]      = __float2bfloat16(f0 - __bfloat162float(h0));
        fel[(size_t)e * 64 + 32 + lane] = __float2bfloat16(f1 - __bfloat162float(h1));
    }
    if (lane < 4) {
        float l = (lane == 0) ? l0 : (lane == 1) ? l1 : (lane == 2) ? l2 : l3;
        logit[(size_t)e * 4 + lane] = l;
        atomicMax(segmax + (size_t)d * 4 + lane, fenc(l));
    }
    float4 ev = reinterpret_cast<const float4*>(efeats + (size_t)e * 128)[lane];
    atomicAdd4(aggn + (size_t)d * 128 + lane * 4, ev);
    if (lane == 0) atomicAdd(cntn + d, 1.0f);
}

// ---------------- line-graph edge kernel (bond->angle): warp per angle ----------------
__global__ void edgeB_kernel(
    const float* __restrict__ lni, const float* __restrict__ lnj,
    const float* __restrict__ lx, const float* __restrict__ xfeats,
    const float* __restrict__ bias, const float* __restrict__ attn,
    const int* __restrict__ lsrc, const int* __restrict__ ldst,
    float* __restrict__ logit, unsigned* __restrict__ segmax,
    float* __restrict__ aggx, float* __restrict__ cnte, int EL)
{
    int el   = (blockIdx.x * blockDim.x + threadIdx.x) >> 5;
    int lane = threadIdx.x & 31;
    if (el >= EL) return;
    int s = lsrc[el], d = ldst[el];
    const float* ap = lni + (size_t)s * 256;
    const float* bp = lnj + (size_t)d * 256;
    const float* cp = lx + (size_t)el * 256;
    float l0 = 0, l1 = 0, l2 = 0, l3 = 0;
#pragma unroll
    for (int i = 0; i < 8; i++) {
        int dim = i * 32 + lane;
        float v = lrelu(ap[dim] + bp[dim] + cp[dim] + bias[dim]);
        float av = v * attn[dim];
        if (i < 2) l0 += av; else if (i < 4) l1 += av;
        else if (i < 6) l2 += av; else l3 += av;
    }
    warpReduce4(l0, l1, l2, l3);
    if (lane < 4) {
        float l = (lane == 0) ? l0 : (lane == 1) ? l1 : (lane == 2) ? l2 : l3;
        logit[(size_t)el * 4 + lane] = l;
        atomicMax(segmax + (size_t)d * 4 + lane, fenc(l));
    }
    if (lane < 16) {
        float4 xv = reinterpret_cast<const float4*>(xfeats + (size_t)el * 64)[lane];
        atomicAdd4(aggx + (size_t)d * 64 + lane * 4, xv);
    }
    if (lane == 0) atomicAdd(cnte + d, 1.0f);
}

// ---------------- graph branch edge kernel (atom->bond): warp per bond ----------------
__global__ void edgeC_kernel(
    const float* __restrict__ gi, const float* __restrict__ gj,
    const float* __restrict__ gfe, const float* __restrict__ hnode,
    const float* __restrict__ bias, const float* __restrict__ attn,
    const int* __restrict__ src, const int* __restrict__ dst,
    float* __restrict__ logit, unsigned* __restrict__ segmax,
    bf* __restrict__ neh, bf* __restrict__ nel, int E)
{
    int e    = (blockIdx.x * blockDim.x + threadIdx.x) >> 5;
    int lane = threadIdx.x & 31;
    if (e >= E) return;
    int s = src[e], d = dst[e];
    const float* ap = gi + (size_t)s * 256;
    const float* bp = gj + (size_t)d * 256;
    const float* cp = gfe + (size_t)e * 256;
    float l0 = 0, l1 = 0, l2 = 0, l3 = 0;
#pragma unroll
    for (int i = 0; i < 8; i++) {
        int dim = i * 32 + lane;
        float v = lrelu(ap[dim] + bp[dim] + cp[dim] + bias[dim]);
        float av = v * attn[dim];
        if (i < 2) l0 += av; else if (i < 4) l1 += av;
        else if (i < 6) l2 += av; else l3 += av;
    }
    warpReduce4(l0, l1, l2, l3);
    if (lane < 4) {
        float l = (lane == 0) ? l0 : (lane == 1) ? l1 : (lane == 2) ? l2 : l3;
        logit[(size_t)e * 4 + lane] = l;
        atomicMax(segmax + (size_t)d * 4 + lane, fenc(l));
    }
    if (lane < 16) {
        float4 a = reinterpret_cast<const float4*>(hnode + (size_t)s * 64)[lane];
        float4 b = reinterpret_cast<const float4*>(hnode + (size_t)d * 64)[lane];
        a.x += b.x; a.y += b.y; a.z += b.z; a.w += b.w;
        unsigned h0, l0u, h1, l1u;
        cvt2(a.x, a.y, h0, l0u); cvt2(a.z, a.w, h1, l1u);
        *reinterpret_cast<uint2*>(neh + (size_t)e * 64 + lane * 4) = make_uint2(h0, h1);
        *reinterpret_cast<uint2*>(nel + (size_t)e * 64 + lane * 4) = make_uint2(l0u, l1u);
    }
}

// ---------------- softmax exp pass ----------------
__global__ void exp_kernel(float* __restrict__ lg, const int* __restrict__ seg,
                           const unsigned* __restrict__ segmax,
                           float* __restrict__ segsum, int M)
{
    int i = blockIdx.x * blockDim.x + threadIdx.x;
    if (i >= M * 4) return;
    int e = i >> 2, hh = i & 3;
    int d = seg[e];
    float ex = expf(lg[i] - fdec(segmax[(size_t)d * 4 + hh]));
    atomicAdd(segsum + (size_t)d * 4 + hh, ex);
    lg[i] = ex;
}

__global__ void norm_kernel(float* __restrict__ w, const int* __restrict__ seg,
                            const float* __restrict__ segsum, int M)
{
    int i = blockIdx.x * blockDim.x + threadIdx.x;
    if (i >= M * 4) return;
    w[i] = w[i] / segsum[(size_t)seg[i >> 2] * 4 + (i & 3)];
}

// segment-mean finalize + bf16 hi/lo split
__global__ void div_mean_cvt(const float* __restrict__ buf, const float* __restrict__ cnt,
                             bf* __restrict__ hi, bf* __restrict__ lo, long total, int cols)
{
    long i = ((long)blockIdx.x * blockDim.x + threadIdx.x) * 4;
    if (i >= total) return;
    float inv = 1.0f / fmaxf(cnt[i / cols], 1.0f);
    float4 v = *reinterpret_cast<const float4*>(buf + i);
    v.x *= inv; v.y *= inv; v.z *= inv; v.w *= inv;
    unsigned h0, l0, h1, l1;
    cvt2(v.x, v.y, h0, l0); cvt2(v.z, v.w, h1, l1);
    *reinterpret_cast<uint2*>(hi + i) = make_uint2(h0, h1);
    *reinterpret_cast<uint2*>(lo + i) = make_uint2(l0, l1);
}

// ---------------- EGAT node aggregation ----------------
__global__ void agg_node(const float* __restrict__ h, const float* __restrict__ ex,
                         const float* __restrict__ segsum,
                         const int* __restrict__ src, const int* __restrict__ dst,
                         float* __restrict__ acc, int E)
{
    int e    = (blockIdx.x * blockDim.x + threadIdx.x) >> 5;
    int lane = threadIdx.x & 31;
    if (e >= E) return;
    int s = src[e], d = dst[e];
    const float* wp = ex + (size_t)e * 4;
    const float* sp = segsum + (size_t)d * 4;
    float w0 = wp[0] / sp[0], w1 = wp[1] / sp[1], w2 = wp[2] / sp[2], w3 = wp[3] / sp[3];
    const float4* mp = reinterpret_cast<const float4*>(h + (size_t)s * 256);
    float* apd = acc + (size_t)d * 256;
#pragma unroll
    for (int j = 0; j < 2; j++) {
        int i4 = lane + j * 32;
        float4 v = mp[i4];
        float wh = (i4 < 16) ? w0 : (i4 < 32) ? w1 : (i4 < 48) ? w2 : w3;
        v.x *= wh; v.y *= wh; v.z *= wh; v.w *= wh;
        atomicAdd4(apd + i4 * 4, v);
    }
}

// ---------------- line-graph aggregation ----------------
__global__ void agg_lg(const float* __restrict__ m, const float* __restrict__ wbuf,
                       const float* __restrict__ segsum,
                       const int* __restrict__ lsrc, const int* __restrict__ ldst,
                       float* __restrict__ acc, int EL, int mode)
{
    int el   = (blockIdx.x * blockDim.x + threadIdx.x) >> 5;
    int lane = threadIdx.x & 31;
    if (el >= EL) return;
    int s = lsrc[el], d = ldst[el];
    float w0, w1, w2, w3;
    if (mode == 0) {
        const float* wp = wbuf + (size_t)el * 4;
        const float* sp = segsum + (size_t)d * 4;
        w0 = wp[0] / sp[0]; w1 = wp[1] / sp[1]; w2 = wp[2] / sp[2]; w3 = wp[3] / sp[3];
    } else {
        const float* wp = wbuf + (size_t)d * 4;
        w0 = wp[0]; w1 = wp[1]; w2 = wp[2]; w3 = wp[3];
    }
    const float4* mp = reinterpret_cast<const float4*>(m + (size_t)s * 256);
    float* apd = acc + (size_t)d * 256;
#pragma unroll
    for (int j = 0; j < 2; j++) {
        int i4 = lane + j * 32;
        float4 v = mp[i4];
        float wh = (i4 < 16) ? w0 : (i4 < 32) ? w1 : (i4 < 48) ? w2 : w3;
        v.x *= wh; v.y *= wh; v.z *= wh; v.w *= wh;
        atomicAdd4(apd + i4 * 4, v);
    }
}

__global__ void fin_node(const float* __restrict__ acc, float* __restrict__ hnode,
                         bf* __restrict__ hnh, bf* __restrict__ hnl, int N)
{
    int i = blockIdx.x * blockDim.x + threadIdx.x;
    if (i >= N * 64) return;
    int n = i >> 6, dd = i & 63;
    const float* a = acc + (size_t)n * 256 + dd;
    float s = lrelu(a[0]) + lrelu(a[64]) + lrelu(a[128]) + lrelu(a[192]);
    hnode[i] = s;
    bf h = __float2bfloat16(s);
    hnh[i] = h;
    hnl[i] = __float2bfloat16(s - __bfloat162float(h));
}

__global__ void fin_out(const float* __restrict__ acc, float* __restrict__ out, int E, int add)
{
    int i = blockIdx.x * blockDim.x + threadIdx.x;
    if (i >= E * 64) return;
    int e = i >> 6, dd = i & 63;
    const float* a = acc + (size_t)e * 256 + dd;
    float s = lrelu(a[0]) + lrelu(a[64]) + lrelu(a[128]) + lrelu(a[192]);
    out[i] = add ? out[i] + s : s;
}

// ---------------- host side ----------------
static inline int cdiv(long a, long b) { return (int)((a + b - 1) / b); }

static inline void gemm(const bf* Ah, const bf* Al, const bf* A2h, const bf* A2l,
                        int ldA, int Ksplit, const bf* Wh, const bf* Wl, int ldW,
                        const float* bias, float* C, int M, int K, int accum)
{
    dim3 grid((unsigned)((M + 127) / 128), 2);
    gemm_bf<<<grid, 256, 2 * STAGE_BYTES>>>(Ah, Al, A2h, A2l, ldA, Ksplit,
                                            Wh, Wl, ldW, bias, C, M, K, accum);
}

static inline void cvt(const float* x, bf* hi, bf* lo, long n)
{
    cvt_hilo<<<cdiv(n / 4, 256), 256>>>(x, hi, lo, n);
}

extern "C" void kernel_launch(void* const* d_in, const int* in_sizes, int n_in,
                              void* d_out, int out_size)
{
    (void)in_sizes; (void)n_in; (void)out_size;
    const float* nfeats  = (const float*)d_in[0];
    const float* efeats  = (const float*)d_in[1];
    const float* xfeats  = (const float*)d_in[2];
    const float* eWni    = (const float*)d_in[3];
    const float* eWnj    = (const float*)d_in[4];
    const float* eWfij   = (const float*)d_in[5];
    const float* eWnode  = (const float*)d_in[6];
    const float* ebnode  = (const float*)d_in[7];
    const float* eattn   = (const float*)d_in[8];
    const float* ebias   = (const float*)d_in[9];
    const float* lgWni   = (const float*)d_in[10];
    const float* lgWnj   = (const float*)d_in[11];
    const float* lgWfij  = (const float*)d_in[12];
    const float* lgWnode = (const float*)d_in[13];
    const float* lgbnode = (const float*)d_in[14];
    const float* lgattn  = (const float*)d_in[15];
    const float* lgbias  = (const float*)d_in[16];
    const float* gWni    = (const float*)d_in[17];
    const float* gWnj    = (const float*)d_in[18];
    const float* gWfij   = (const float*)d_in[19];
    const float* gWnode  = (const float*)d_in[20];
    const float* gbnode  = (const float*)d_in[21];
    const float* gattn   = (const float*)d_in[22];
    const float* gbias   = (const float*)d_in[23];
    const int*   src     = (const int*)d_in[24];
    const int*   dst     = (const int*)d_in[25];
    const int*   lsrc    = (const int*)d_in[26];
    const int*   ldst    = (const int*)d_in[27];
    float* out = (float*)d_out;

    cudaFuncSetAttribute(gemm_bf, cudaFuncAttributeMaxDynamicSharedMemorySize,
                         2 * STAGE_BYTES);

    void* p;
    float *ni, *nj, *big, *mbuf, *acc, *h, *hnode, *aggn, *cntn;
    float *aggx, *cnte, *logE, *alg, *ag, *ssum;
    unsigned* smax;
    bf *nfh, *nfl, *efh, *efl, *xfh, *xfl, *agnh, *agnl, *feh, *fel;
    bf *agxh, *agxl, *hnh, *hnl, *neh, *nel, *wh, *wl;
    cudaGetSymbolAddress(&p, g_ni);    ni    = (float*)p;
    cudaGetSymbolAddress(&p, g_nj);    nj    = (float*)p;
    cudaGetSymbolAddress(&p, g_big);   big   = (float*)p;
    cudaGetSymbolAddress(&p, g_mbuf);  mbuf  = (float*)p;
    cudaGetSymbolAddress(&p, g_accb);  acc   = (float*)p;
    cudaGetSymbolAddress(&p, g_hb);    h     = (float*)p;
    cudaGetSymbolAddress(&p, g_hnode); hnode = (float*)p;
    cudaGetSymbolAddress(&p, g_aggn);  aggn  = (float*)p;
    cudaGetSymbolAddress(&p, g_cntn);  cntn  = (float*)p;
    cudaGetSymbolAddress(&p, g_aggx);  aggx  = (float*)p;
    cudaGetSymbolAddress(&p, g_cnte);  cnte  = (float*)p;
    cudaGetSymbolAddress(&p, g_logE);  logE  = (float*)p;
    cudaGetSymbolAddress(&p, g_alg);   alg   = (float*)p;
    cudaGetSymbolAddress(&p, g_ag);    ag    = (float*)p;
    cudaGetSymbolAddress(&p, g_smax);  smax  = (unsigned*)p;
    cudaGetSymbolAddress(&p, g_ssum);  ssum  = (float*)p;
    cudaGetSymbolAddress(&p, g_nfh);   nfh   = (bf*)p;
    cudaGetSymbolAddress(&p, g_nfl);   nfl   = (bf*)p;
    cudaGetSymbolAddress(&p, g_efh);   efh   = (bf*)p;
    cudaGetSymbolAddress(&p, g_efl);   efl   = (bf*)p;
    cudaGetSymbolAddress(&p, g_xfh);   xfh   = (bf*)p;
    cudaGetSymbolAddress(&p, g_xfl);   xfl   = (bf*)p;
    cudaGetSymbolAddress(&p, g_agnh);  agnh  = (bf*)p;
    cudaGetSymbolAddress(&p, g_agnl);  agnl  = (bf*)p;
    cudaGetSymbolAddress(&p, g_feh);   feh   = (bf*)p;
    cudaGetSymbolAddress(&p, g_fel);   fel   = (bf*)p;
    cudaGetSymbolAddress(&p, g_agxh);  agxh  = (bf*)p;
    cudaGetSymbolAddress(&p, g_agxl);  agxl  = (bf*)p;
    cudaGetSymbolAddress(&p, g_hnh);   hnh   = (bf*)p;
    cudaGetSymbolAddress(&p, g_hnl);   hnl   = (bf*)p;
    cudaGetSymbolAddress(&p, g_neh);   neh   = (bf*)p;
    cudaGetSymbolAddress(&p, g_nel);   nel   = (bf*)p;
    cudaGetSymbolAddress(&p, g_wh);    wh    = (bf*)p;
    cudaGetSymbolAddress(&p, g_wl);    wl    = (bf*)p;

    const int TPB = 256;

    // ---- one-time operand conversions ----
    cvt(nfeats, nfh, nfl, (long)NN * 128);
    cvt(efeats, efh, efl, (long)EE * 128);
    cvt(xfeats, xfh, xfl, (long)ELL * 64);
    cvt(eWni,    wh + OFF_EWNI,   wl + OFF_EWNI,   32768);
    cvt(eWnj,    wh + OFF_EWNJ,   wl + OFF_EWNJ,   32768);
    cvt(eWfij,   wh + OFF_EWFIJ,  wl + OFF_EWFIJ,  32768);
    cvt(eWnode,  wh + OFF_EWNODE, wl + OFF_EWNODE, 65536);
    cvt(lgWni,   wh + OFF_LWNI,   wl + OFF_LWNI,   16384);
    cvt(lgWnj,   wh + OFF_LWNJ,   wl + OFF_LWNJ,   16384);
    cvt(lgWfij,  wh + OFF_LWFIJ,  wl + OFF_LWFIJ,  16384);
    cvt(lgWnode, wh + OFF_LWNODE, wl + OFF_LWNODE, 32768);
    cvt(gWni,    wh + OFF_GWNI,   wl + OFF_GWNI,   16384);
    cvt(gWnj,    wh + OFF_GWNJ,   wl + OFF_GWNJ,   16384);
    cvt(gWfij,   wh + OFF_GWFIJ,  wl + OFF_GWFIJ,  16384);
    cvt(gWnode,  wh + OFF_GWNODE, wl + OFF_GWNODE, 32768);

    // ================= Stage A: EGAT on atom graph =================
    cudaMemsetAsync(smax, 0, (size_t)NN * 4 * sizeof(unsigned));
    cudaMemsetAsync(ssum, 0, (size_t)NN * 4 * sizeof(float));
    cudaMemsetAsync(aggn, 0, (size_t)NN * 128 * sizeof(float));
    cudaMemsetAsync(cntn, 0, (size_t)NN * sizeof(float));
    gemm(nfh, nfl, nfh, nfl, 128, 128, wh + OFF_EWNI,  wl + OFF_EWNI,  128, nullptr, ni,  NN, 128, 0);
    gemm(nfh, nfl, nfh, nfl, 128, 128, wh + OFF_EWNJ,  wl + OFF_EWNJ,  128, nullptr, nj,  NN, 128, 0);
    gemm(efh, efl, efh, efl, 128, 128, wh + OFF_EWFIJ, wl + OFF_EWFIJ, 128, nullptr, big, EE, 128, 0);
    edgeA_kernel<<<cdiv((long)EE * 32, TPB), TPB>>>(
        ni, nj, big, efeats, ebias, eattn, src, dst,
        feh, fel, logE, smax, aggn, cntn, EE);
    exp_kernel<<<cdiv((long)EE * 4, TPB), TPB>>>(logE, dst, smax, ssum, EE);
    div_mean_cvt<<<cdiv((long)NN * 128 / 4, TPB), TPB>>>(aggn, cntn, agnh, agnl, (long)NN * 128, 128);
    gemm(nfh, nfl, agnh, agnl, 128, 128, wh + OFF_EWNODE, wl + OFF_EWNODE, 256, ebnode, h, NN, 256, 0);
    cudaMemsetAsync(ni, 0, (size_t)NN * 256 * sizeof(float));  // ni dead -> node accumulator
    agg_node<<<cdiv((long)EE * 32, TPB), TPB>>>(h, logE, ssum, src, dst, ni, EE);
    fin_node<<<cdiv((long)NN * 64, TPB), TPB>>>(ni, hnode, hnh, hnl, NN);

    // ================= Stage B: line-graph branch (bond -> angle) =================
    cudaMemsetAsync(smax, 0, (size_t)EE * 4 * sizeof(unsigned));
    cudaMemsetAsync(ssum, 0, (size_t)EE * 4 * sizeof(float));
    cudaMemsetAsync(aggx, 0, (size_t)EE * 64 * sizeof(float));
    cudaMemsetAsync(cnte, 0, (size_t)EE * sizeof(float));
    gemm(feh, fel, feh, fel, 64, 64, wh + OFF_LWNI,  wl + OFF_LWNI,  64, nullptr, mbuf, EE,  64, 0);
    gemm(feh, fel, feh, fel, 64, 64, wh + OFF_LWNJ,  wl + OFF_LWNJ,  64, nullptr, acc,  EE,  64, 0);
    gemm(xfh, xfl, xfh, xfl, 64, 64, wh + OFF_LWFIJ, wl + OFF_LWFIJ, 64, nullptr, big,  ELL, 64, 0);
    edgeB_kernel<<<cdiv((long)ELL * 32, TPB), TPB>>>(
        mbuf, acc, big, xfeats, lgbias, lgattn, lsrc, ldst,
        alg, smax, aggx, cnte, ELL);
    exp_kernel<<<cdiv((long)ELL * 4, TPB), TPB>>>(alg, ldst, smax, ssum, ELL);
    div_mean_cvt<<<cdiv((long)EE * 64 / 4, TPB), TPB>>>(aggx, cnte, agxh, agxl, (long)EE * 64, 64);
    gemm(feh, fel, agxh, agxl, 64, 64, wh + OFF_LWNODE, wl + OFF_LWNODE, 128, lgbnode, mbuf, EE, 128, 0);
    cudaMemsetAsync(acc, 0, (size_t)EE * 256 * sizeof(float));
    agg_lg<<<cdiv((long)ELL * 32, TPB), TPB>>>(mbuf, alg, ssum, lsrc, ldst, acc, ELL, 0);
    fin_out<<<cdiv((long)EE * 64, TPB), TPB>>>(acc, out, EE, 0);

    // ================= Stage C: graph branch (atom -> bond) =================
    cudaMemsetAsync(smax, 0, (size_t)NN * 4 * sizeof(unsigned));
    cudaMemsetAsync(ssum, 0, (size_t)NN * 4 * sizeof(float));
    gemm(hnh, hnl, hnh, hnl, 64, 64, wh + OFF_GWNI,  wl + OFF_GWNI,  64, nullptr, ni,  NN, 64, 0);
    gemm(hnh, hnl, hnh, hnl, 64, 64, wh + OFF_GWNJ,  wl + OFF_GWNJ,  64, nullptr, nj,  NN, 64, 0);
    gemm(feh, fel, feh, fel, 64, 64, wh + OFF_GWFIJ, wl + OFF_GWFIJ, 64, nullptr, big, EE, 64, 0);
    edgeC_kernel<<<cdiv((long)EE * 32, TPB), TPB>>>(
        ni, nj, big, hnode, gbias, gattn, src, dst,
        ag, smax, neh, nel, EE);
    exp_kernel<<<cdiv((long)EE * 4, TPB), TPB>>>(ag, dst, smax, ssum, EE);
    norm_kernel<<<cdiv((long)EE * 4, TPB), TPB>>>(ag, dst, ssum, EE);
    gemm(neh, nel, feh, fel, 64, 64, wh + OFF_GWNODE, wl + OFF_GWNODE, 128, gbnode, mbuf, EE, 128, 0);
    cudaMemsetAsync(acc, 0, (size_t)EE * 256 * sizeof(float));
    agg_lg<<<cdiv((long)ELL * 32, TPB), TPB>>>(mbuf, ag, ssum, lsrc, ldst, acc, ELL, 1);
    fin_out<<<cdiv((long)EE * 64, TPB), TPB>>>(acc, out, EE, 1);
}

// round 17
// speedup vs baseline: 1.8611x; 1.0380x over previous
#include <cuda_runtime.h>
#include <cuda_bf16.h>

#define NN   50000
#define EE   150000
#define ELL  300000

typedef __nv_bfloat16 bf;

// ---------------- scratch (device globals; no runtime allocation) ----------------
__device__ __align__(16) float    g_pair [(size_t)EE * 768];   // (ni|nj), (lni|lnj|gfe)
__device__ __align__(16) float    g_ginj [(size_t)NN * 512];   // (gi|gj)
__device__ __align__(16) float    g_big  [(size_t)ELL * 256];  // lx
__device__ __align__(16) float    g_fe   [(size_t)EE * 256];   // fe (stage A edge transform)
__device__ __align__(16) float    g_mbuf [(size_t)EE * 256];   // m1, then m2
__device__ __align__(16) float    g_accb [(size_t)EE * 256];   // lg-acc, then g-acc
__device__ __align__(16) float    g_hb   [(size_t)NN * 256];   // node transform h
__device__ __align__(16) float    g_ni   [(size_t)NN * 256];   // node accumulator
__device__ __align__(16) float    g_hnode[(size_t)NN * 64];
__device__ __align__(16) unsigned g_sm   [(size_t)EE * 8];     // smax | ssum (per stage)
__device__ __align__(16) float    g_aggnc[(size_t)NN * 129];   // aggn | cntn
__device__ __align__(16) float    g_aggxc[(size_t)EE * 65];    // aggx | cnte
__device__             float      g_logE [(size_t)EE * 4];
__device__             float      g_alg  [(size_t)ELL * 4];
__device__             float      g_ag   [(size_t)EE * 4];

// bf16 hi/lo operand buffers
__device__ __align__(16) bf g_nfh [(size_t)NN  * 128];
__device__ __align__(16) bf g_nfl [(size_t)NN  * 128];
__device__ __align__(16) bf g_efh [(size_t)EE  * 128];
__device__ __align__(16) bf g_efl [(size_t)EE  * 128];
__device__ __align__(16) bf g_xfh [(size_t)ELL * 64];
__device__ __align__(16) bf g_xfl [(size_t)ELL * 64];
__device__ __align__(16) bf g_agnh[(size_t)NN  * 128];
__device__ __align__(16) bf g_agnl[(size_t)NN  * 128];
__device__ __align__(16) bf g_feh [(size_t)EE  * 64];
__device__ __align__(16) bf g_fel [(size_t)EE  * 64];
__device__ __align__(16) bf g_agxh[(size_t)EE  * 64];
__device__ __align__(16) bf g_agxl[(size_t)EE  * 64];
__device__ __align__(16) bf g_hnh [(size_t)NN  * 64];
__device__ __align__(16) bf g_hnl [(size_t)NN  * 64];
__device__ __align__(16) bf g_neh [(size_t)EE  * 64];
__device__ __align__(16) bf g_nel [(size_t)EE  * 64];
__device__ __align__(16) bf g_wh  [327680];
__device__ __align__(16) bf g_wl  [327680];

// packed weight offsets (rows are contiguous for merged GEMMs)
#define OFF_EWNI   0        // 256 x 128   \ merged pair (512 rows)
#define OFF_EWNJ   32768    // 256 x 128   /
#define OFF_EWFIJ  65536    // 256 x 128
#define OFF_EWNODE 98304    // 256 x 256
#define OFF_LWNI   163840   // 256 x 64    \
#define OFF_LWNJ   180224   // 256 x 64     > merged triple (768 rows)
#define OFF_GWFIJ  196608   // 256 x 64    /
#define OFF_LWFIJ  212992   // 256 x 64
#define OFF_LWNODE 229376   // 256 x 128
#define OFF_GWNI   262144   // 256 x 64    \ merged pair (512 rows)
#define OFF_GWNJ   278528   // 256 x 64    /
#define OFF_GWNODE 294912   // 256 x 128
#define W_TOTAL    327680

// ---------------- device helpers ----------------
__device__ __forceinline__ float lrelu(float v) { return v >= 0.f ? v : 0.01f * v; }

__device__ __forceinline__ unsigned fenc(float f) {
    unsigned u = __float_as_uint(f);
    return (u & 0x80000000u) ? ~u : (u | 0x80000000u);
}
__device__ __forceinline__ float fdec(unsigned e) {
    unsigned u = (e & 0x80000000u) ? (e ^ 0x80000000u) : ~e;
    return __uint_as_float(u);
}

__device__ __forceinline__ void atomicAdd4(float* p, float4 v) {
#if defined(__CUDA_ARCH__) && (__CUDA_ARCH__ >= 900)
    atomicAdd(reinterpret_cast<float4*>(p), v);
#else
    atomicAdd(p + 0, v.x); atomicAdd(p + 1, v.y);
    atomicAdd(p + 2, v.z); atomicAdd(p + 3, v.w);
#endif
}

__device__ __forceinline__ void warpReduce4(float& a, float& b, float& c, float& d) {
#pragma unroll
    for (int off = 16; off; off >>= 1) {
        a += __shfl_xor_sync(0xffffffffu, a, off);
        b += __shfl_xor_sync(0xffffffffu, b, off);
        c += __shfl_xor_sync(0xffffffffu, c, off);
        d += __shfl_xor_sync(0xffffffffu, d, off);
    }
}

__device__ __forceinline__ void cvt2(float x, float y, unsigned& hi, unsigned& lo) {
    __nv_bfloat162 h = __floats2bfloat162_rn(x, y);
    float rx = x - __bfloat162float(h.x);
    float ry = y - __bfloat162float(h.y);
    __nv_bfloat162 l = __floats2bfloat162_rn(rx, ry);
    hi = *reinterpret_cast<unsigned*>(&h);
    lo = *reinterpret_cast<unsigned*>(&l);
}

// ---------------- tensor-core primitives ----------------
__device__ __forceinline__ void ldsm4(unsigned& r0, unsigned& r1, unsigned& r2, unsigned& r3,
                                      unsigned addr) {
    asm volatile("ldmatrix.sync.aligned.m8n8.x4.shared.b16 {%0,%1,%2,%3}, [%4];"
                 : "=r"(r0), "=r"(r1), "=r"(r2), "=r"(r3) : "r"(addr));
}
__device__ __forceinline__ void mma_bf16(float* c, const unsigned* a, unsigned b0, unsigned b1) {
    asm volatile("mma.sync.aligned.m16n8k16.row.col.f32.bf16.bf16.f32 "
                 "{%0,%1,%2,%3}, {%4,%5,%6,%7}, {%8,%9}, {%0,%1,%2,%3};"
                 : "+f"(c[0]), "+f"(c[1]), "+f"(c[2]), "+f"(c[3])
                 : "r"(a[0]), "r"(a[1]), "r"(a[2]), "r"(a[3]), "r"(b0), "r"(b1));
}
__device__ __forceinline__ void cpa(unsigned dst, const bf* src, unsigned src_bytes) {
    asm volatile("cp.async.cg.shared.global [%0], [%1], 16, %2;"
                 :: "r"(dst), "l"(src), "r"(src_bytes));
}

// ---------------- fp32 -> bf16 hi/lo conversion ----------------
__global__ void cvt_hilo(const float* __restrict__ x, bf* __restrict__ hi,
                         bf* __restrict__ lo, long n)
{
    long i = ((long)blockIdx.x * blockDim.x + threadIdx.x) * 4;
    if (i >= n) return;
    float4 v = *reinterpret_cast<const float4*>(x + i);
    unsigned h0, l0, h1, l1;
    cvt2(v.x, v.y, h0, l0); cvt2(v.z, v.w, h1, l1);
    *reinterpret_cast<uint2*>(hi + i) = make_uint2(h0, h1);
    *reinterpret_cast<uint2*>(lo + i) = make_uint2(l0, l1);
}

// batched weight conversion: 12 segments into one packed buffer
struct WCvt { const float* src[12]; int cum[13]; };
__global__ void cvt_w(WCvt w, bf* __restrict__ hi, bf* __restrict__ lo)
{
    int i = (blockIdx.x * blockDim.x + threadIdx.x) * 4;
    if (i >= W_TOTAL) return;
    int s = 0;
#pragma unroll
    for (int k = 0; k < 11; k++) if (i >= w.cum[k + 1]) s = k + 1;
    const float* src = w.src[s] + (i - w.cum[s]);
    float4 v = *reinterpret_cast<const float4*>(src);
    unsigned h0, l0, h1, l1;
    cvt2(v.x, v.y, h0, l0); cvt2(v.z, v.w, h1, l1);
    *reinterpret_cast<uint2*>(hi + i) = make_uint2(h0, h1);
    *reinterpret_cast<uint2*>(lo + i) = make_uint2(l0, l1);
}

// ---------------- GEMM: C[M,N] = [A|A2][M,K] @ W[N,K]^T (+bias, +=C) ----------------
// bf16-split tensor-core GEMM: C = Ah*Bh + Ah*Bl + Al*Bh (fp32 accum).
// 2-stage cp.async pipeline, 128x128 block tile, 8 warps, 64x32 warp tile, BK=32.
#define SROW 40
#define STAGE_ELEM (4 * 128 * SROW)
#define STAGE_BYTES (STAGE_ELEM * 2)
__global__ void __launch_bounds__(256, 2) gemm_bf(
    const bf* __restrict__ Ah, const bf* __restrict__ Al,
    const bf* __restrict__ A2h, const bf* __restrict__ A2l, int ldA, int Ksplit,
    const bf* __restrict__ Wh, const bf* __restrict__ Wl, int ldW,
    const float* __restrict__ bias,
    float* __restrict__ C, int ldC, int M, int K, int accum)
{
    extern __shared__ __align__(16) bf dsm[];
    const unsigned sbase = (unsigned)__cvta_generic_to_shared(dsm);

    const int t    = threadIdx.x;
    const int lane = t & 31;
    const int warp = t >> 5;
    const int wm   = warp & 1;
    const int wn   = warp >> 1;
    const int row0 = blockIdx.x * 128;
    const int col0 = blockIdx.y * 128;

    const unsigned g = lane >> 3, r = lane & 7;
    const unsigned aoff = ((wm * 64 + ((g & 1) << 3) + r) * SROW + ((g >> 1) << 3)) * 2;
    const unsigned boff = ((wn * 32 + ((g >> 1) << 3) + r) * SROW + ((g & 1) << 3)) * 2;

    const int lrow = t >> 1;
    const int lcol = (t & 1) << 4;
    const int arow = row0 + lrow;
    const unsigned abytes = (arow < M) ? 16u : 0u;
    const int acl = (arow < M) ? arow : (M - 1);

    const int ntiles = K >> 5;

    const unsigned dA = (lrow * SROW + lcol) * 2;
    const unsigned dB = (2 * 128 * SROW + lrow * SROW + lcol) * 2;

    auto load_tile = [&](int kt, int st) {
        int k0 = kt << 5;
        const bf* pAh = (k0 < Ksplit) ? Ah : A2h;
        const bf* pAl = (k0 < Ksplit) ? Al : A2l;
        int ka = (k0 < Ksplit) ? k0 : (k0 - Ksplit);
        unsigned sb = sbase + st * STAGE_BYTES;
        const bf* sAh = pAh + (size_t)acl * ldA + ka + lcol;
        const bf* sAl = pAl + (size_t)acl * ldA + ka + lcol;
        cpa(sb + dA,                       sAh,     abytes);
        cpa(sb + dA + 16,                  sAh + 8, abytes);
        cpa(sb + dA + 128 * SROW * 2,      sAl,     abytes);
        cpa(sb + dA + 128 * SROW * 2 + 16, sAl + 8, abytes);
        const bf* sBh = Wh + (size_t)(col0 + lrow) * ldW + k0 + lcol;
        const bf* sBl = Wl + (size_t)(col0 + lrow) * ldW + k0 + lcol;
        cpa(sb + dB,                       sBh,     16);
        cpa(sb + dB + 16,                  sBh + 8, 16);
        cpa(sb + dB + 128 * SROW * 2,      sBl,     16);
        cpa(sb + dB + 128 * SROW * 2 + 16, sBl + 8, 16);
        asm volatile("cp.async.commit_group;");
    };

    float acc[4][4][4] = {};

    load_tile(0, 0);

    for (int kt = 0; kt < ntiles; kt++) {
        int st = kt & 1;
        if (kt + 1 < ntiles) {
            load_tile(kt + 1, st ^ 1);
            asm volatile("cp.async.wait_group 1;");
        } else {
            asm volatile("cp.async.wait_group 0;");
        }
        __syncthreads();

        unsigned base = sbase + st * STAGE_BYTES;
        unsigned uAh = base;
        unsigned uAl = base + 128 * SROW * 2;
        unsigned uBh = base + 2 * 128 * SROW * 2;
        unsigned uBl = base + 3 * 128 * SROW * 2;

#pragma unroll
        for (int kk = 0; kk < 32; kk += 16) {
            unsigned ah[4][4], al[4][4];
#pragma unroll
            for (int mt = 0; mt < 4; mt++) {
                unsigned ad = aoff + mt * (16 * SROW * 2) + kk * 2;
                ldsm4(ah[mt][0], ah[mt][1], ah[mt][2], ah[mt][3], uAh + ad);
                ldsm4(al[mt][0], al[mt][1], al[mt][2], al[mt][3], uAl + ad);
            }
#pragma unroll
            for (int nt2 = 0; nt2 < 2; nt2++) {
                unsigned bh[4], bl[4];
                unsigned bd = boff + nt2 * (16 * SROW * 2) + kk * 2;
                ldsm4(bh[0], bh[1], bh[2], bh[3], uBh + bd);
                ldsm4(bl[0], bl[1], bl[2], bl[3], uBl + bd);
#pragma unroll
                for (int mt = 0; mt < 4; mt++) {
#pragma unroll
                    for (int tn = 0; tn < 2; tn++) {
                        float* c = acc[mt][nt2 * 2 + tn];
                        mma_bf16(c, ah[mt], bh[tn * 2], bh[tn * 2 + 1]);
                        mma_bf16(c, ah[mt], bl[tn * 2], bl[tn * 2 + 1]);
                        mma_bf16(c, al[mt], bh[tn * 2], bh[tn * 2 + 1]);
                    }
                }
            }
        }
        __syncthreads();
    }

#pragma unroll
    for (int mt = 0; mt < 4; mt++) {
#pragma unroll
        for (int nt = 0; nt < 4; nt++) {
            int row = row0 + wm * 64 + mt * 16 + (lane >> 2);
            int col = col0 + wn * 32 + nt * 8 + ((lane & 3) << 1);
            float b0 = 0.f, b1 = 0.f;
            if (bias) { b0 = bias[col]; b1 = bias[col + 1]; }
            float* c = acc[mt][nt];
            if (row < M) {
                float* p = C + (size_t)row * ldC + col;
                float2 o = accum ? *reinterpret_cast<float2*>(p) : make_float2(0.f, 0.f);
                *reinterpret_cast<float2*>(p) = make_float2(o.x + c[0] + b0, o.y + c[1] + b1);
            }
            if (row + 8 < M) {
                float* p = C + (size_t)(row + 8) * ldC + col;
                float2 o = accum ? *reinterpret_cast<float2*>(p) : make_float2(0.f, 0.f);
                *reinterpret_cast<float2*>(p) = make_float2(o.x + c[2] + b0, o.y + c[3] + b1);
            }
        }
    }
}

// ---------------- EGAT edge kernel (atom graph): warp per bond ----------------
__global__ void edgeA_kernel(
    const float* __restrict__ pair, int ps,
    const float* __restrict__ fe, int cs,
    const float* __restrict__ efeats,
    const float* __restrict__ bias, const float* __restrict__ attn,
    const int* __restrict__ src, const int* __restrict__ dst,
    bf* __restrict__ feh, bf* __restrict__ fel,
    float* __restrict__ logit, unsigned* __restrict__ segmax,
    float* __restrict__ aggn, float* __restrict__ cntn, int E)
{
    int e    = (blockIdx.x * blockDim.x + threadIdx.x) >> 5;
    int lane = threadIdx.x & 31;
    if (e >= E) return;
    int s = src[e], d = dst[e];
    const float* ap = pair + (size_t)s * ps;
    const float* bp = pair + (size_t)d * ps + 256;
    const float* cp = fe + (size_t)e * cs;
    float l0 = 0, l1 = 0, l2 = 0, l3 = 0, f0 = 0, f1 = 0;
#pragma unroll
    for (int i = 0; i < 8; i++) {
        int dim = i * 32 + lane;
        float v = lrelu(ap[dim] + bp[dim] + cp[dim] + bias[dim]);
        float av = v * attn[dim];
        if (i < 2) l0 += av; else if (i < 4) l1 += av;
        else if (i < 6) l2 += av; else l3 += av;
        if (i & 1) f1 += v; else f0 += v;
    }
    warpReduce4(l0, l1, l2, l3);
    {
        bf h0 = __float2bfloat16(f0);
        bf h1 = __float2bfloat16(f1);
        feh[(size_t)e * 64 + lane]      = h0;
        feh[(size_t)e * 64 + 32 + lane] = h1;
        fel[(size_t)e * 64 + lane]      = __float2bfloat16(f0 - __bfloat162float(h0));
        fel[(size_t)e * 64 + 32 + lane] = __float2bfloat16(f1 - __bfloat162float(h1));
    }
    if (lane < 4) {
        float l = (lane == 0) ? l0 : (lane == 1) ? l1 : (lane == 2) ? l2 : l3;
        logit[(size_t)e * 4 + lane] = l;
        atomicMax(segmax + (size_t)d * 4 + lane, fenc(l));
    }
    float4 ev = reinterpret_cast<const float4*>(efeats + (size_t)e * 128)[lane];
    atomicAdd4(aggn + (size_t)d * 128 + lane * 4, ev);
    if (lane == 0) atomicAdd(cntn + d, 1.0f);
}

// ---------------- line-graph edge kernel (bond->angle): warp per angle ----------------
__global__ void edgeB_kernel(
    const float* __restrict__ pair, int ps,
    const float* __restrict__ lx, int cs,
    const float* __restrict__ xfeats,
    const float* __restrict__ bias, const float* __restrict__ attn,
    const int* __restrict__ lsrc, const int* __restrict__ ldst,
    float* __restrict__ logit, unsigned* __restrict__ segmax,
    float* __restrict__ aggx, float* __restrict__ cnte, int EL)
{
    int el   = (blockIdx.x * blockDim.x + threadIdx.x) >> 5;
    int lane = threadIdx.x & 31;
    if (el >= EL) return;
    int s = lsrc[el], d = ldst[el];
    const float* ap = pair + (size_t)s * ps;
    const float* bp = pair + (size_t)d * ps + 256;
    const float* cp = lx + (size_t)el * cs;
    float l0 = 0, l1 = 0, l2 = 0, l3 = 0;
#pragma unroll
    for (int i = 0; i < 8; i++) {
        int dim = i * 32 + lane;
        float v = lrelu(ap[dim] + bp[dim] + cp[dim] + bias[dim]);
        float av = v * attn[dim];
        if (i < 2) l0 += av; else if (i < 4) l1 += av;
        else if (i < 6) l2 += av; else l3 += av;
    }
    warpReduce4(l0, l1, l2, l3);
    if (lane < 4) {
        float l = (lane == 0) ? l0 : (lane == 1) ? l1 : (lane == 2) ? l2 : l3;
        logit[(size_t)el * 4 + lane] = l;
        atomicMax(segmax + (size_t)d * 4 + lane, fenc(l));
    }
    if (lane < 16) {
        float4 xv = reinterpret_cast<const float4*>(xfeats + (size_t)el * 64)[lane];
        atomicAdd4(aggx + (size_t)d * 64 + lane * 4, xv);
    }
    if (lane == 0) atomicAdd(cnte + d, 1.0f);
}

// ---------------- graph branch edge kernel (atom->bond): warp per bond ----------------
__global__ void edgeC_kernel(
    const float* __restrict__ pair, int ps,
    const float* __restrict__ gfe, int cs,
    const float* __restrict__ hnode,
    const float* __restrict__ bias, const float* __restrict__ attn,
    const int* __restrict__ src, const int* __restrict__ dst,
    float* __restrict__ logit, unsigned* __restrict__ segmax,
    bf* __restrict__ neh, bf* __restrict__ nel, int E)
{
    int e    = (blockIdx.x * blockDim.x + threadIdx.x) >> 5;
    int lane = threadIdx.x & 31;
    if (e >= E) return;
    int s = src[e], d = dst[e];
    const float* ap = pair + (size_t)s * ps;
    const float* bp = pair + (size_t)d * ps + 256;
    const float* cp = gfe + (size_t)e * cs;
    float l0 = 0, l1 = 0, l2 = 0, l3 = 0;
#pragma unroll
    for (int i = 0; i < 8; i++) {
        int dim = i * 32 + lane;
        float v = lrelu(ap[dim] + bp[dim] + cp[dim] + bias[dim]);
        float av = v * attn[dim];
        if (i < 2) l0 += av; else if (i < 4) l1 += av;
        else if (i < 6) l2 += av; else l3 += av;
    }
    warpReduce4(l0, l1, l2, l3);
    if (lane < 4) {
        float l = (lane == 0) ? l0 : (lane == 1) ? l1 : (lane == 2) ? l2 : l3;
        logit[(size_t)e * 4 + lane] = l;
        atomicMax(segmax + (size_t)d * 4 + lane, fenc(l));
    }
    if (lane < 16) {
        float4 a = reinterpret_cast<const float4*>(hnode + (size_t)s * 64)[lane];
        float4 b = reinterpret_cast<const float4*>(hnode + (size_t)d * 64)[lane];
        a.x += b.x; a.y += b.y; a.z += b.z; a.w += b.w;
        unsigned h0, l0u, h1, l1u;
        cvt2(a.x, a.y, h0, l0u); cvt2(a.z, a.w, h1, l1u);
        *reinterpret_cast<uint2*>(neh + (size_t)e * 64 + lane * 4) = make_uint2(h0, h1);
        *reinterpret_cast<uint2*>(nel + (size_t)e * 64 + lane * 4) = make_uint2(l0u, l1u);
    }
}

// ---------------- softmax exp pass ----------------
__global__ void exp_kernel(float* __restrict__ lg, const int* __restrict__ seg,
                           const unsigned* __restrict__ segmax,
                           float* __restrict__ segsum, int M)
{
    int i = blockIdx.x * blockDim.x + threadIdx.x;
    if (i >= M * 4) return;
    int e = i >> 2, hh = i & 3;
    int d = seg[e];
    float ex = expf(lg[i] - fdec(segmax[(size_t)d * 4 + hh]));
    atomicAdd(segsum + (size_t)d * 4 + hh, ex);
    lg[i] = ex;
}

__global__ void norm_kernel(float* __restrict__ w, const int* __restrict__ seg,
                            const float* __restrict__ segsum, int M)
{
    int i = blockIdx.x * blockDim.x + threadIdx.x;
    if (i >= M * 4) return;
    w[i] = w[i] / segsum[(size_t)seg[i >> 2] * 4 + (i & 3)];
}

// segment-mean finalize + bf16 hi/lo split
__global__ void div_mean_cvt(const float* __restrict__ buf, const float* __restrict__ cnt,
                             bf* __restrict__ hi, bf* __restrict__ lo, long total, int cols)
{
    long i = ((long)blockIdx.x * blockDim.x + threadIdx.x) * 4;
    if (i >= total) return;
    float inv = 1.0f / fmaxf(cnt[i / cols], 1.0f);
    float4 v = *reinterpret_cast<const float4*>(buf + i);
    v.x *= inv; v.y *= inv; v.z *= inv; v.w *= inv;
    unsigned h0, l0, h1, l1;
    cvt2(v.x, v.y, h0, l0); cvt2(v.z, v.w, h1, l1);
    *reinterpret_cast<uint2*>(hi + i) = make_uint2(h0, h1);
    *reinterpret_cast<uint2*>(lo + i) = make_uint2(l0, l1);
}

// ---------------- EGAT node aggregation ----------------
__global__ void agg_node(const float* __restrict__ h, const float* __restrict__ ex,
                         const float* __restrict__ segsum,
                         const int* __restrict__ src, const int* __restrict__ dst,
                         float* __restrict__ acc, int E)
{
    int e    = (blockIdx.x * blockDim.x + threadIdx.x) >> 5;
    int lane = threadIdx.x & 31;
    if (e >= E) return;
    int s = src[e], d = dst[e];
    const float* wp = ex + (size_t)e * 4;
    const float* sp = segsum + (size_t)d * 4;
    float w0 = wp[0] / sp[0], w1 = wp[1] / sp[1], w2 = wp[2] / sp[2], w3 = wp[3] / sp[3];
    const float4* mp = reinterpret_cast<const float4*>(h + (size_t)s * 256);
    float* apd = acc + (size_t)d * 256;
#pragma unroll
    for (int j = 0; j < 2; j++) {
        int i4 = lane + j * 32;
        float4 v = mp[i4];
        float wh = (i4 < 16) ? w0 : (i4 < 32) ? w1 : (i4 < 48) ? w2 : w3;
        v.x *= wh; v.y *= wh; v.z *= wh; v.w *= wh;
        atomicAdd4(apd + i4 * 4, v);
    }
}

// ---------------- line-graph aggregation ----------------
__global__ void agg_lg(const float* __restrict__ m, const float* __restrict__ wbuf,
                       const float* __restrict__ segsum,
                       const int* __restrict__ lsrc, const int* __restrict__ ldst,
                       float* __restrict__ acc, int EL, int mode)
{
    int el   = (blockIdx.x * blockDim.x + threadIdx.x) >> 5;
    int lane = threadIdx.x & 31;
    if (el >= EL) return;
    int s = lsrc[el], d = ldst[el];
    float w0, w1, w2, w3;
    if (mode == 0) {
        const float* wp = wbuf + (size_t)el * 4;
        const float* sp = segsum + (size_t)d * 4;
        w0 = wp[0] / sp[0]; w1 = wp[1] / sp[1]; w2 = wp[2] / sp[2]; w3 = wp[3] / sp[3];
    } else {
        const float* wp = wbuf + (size_t)d * 4;
        w0 = wp[0]; w1 = wp[1]; w2 = wp[2]; w3 = wp[3];
    }
    const float4* mp = reinterpret_cast<const float4*>(m + (size_t)s * 256);
    float* apd = acc + (size_t)d * 256;
#pragma unroll
    for (int j = 0; j < 2; j++) {
        int i4 = lane + j * 32;
        float4 v = mp[i4];
        float wh = (i4 < 16) ? w0 : (i4 < 32) ? w1 : (i4 < 48) ? w2 : w3;
        v.x *= wh; v.y *= wh; v.z *= wh; v.w *= wh;
        atomicAdd4(apd + i4 * 4, v);
    }
}

__global__ void fin_node(const float* __restrict__ acc, float* __restrict__ hnode,
                         bf* __restrict__ hnh, bf* __restrict__ hnl, int N)
{
    int i = blockIdx.x * blockDim.x + threadIdx.x;
    if (i >= N * 64) return;
    int n = i >> 6, dd = i & 63;
    const float* a = acc + (size_t)n * 256 + dd;
    float s = lrelu(a[0]) + lrelu(a[64]) + lrelu(a[128]) + lrelu(a[192]);
    hnode[i] = s;
    bf h = __float2bfloat16(s);
    hnh[i] = h;
    hnl[i] = __float2bfloat16(s - __bfloat162float(h));
}

__global__ void fin_out(const float* __restrict__ acc, float* __restrict__ out, int E, int add)
{
    int i = blockIdx.x * blockDim.x + threadIdx.x;
    if (i >= E * 64) return;
    int e = i >> 6, dd = i & 63;
    const float* a = acc + (size_t)e * 256 + dd;
    float s = lrelu(a[0]) + lrelu(a[64]) + lrelu(a[128]) + lrelu(a[192]);
    out[i] = add ? out[i] + s : s;
}

// ---------------- host side ----------------
static inline int cdiv(long a, long b) { return (int)((a + b - 1) / b); }

static inline void gemm(const bf* Ah, const bf* Al, const bf* A2h, const bf* A2l,
                        int ldA, int Ksplit, const bf* Wh, const bf* Wl, int ldW,
                        const float* bias, float* C, int ldC, int M, int N, int K, int accum)
{
    dim3 grid((unsigned)((M + 127) / 128), (unsigned)(N / 128));
    gemm_bf<<<grid, 256, 2 * STAGE_BYTES>>>(Ah, Al, A2h, A2l, ldA, Ksplit,
                                            Wh, Wl, ldW, bias, C, ldC, M, K, accum);
}

static inline void cvt(const float* x, bf* hi, bf* lo, long n)
{
    cvt_hilo<<<cdiv(n / 4, 256), 256>>>(x, hi, lo, n);
}

extern "C" void kernel_launch(void* const* d_in, const int* in_sizes, int n_in,
                              void* d_out, int out_size)
{
    (void)in_sizes; (void)n_in; (void)out_size;
    const float* nfeats  = (const float*)d_in[0];
    const float* efeats  = (const float*)d_in[1];
    const float* xfeats  = (const float*)d_in[2];
    const float* eWni    = (const float*)d_in[3];
    const float* eWnj    = (const float*)d_in[4];
    const float* eWfij   = (const float*)d_in[5];
    const float* eWnode  = (const float*)d_in[6];
    const float* ebnode  = (const float*)d_in[7];
    const float* eattn   = (const float*)d_in[8];
    const float* ebias   = (const float*)d_in[9];
    const float* lgWni   = (const float*)d_in[10];
    const float* lgWnj   = (const float*)d_in[11];
    const float* lgWfij  = (const float*)d_in[12];
    const float* lgWnode = (const float*)d_in[13];
    const float* lgbnode = (const float*)d_in[14];
    const float* lgattn  = (const float*)d_in[15];
    const float* lgbias  = (const float*)d_in[16];
    const float* gWni    = (const float*)d_in[17];
    const float* gWnj    = (const float*)d_in[18];
    const float* gWfij   = (const float*)d_in[19];
    const float* gWnode  = (const float*)d_in[20];
    const float* gbnode  = (const float*)d_in[21];
    const float* gattn   = (const float*)d_in[22];
    const float* gbias   = (const float*)d_in[23];
    const int*   src     = (const int*)d_in[24];
    const int*   dst     = (const int*)d_in[25];
    const int*   lsrc    = (const int*)d_in[26];
    const int*   ldst    = (const int*)d_in[27];
    float* out = (float*)d_out;

    cudaFuncSetAttribute(gemm_bf, cudaFuncAttributeMaxDynamicSharedMemorySize,
                         2 * STAGE_BYTES);

    void* p;
    float *pair, *ginj, *big, *fe, *mbuf, *acc, *h, *ni, *hnode;
    float *aggnc, *aggxc, *logE, *alg, *ag;
    unsigned* sm;
    bf *nfh, *nfl, *efh, *efl, *xfh, *xfl, *agnh, *agnl, *feh, *fel;
    bf *agxh, *agxl, *hnh, *hnl, *neh, *nel, *wh, *wl;
    cudaGetSymbolAddress(&p, g_pair);  pair  = (float*)p;
    cudaGetSymbolAddress(&p, g_ginj);  ginj  = (float*)p;
    cudaGetSymbolAddress(&p, g_big);   big   = (float*)p;
    cudaGetSymbolAddress(&p, g_fe);    fe    = (float*)p;
    cudaGetSymbolAddress(&p, g_mbuf);  mbuf  = (float*)p;
    cudaGetSymbolAddress(&p, g_accb);  acc   = (float*)p;
    cudaGetSymbolAddress(&p, g_hb);    h     = (float*)p;
    cudaGetSymbolAddress(&p, g_ni);    ni    = (float*)p;
    cudaGetSymbolAddress(&p, g_hnode); hnode = (float*)p;
    cudaGetSymbolAddress(&p, g_sm);    sm    = (unsigned*)p;
    cudaGetSymbolAddress(&p, g_aggnc); aggnc = (float*)p;
    cudaGetSymbolAddress(&p, g_aggxc); aggxc = (float*)p;
    cudaGetSymbolAddress(&p, g_logE);  logE  = (float*)p;
    cudaGetSymbolAddress(&p, g_alg);   alg   = (float*)p;
    cudaGetSymbolAddress(&p, g_ag);    ag    = (float*)p;
    cudaGetSymbolAddress(&p, g_nfh);   nfh   = (bf*)p;
    cudaGetSymbolAddress(&p, g_nfl);   nfl   = (bf*)p;
    cudaGetSymbolAddress(&p, g_efh);   efh   = (bf*)p;
    cudaGetSymbolAddress(&p, g_efl);   efl   = (bf*)p;
    cudaGetSymbolAddress(&p, g_xfh);   xfh   = (bf*)p;
    cudaGetSymbolAddress(&p, g_xfl);   xfl   = (bf*)p;
    cudaGetSymbolAddress(&p, g_agnh);  agnh  = (bf*)p;
    cudaGetSymbolAddress(&p, g_agnl);  agnl  = (bf*)p;
    cudaGetSymbolAddress(&p, g_feh);   feh   = (bf*)p;
    cudaGetSymbolAddress(&p, g_fel);   fel   = (bf*)p;
    cudaGetSymbolAddress(&p, g_agxh);  agxh  = (bf*)p;
    cudaGetSymbolAddress(&p, g_agxl);  agxl  = (bf*)p;
    cudaGetSymbolAddress(&p, g_hnh);   hnh   = (bf*)p;
    cudaGetSymbolAddress(&p, g_hnl);   hnl   = (bf*)p;
    cudaGetSymbolAddress(&p, g_neh);   neh   = (bf*)p;
    cudaGetSymbolAddress(&p, g_nel);   nel   = (bf*)p;
    cudaGetSymbolAddress(&p, g_wh);    wh    = (bf*)p;
    cudaGetSymbolAddress(&p, g_wl);    wl    = (bf*)p;

    const int TPB = 256;

    // ---- launches 0-3: operand conversions ----
    cvt(nfeats, nfh, nfl, (long)NN * 128);                 // launch 0
    cvt(efeats, efh, efl, (long)EE * 128);                 // launch 1
    cvt(xfeats, xfh, xfl, (long)ELL * 64);                 // launch 2
    {
        WCvt w;
        const float* srcs[12] = {eWni, eWnj, eWfij, eWnode, lgWni, lgWnj,
                                 gWfij, lgWfij, lgWnode, gWni, gWnj, gWnode};
        int counts[12] = {32768, 32768, 32768, 65536, 16384, 16384,
                          16384, 16384, 32768, 16384, 16384, 32768};
        int c = 0;
        for (int i = 0; i < 12; i++) { w.src[i] = srcs[i]; w.cum[i] = c; c += counts[i]; }
        w.cum[12] = c;
        cvt_w<<<cdiv(W_TOTAL / 4, TPB), TPB>>>(w, wh, wl); // launch 3
    }

    // ---- launches 4-5: two GEMMs (launch 5 = biggest GEMM, lands under ncu -s 5) ----
    gemm(nfh, nfl, nfh, nfl, 128, 128, wh + OFF_EWNI, wl + OFF_EWNI, 128,
         nullptr, pair, 512, NN, 512, 128, 0);             // launch 4: (ni|nj)
    gemm(xfh, xfl, xfh, xfl, 64, 64, wh + OFF_LWFIJ, wl + OFF_LWFIJ, 64,
         nullptr, big, 256, ELL, 256, 64, 0);              // launch 5: lx

    // ================= Stage A: EGAT on atom graph =================
    unsigned* smaxA = sm;                         // NN*4
    float*    ssumA = (float*)(sm + (size_t)NN * 4);
    cudaMemsetAsync(sm, 0, (size_t)NN * 8 * sizeof(unsigned));
    cudaMemsetAsync(aggnc, 0, (size_t)NN * 129 * sizeof(float));
    float* aggn = aggnc;
    float* cntn = aggnc + (size_t)NN * 128;
    gemm(efh, efl, efh, efl, 128, 128, wh + OFF_EWFIJ, wl + OFF_EWFIJ, 128,
         nullptr, fe, 256, EE, 256, 128, 0);
    edgeA_kernel<<<cdiv((long)EE * 32, TPB), TPB>>>(
        pair, 512, fe, 256, efeats, ebias, eattn, src, dst,
        feh, fel, logE, smaxA, aggn, cntn, EE);
    exp_kernel<<<cdiv((long)EE * 4, TPB), TPB>>>(logE, dst, smaxA, ssumA, EE);
    div_mean_cvt<<<cdiv((long)NN * 128 / 4, TPB), TPB>>>(aggn, cntn, agnh, agnl,
                                                         (long)NN * 128, 128);
    gemm(nfh, nfl, agnh, agnl, 128, 128, wh + OFF_EWNODE, wl + OFF_EWNODE, 256,
         ebnode, h, 256, NN, 256, 256, 0);
    cudaMemsetAsync(ni, 0, (size_t)NN * 256 * sizeof(float));
    agg_node<<<cdiv((long)EE * 32, TPB), TPB>>>(h, logE, ssumA, src, dst, ni, EE);
    fin_node<<<cdiv((long)NN * 64, TPB), TPB>>>(ni, hnode, hnh, hnl, NN);

    // ================= Stage B: line-graph branch (bond -> angle) =================
    unsigned* smaxB = sm;                         // EE*4
    float*    ssumB = (float*)(sm + (size_t)EE * 4);
    cudaMemsetAsync(sm, 0, (size_t)EE * 8 * sizeof(unsigned));
    cudaMemsetAsync(aggxc, 0, (size_t)EE * 65 * sizeof(float));
    float* aggx = aggxc;
    float* cnte = aggxc + (size_t)EE * 64;
    // merged (lni|lnj|gfe): A = f_edge, N = 768
    gemm(feh, fel, feh, fel, 64, 64, wh + OFF_LWNI, wl + OFF_LWNI, 64,
         nullptr, pair, 768, EE, 768, 64, 0);
    edgeB_kernel<<<cdiv((long)ELL * 32, TPB), TPB>>>(
        pair, 768, big, 256, xfeats, lgbias, lgattn, lsrc, ldst,
        alg, smaxB, aggx, cnte, ELL);
    exp_kernel<<<cdiv((long)ELL * 4, TPB), TPB>>>(alg, ldst, smaxB, ssumB, ELL);
    div_mean_cvt<<<cdiv((long)EE * 64 / 4, TPB), TPB>>>(aggx, cnte, agxh, agxl,
                                                        (long)EE * 64, 64);
    gemm(feh, fel, agxh, agxl, 64, 64, wh + OFF_LWNODE, wl + OFF_LWNODE, 128,
         lgbnode, mbuf, 256, EE, 256, 128, 0);
    cudaMemsetAsync(acc, 0, (size_t)EE * 256 * sizeof(float));
    agg_lg<<<cdiv((long)ELL * 32, TPB), TPB>>>(mbuf, alg, ssumB, lsrc, ldst, acc, ELL, 0);
    fin_out<<<cdiv((long)EE * 64, TPB), TPB>>>(acc, out, EE, 0);

    // ================= Stage C: graph branch (atom -> bond) =================
    unsigned* smaxC = sm;
    float*    ssumC = (float*)(sm + (size_t)NN * 4);
    cudaMemsetAsync(sm, 0, (size_t)NN * 8 * sizeof(unsigned));
    gemm(hnh, hnl, hnh, hnl, 64, 64, wh + OFF_GWNI, wl + OFF_GWNI, 64,
         nullptr, ginj, 512, NN, 512, 64, 0);              // (gi|gj)
    edgeC_kernel<<<cdiv((long)EE * 32, TPB), TPB>>>(
        ginj, 512, pair + 512, 768, hnode, gbias, gattn, src, dst,
        ag, smaxC, neh, nel, EE);
    exp_kernel<<<cdiv((long)EE * 4, TPB), TPB>>>(ag, dst, smaxC, ssumC, EE);
    norm_kernel<<<cdiv((long)EE * 4, TPB), TPB>>>(ag, dst, ssumC, EE);
    gemm(neh, nel, feh, fel, 64, 64, wh + OFF_GWNODE, wl + OFF_GWNODE, 128,
         gbnode, mbuf, 256, EE, 256, 128, 0);
    cudaMemsetAsync(acc, 0, (size_t)EE * 256 * sizeof(float));
    agg_lg<<<cdiv((long)ELL * 32, TPB), TPB>>>(mbuf, ag, ssumC, lsrc, ldst, acc, ELL, 1);
    fin_out<<<cdiv((long)EE * 64, TPB), TPB>>>(acc, out, EE, 1);
}